// round 1
// baseline (speedup 1.0000x reference)
#include <cuda_runtime.h>
#include <cuda_bf16.h>
#include <math.h>

#define T_STEPS 100
#define BATCH   64
#define HID     512
#define NGATE   2048   // 4*512
#define VOCAB   10000

// ------------------------- scratch (static device memory) -------------------
__device__ float g_XW1[T_STEPS * BATCH * NGATE];   // [t][b][g*512+o]  52.4MB
__device__ float g_H2 [T_STEPS * BATCH * HID];     // [t][b][h]        13.1MB
__device__ float g_h1 [2 * BATCH * HID];
__device__ float g_h2 [2 * BATCH * HID];
__device__ float g_c1 [BATCH * HID];
__device__ float g_c2 [BATCH * HID];

// ------------------------- f32x2 helpers (B300: FFMA2 only via PTX) ---------
__device__ __forceinline__ unsigned long long pack2(float x, float y) {
    unsigned long long r;
    asm("mov.b64 %0, {%1, %2};" : "=l"(r)
        : "r"(__float_as_uint(x)), "r"(__float_as_uint(y)));
    return r;
}
__device__ __forceinline__ unsigned long long dup2(float x) {
    unsigned long long r;
    asm("mov.b64 %0, {%1, %1};" : "=l"(r) : "r"(__float_as_uint(x)));
    return r;
}
__device__ __forceinline__ void fma2(unsigned long long &d,
                                     unsigned long long a, unsigned long long b) {
    asm("fma.rn.f32x2 %0, %1, %2, %0;" : "+l"(d) : "l"(a), "l"(b));
}
__device__ __forceinline__ float2 unpack2(unsigned long long v) {
    float2 r;
    r.x = __uint_as_float((unsigned)(v & 0xFFFFFFFFu));
    r.y = __uint_as_float((unsigned)(v >> 32));
    return r;
}
__device__ __forceinline__ float sigm(float x) { return 1.f / (1.f + expf(-x)); }

// ------------------------- init: copy input states into scratch -------------
__global__ void init_state(const float* __restrict__ h1, const float* __restrict__ h2,
                           const float* __restrict__ c1, const float* __restrict__ c2) {
    int i = blockIdx.x * blockDim.x + threadIdx.x;
    if (i < BATCH * HID) {
        g_h1[i] = h1[i]; g_h2[i] = h2[i];
        g_c1[i] = c1[i]; g_c2[i] = c2[i];
    }
}

// ------------------------- precompute XW1 = emb[tok] @ wi1 -------------------
// GEMM M=6400 (t,b) N=2048 (g*512+o) K=512. 128x128x8 tile, 256 thr, 8x8 micro.
__global__ __launch_bounds__(256) void precompute_xw1(
    const int* __restrict__ tok, const float* __restrict__ emb,
    const float* __restrict__ wi1)
{
    __shared__ float As[8][128];   // [k][m] transposed
    __shared__ float Bs[8][128];   // [k][n]
    __shared__ int   toks[128];

    const int tid = threadIdx.x;
    const int m0 = blockIdx.y * 128;
    const int n0 = blockIdx.x * 128;           // within [0,2048); never spans a gate
    const int g  = n0 >> 9;
    const float* wbase = wi1 + (size_t)g * HID * HID + (n0 & 511);

    if (tid < 128) toks[tid] = tok[m0 + tid];
    __syncthreads();

    const int lr = tid >> 1;            // 0..127
    const int lk = (tid & 1) * 4;       // 0 or 4
    const int bk = tid >> 5;            // 0..7
    const int bn = (tid & 31) * 4;
    const int tx = tid & 15, ty = tid >> 4;

    unsigned long long acc[8][4];
#pragma unroll
    for (int i = 0; i < 8; i++)
#pragma unroll
        for (int j = 0; j < 4; j++) acc[i][j] = 0ULL;

    for (int k0 = 0; k0 < HID; k0 += 8) {
        float4 av = *(const float4*)(emb + (size_t)toks[lr] * HID + k0 + lk);
        As[lk+0][lr] = av.x; As[lk+1][lr] = av.y; As[lk+2][lr] = av.z; As[lk+3][lr] = av.w;
        float4 bv = *(const float4*)(wbase + (size_t)(k0 + bk) * HID + bn);
        *(float4*)&Bs[bk][bn] = bv;
        __syncthreads();
#pragma unroll
        for (int k = 0; k < 8; k++) {
            float4 a0 = *(float4*)&As[k][ty * 4];
            float4 a1 = *(float4*)&As[k][64 + ty * 4];
            float4 b0 = *(float4*)&Bs[k][tx * 4];
            float4 b1 = *(float4*)&Bs[k][64 + tx * 4];
            unsigned long long bp0 = pack2(b0.x, b0.y), bp1 = pack2(b0.z, b0.w);
            unsigned long long bp2 = pack2(b1.x, b1.y), bp3 = pack2(b1.z, b1.w);
            float ar[8] = {a0.x, a0.y, a0.z, a0.w, a1.x, a1.y, a1.z, a1.w};
#pragma unroll
            for (int i = 0; i < 8; i++) {
                unsigned long long ad = dup2(ar[i]);
                fma2(acc[i][0], ad, bp0);
                fma2(acc[i][1], ad, bp1);
                fma2(acc[i][2], ad, bp2);
                fma2(acc[i][3], ad, bp3);
            }
        }
        __syncthreads();
    }
#pragma unroll
    for (int i = 0; i < 8; i++) {
        int m = m0 + (i < 4 ? ty * 4 + i : 64 + ty * 4 + (i - 4));
        float* orow = g_XW1 + (size_t)m * NGATE + n0;
#pragma unroll
        for (int j = 0; j < 4; j++) {
            float2 v = unpack2(acc[i][j]);
            int cb = (j < 2) ? (tx * 4 + j * 2) : (64 + tx * 4 + (j - 2) * 2);
            orow[cb] = v.x; orow[cb + 1] = v.y;
        }
    }
}

// ------------------------- LSTM step (fused GEMM + gates) --------------------
// Block: 64 batch x 16 gate-cols (4 gates x o-tile of 4). grid=128, 128 threads.
__device__ __forceinline__ void gemm_part(
    const float* __restrict__ A, const float* __restrict__ W,
    int o0, int tid, unsigned long long acc[4],
    float (*As)[68], float (*Ws)[18])
{
    const int am = tid >> 1;            // 0..63
    const int ak = (tid & 1) * 8;       // 0 or 8
    const int wc = tid & 15;            // col 0..15
    const int wk = tid >> 4;            // 0..7
    const float* wcol = W + (size_t)(wc >> 2) * HID * HID + o0 + (wc & 3);
    const int tx = tid & 7, ty = tid >> 3;

    for (int k0 = 0; k0 < HID; k0 += 16) {
        float4 a0 = *(const float4*)(A + am * HID + k0 + ak);
        float4 a1 = *(const float4*)(A + am * HID + k0 + ak + 4);
        As[ak+0][am] = a0.x; As[ak+1][am] = a0.y; As[ak+2][am] = a0.z; As[ak+3][am] = a0.w;
        As[ak+4][am] = a1.x; As[ak+5][am] = a1.y; As[ak+6][am] = a1.z; As[ak+7][am] = a1.w;
        Ws[wk][wc]     = wcol[(size_t)(k0 + wk) * HID];
        Ws[wk + 8][wc] = wcol[(size_t)(k0 + wk + 8) * HID];
        __syncthreads();
#pragma unroll
        for (int k = 0; k < 16; k++) {
            float4 av = *(float4*)&As[k][ty * 4];
            unsigned long long bp = pack2(Ws[k][tx * 2], Ws[k][tx * 2 + 1]);
            fma2(acc[0], dup2(av.x), bp);
            fma2(acc[1], dup2(av.y), bp);
            fma2(acc[2], dup2(av.z), bp);
            fma2(acc[3], dup2(av.w), bp);
        }
        __syncthreads();
    }
}

__global__ __launch_bounds__(128) void lstm_step(
    const float* __restrict__ A1, const float* __restrict__ W1,
    const float* __restrict__ A2, const float* __restrict__ W2,
    const float* __restrict__ addsrc,   // XW1 row block for layer1, else null
    float* __restrict__ cstate, float* __restrict__ h_next,
    float* __restrict__ h_copy)         // H2out slice for layer2, else null
{
    __shared__ float As[16][68];
    __shared__ float Ws[16][18];
    __shared__ float gs[16][65];        // [gate*4+oo][batch]

    const int tid = threadIdx.x;
    const int o0 = blockIdx.x * 4;      // o-tile of 4 within [0,512)

    unsigned long long acc[4] = {0ULL, 0ULL, 0ULL, 0ULL};
    gemm_part(A1, W1, o0, tid, acc, As, Ws);
    if (A2) gemm_part(A2, W2, o0, tid, acc, As, Ws);

    const int tx = tid & 7, ty = tid >> 3;
#pragma unroll
    for (int i = 0; i < 4; i++) {
        float2 v = unpack2(acc[i]);
        int m = ty * 4 + i;
        int c0 = tx * 2;
        float gv0 = v.x, gv1 = v.y;
        if (addsrc) {
            const float* arow = addsrc + m * NGATE;
            gv0 += arow[((c0 >> 2) << 9) + o0 + (c0 & 3)];
            gv1 += arow[(((c0 + 1) >> 2) << 9) + o0 + ((c0 + 1) & 3)];
        }
        gs[c0][m] = gv0; gs[c0 + 1][m] = gv1;
    }
    __syncthreads();

    for (int idx = tid; idx < BATCH * 4; idx += 128) {
        int b = idx >> 2, oo = idx & 3;
        float iv = gs[0 * 4 + oo][b];
        float fv = gs[1 * 4 + oo][b];
        float gv = gs[2 * 4 + oo][b];
        float ov = gs[3 * 4 + oo][b];
        float ig = sigm(iv), fg = sigm(fv), gg = tanhf(gv), og = sigm(ov);
        int col = o0 + oo;
        float cp = cstate[b * HID + col];
        float cn = fg * cp + ig * gg;
        float hn = og * tanhf(cn);
        cstate[b * HID + col] = cn;
        h_next[b * HID + col] = hn;
        if (h_copy) h_copy[b * HID + col] = hn;
    }
}

// ------------------------- decoder: H2 @ dec_w^T + dec_b ---------------------
// GEMM M=6400 N=10000 K=512. Same 128x128x8 f32x2 scheme; B is K-contiguous.
__global__ __launch_bounds__(256) void decoder_gemm(
    const float* __restrict__ A,      // g_H2 [6400][512]
    const float* __restrict__ Bw,     // dec_w [10000][512]
    const float* __restrict__ bias,
    float* __restrict__ out)
{
    __shared__ float As[8][128];
    __shared__ float Bs[8][128];

    const int tid = threadIdx.x;
    const int m0 = blockIdx.y * 128;
    const int n0 = blockIdx.x * 128;
    const int lr = tid >> 1;
    const int lk = (tid & 1) * 4;
    const int tx = tid & 15, ty = tid >> 4;

    unsigned long long acc[8][4];
#pragma unroll
    for (int i = 0; i < 8; i++)
#pragma unroll
        for (int j = 0; j < 4; j++) acc[i][j] = 0ULL;

    for (int k0 = 0; k0 < HID; k0 += 8) {
        float4 av = *(const float4*)(A + (size_t)(m0 + lr) * HID + k0 + lk);
        As[lk+0][lr] = av.x; As[lk+1][lr] = av.y; As[lk+2][lr] = av.z; As[lk+3][lr] = av.w;
        int nrow = n0 + lr;
        float4 bv = make_float4(0.f, 0.f, 0.f, 0.f);
        if (nrow < VOCAB)
            bv = *(const float4*)(Bw + (size_t)nrow * HID + k0 + lk);
        Bs[lk+0][lr] = bv.x; Bs[lk+1][lr] = bv.y; Bs[lk+2][lr] = bv.z; Bs[lk+3][lr] = bv.w;
        __syncthreads();
#pragma unroll
        for (int k = 0; k < 8; k++) {
            float4 a0 = *(float4*)&As[k][ty * 4];
            float4 a1 = *(float4*)&As[k][64 + ty * 4];
            float4 b0 = *(float4*)&Bs[k][tx * 4];
            float4 b1 = *(float4*)&Bs[k][64 + tx * 4];
            unsigned long long bp0 = pack2(b0.x, b0.y), bp1 = pack2(b0.z, b0.w);
            unsigned long long bp2 = pack2(b1.x, b1.y), bp3 = pack2(b1.z, b1.w);
            float ar[8] = {a0.x, a0.y, a0.z, a0.w, a1.x, a1.y, a1.z, a1.w};
#pragma unroll
            for (int i = 0; i < 8; i++) {
                unsigned long long ad = dup2(ar[i]);
                fma2(acc[i][0], ad, bp0);
                fma2(acc[i][1], ad, bp1);
                fma2(acc[i][2], ad, bp2);
                fma2(acc[i][3], ad, bp3);
            }
        }
        __syncthreads();
    }
#pragma unroll
    for (int i = 0; i < 8; i++) {
        int m = m0 + (i < 4 ? ty * 4 + i : 64 + ty * 4 + (i - 4));
#pragma unroll
        for (int j = 0; j < 4; j++) {
            float2 v = unpack2(acc[i][j]);
            int cb = n0 + ((j < 2) ? (tx * 4 + j * 2) : (64 + tx * 4 + (j - 2) * 2));
            if (cb < VOCAB) {   // VOCAB even, cb even -> cb+1 also valid
                out[(size_t)m * VOCAB + cb]     = v.x + bias[cb];
                out[(size_t)m * VOCAB + cb + 1] = v.y + bias[cb + 1];
            }
        }
    }
}

// ------------------------- finals ------------------------------------------
__global__ void write_finals(float* __restrict__ out, int cur) {
    int i = blockIdx.x * blockDim.x + threadIdx.x;
    if (i < BATCH * HID) {
        float* o = out + (size_t)T_STEPS * BATCH * VOCAB;
        o[i]                 = g_h1[cur * BATCH * HID + i];
        o[BATCH * HID + i]   = g_h2[cur * BATCH * HID + i];
        o[2 * BATCH * HID + i] = g_c1[i];
        o[3 * BATCH * HID + i] = g_c2[i];
    }
}

// ------------------------- launch ------------------------------------------
extern "C" void kernel_launch(void* const* d_in, const int* in_sizes, int n_in,
                              void* d_out, int out_size) {
    const int*   raw   = (const int*)  d_in[0];
    const float* h1    = (const float*)d_in[1];
    const float* h2    = (const float*)d_in[2];
    const float* c1    = (const float*)d_in[3];
    const float* c2    = (const float*)d_in[4];
    const float* emb   = (const float*)d_in[5];
    const float* wi1   = (const float*)d_in[6];
    const float* wh1   = (const float*)d_in[7];
    const float* wi2   = (const float*)d_in[8];
    const float* wh2   = (const float*)d_in[9];
    const float* dec_w = (const float*)d_in[10];
    const float* dec_b = (const float*)d_in[11];
    float* out = (float*)d_out;

    float *p_xw1, *p_h2buf, *p_h1s, *p_h2s, *p_c1, *p_c2;
    cudaGetSymbolAddress((void**)&p_xw1,   g_XW1);
    cudaGetSymbolAddress((void**)&p_h2buf, g_H2);
    cudaGetSymbolAddress((void**)&p_h1s,   g_h1);
    cudaGetSymbolAddress((void**)&p_h2s,   g_h2);
    cudaGetSymbolAddress((void**)&p_c1,    g_c1);
    cudaGetSymbolAddress((void**)&p_c2,    g_c2);

    init_state<<<128, 256>>>(h1, h2, c1, c2);
    precompute_xw1<<<dim3(16, 50), 256>>>(raw, emb, wi1);

    int cur = 0;
    for (int t = 0; t < T_STEPS; t++) {
        const float* xw_t = p_xw1 + (size_t)t * BATCH * NGATE;
        lstm_step<<<128, 128>>>(p_h1s + cur * BATCH * HID, wh1,
                                nullptr, nullptr,
                                xw_t, p_c1,
                                p_h1s + (cur ^ 1) * BATCH * HID, nullptr);
        lstm_step<<<128, 128>>>(p_h1s + (cur ^ 1) * BATCH * HID, wi2,
                                p_h2s + cur * BATCH * HID, wh2,
                                nullptr, p_c2,
                                p_h2s + (cur ^ 1) * BATCH * HID,
                                p_h2buf + (size_t)t * BATCH * HID);
        cur ^= 1;
    }

    decoder_gemm<<<dim3(79, 50), 256>>>(p_h2buf, dec_w, dec_b, out);
    write_finals<<<128, 256>>>(out, cur);
}

// round 2
// speedup vs baseline: 1.0239x; 1.0239x over previous
#include <cuda_runtime.h>
#include <cuda_bf16.h>
#include <math.h>

#define T_STEPS 100
#define BATCH   64
#define HID     512
#define NGATE   2048   // 4*512
#define VOCAB   10000

// ------------------------- scratch (static device memory) -------------------
__device__ float g_XW1[T_STEPS * BATCH * NGATE];   // [t][b][g*512+o]  52.4MB
__device__ float g_H2 [T_STEPS * BATCH * HID];     // [t][b][h]        13.1MB
__device__ float g_h1 [2 * BATCH * HID];
__device__ float g_h2 [2 * BATCH * HID];
__device__ float g_c1 [BATCH * HID];
__device__ float g_c2 [BATCH * HID];

// ------------------------- f32x2 helpers (B300: FFMA2 only via PTX) ---------
__device__ __forceinline__ unsigned long long pack2(float x, float y) {
    unsigned long long r;
    asm("mov.b64 %0, {%1, %2};" : "=l"(r)
        : "r"(__float_as_uint(x)), "r"(__float_as_uint(y)));
    return r;
}
__device__ __forceinline__ unsigned long long dup2(float x) {
    unsigned long long r;
    asm("mov.b64 %0, {%1, %1};" : "=l"(r) : "r"(__float_as_uint(x)));
    return r;
}
__device__ __forceinline__ void fma2(unsigned long long &d,
                                     unsigned long long a, unsigned long long b) {
    asm("fma.rn.f32x2 %0, %1, %2, %0;" : "+l"(d) : "l"(a), "l"(b));
}
__device__ __forceinline__ float2 unpack2(unsigned long long v) {
    float2 r;
    r.x = __uint_as_float((unsigned)(v & 0xFFFFFFFFu));
    r.y = __uint_as_float((unsigned)(v >> 32));
    return r;
}
__device__ __forceinline__ float sigm(float x) { return 1.f / (1.f + expf(-x)); }

// ------------------------- cp.async helpers ----------------------------------
__device__ __forceinline__ void cp_async16(void* dst, const void* src) {
    unsigned d = (unsigned)__cvta_generic_to_shared(dst);
    asm volatile("cp.async.cg.shared.global [%0], [%1], 16;" :: "r"(d), "l"(src));
}
__device__ __forceinline__ void cp_commit() {
    asm volatile("cp.async.commit_group;");
}
template<int N> __device__ __forceinline__ void cp_wait() {
    asm volatile("cp.async.wait_group %0;" :: "n"(N));
}

// ------------------------- init: copy input states into scratch -------------
__global__ void init_state(const float* __restrict__ h1, const float* __restrict__ h2,
                           const float* __restrict__ c1, const float* __restrict__ c2) {
    int i = blockIdx.x * blockDim.x + threadIdx.x;
    if (i < BATCH * HID) {
        g_h1[i] = h1[i]; g_h2[i] = h2[i];
        g_c1[i] = c1[i]; g_c2[i] = c2[i];
    }
}

// ------------------------- precompute XW1 = emb[tok] @ wi1 -------------------
__global__ __launch_bounds__(256) void precompute_xw1(
    const int* __restrict__ tok, const float* __restrict__ emb,
    const float* __restrict__ wi1)
{
    __shared__ float As[8][128];
    __shared__ float Bs[8][128];
    __shared__ int   toks[128];

    const int tid = threadIdx.x;
    const int m0 = blockIdx.y * 128;
    const int n0 = blockIdx.x * 128;
    const int g  = n0 >> 9;
    const float* wbase = wi1 + (size_t)g * HID * HID + (n0 & 511);

    if (tid < 128) toks[tid] = tok[m0 + tid];
    __syncthreads();

    const int lr = tid >> 1;
    const int lk = (tid & 1) * 4;
    const int bk = tid >> 5;
    const int bn = (tid & 31) * 4;
    const int tx = tid & 15, ty = tid >> 4;

    unsigned long long acc[8][4];
#pragma unroll
    for (int i = 0; i < 8; i++)
#pragma unroll
        for (int j = 0; j < 4; j++) acc[i][j] = 0ULL;

    for (int k0 = 0; k0 < HID; k0 += 8) {
        float4 av = *(const float4*)(emb + (size_t)toks[lr] * HID + k0 + lk);
        As[lk+0][lr] = av.x; As[lk+1][lr] = av.y; As[lk+2][lr] = av.z; As[lk+3][lr] = av.w;
        float4 bv = *(const float4*)(wbase + (size_t)(k0 + bk) * HID + bn);
        *(float4*)&Bs[bk][bn] = bv;
        __syncthreads();
#pragma unroll
        for (int k = 0; k < 8; k++) {
            float4 a0 = *(float4*)&As[k][ty * 4];
            float4 a1 = *(float4*)&As[k][64 + ty * 4];
            float4 b0 = *(float4*)&Bs[k][tx * 4];
            float4 b1 = *(float4*)&Bs[k][64 + tx * 4];
            unsigned long long bp0 = pack2(b0.x, b0.y), bp1 = pack2(b0.z, b0.w);
            unsigned long long bp2 = pack2(b1.x, b1.y), bp3 = pack2(b1.z, b1.w);
            float ar[8] = {a0.x, a0.y, a0.z, a0.w, a1.x, a1.y, a1.z, a1.w};
#pragma unroll
            for (int i = 0; i < 8; i++) {
                unsigned long long ad = dup2(ar[i]);
                fma2(acc[i][0], ad, bp0);
                fma2(acc[i][1], ad, bp1);
                fma2(acc[i][2], ad, bp2);
                fma2(acc[i][3], ad, bp3);
            }
        }
        __syncthreads();
    }
#pragma unroll
    for (int i = 0; i < 8; i++) {
        int m = m0 + (i < 4 ? ty * 4 + i : 64 + ty * 4 + (i - 4));
        float* orow = g_XW1 + (size_t)m * NGATE + n0;
#pragma unroll
        for (int j = 0; j < 4; j++) {
            float2 v = unpack2(acc[i][j]);
            int cb = (j < 2) ? (tx * 4 + j * 2) : (64 + tx * 4 + (j - 2) * 2);
            orow[cb] = v.x; orow[cb + 1] = v.y;
        }
    }
}

// ------------------------- LSTM step v2 --------------------------------------
// grid=128 (o-tiles of 4), block=128 threads.
// Thread owns: batch row b = tid>>1, o-pair op = tid&1 (cols o0+2op, o0+2op+1),
// ALL 4 gates -> pointwise update fully in registers.
// A row lives in registers (2x32 double buffer). Weights double-buffered via
// cp.async into Ws[2][4][32][4] (g-major tile, o contiguous -> LDS64 o-pairs).
__device__ __forceinline__ void gemm_acc(
    const float* __restrict__ A,      // [64][512]
    const float* __restrict__ Wo,     // W + o0 : [4][512][512] base offset o0
    int b, int op, int tid,
    float (&Ws)[2][4][32][4],
    unsigned long long (&acc)[4])
{
    const float* arow = A + b * HID;
    const int sg  = tid >> 5;       // staging: gate
    const int skt = tid & 31;       // staging: k within tile
    const float* wsrc = Wo + ((size_t)sg * HID + skt) * HID;

    float a[2][32];
#pragma unroll
    for (int i = 0; i < 8; i++)
        *(float4*)&a[0][i * 4] = *(const float4*)(arow + i * 4);
    cp_async16(&Ws[0][sg][skt][0], wsrc);
    cp_commit();

    for (int t = 0; t < 16; t++) {
        const int cur = t & 1, nxt = cur ^ 1;
        if (t + 1 < 16) {
            const float* an = arow + (t + 1) * 32;
#pragma unroll
            for (int i = 0; i < 8; i++)
                *(float4*)&a[nxt][i * 4] = *(const float4*)(an + i * 4);
            cp_async16(&Ws[nxt][sg][skt][0], wsrc + (size_t)(t + 1) * 32 * HID);
            cp_commit();
            cp_wait<1>();
        } else {
            cp_wait<0>();
        }
        __syncthreads();
#pragma unroll
        for (int kt = 0; kt < 32; kt++) {
            unsigned long long ad = dup2(a[cur][kt]);
            fma2(acc[0], ad, *(unsigned long long*)&Ws[cur][0][kt][2 * op]);
            fma2(acc[1], ad, *(unsigned long long*)&Ws[cur][1][kt][2 * op]);
            fma2(acc[2], ad, *(unsigned long long*)&Ws[cur][2][kt][2 * op]);
            fma2(acc[3], ad, *(unsigned long long*)&Ws[cur][3][kt][2 * op]);
        }
        __syncthreads();
    }
}

__global__ __launch_bounds__(128, 1) void lstm_step(
    const float* __restrict__ A1, const float* __restrict__ W1,
    const float* __restrict__ A2, const float* __restrict__ W2,
    const float* __restrict__ xw,      // XW1 slice for layer1, else null
    float* __restrict__ cstate, float* __restrict__ h_next,
    float* __restrict__ h_copy)        // H2out slice for layer2, else null
{
    __shared__ float Ws[2][4][32][4];

    const int tid = threadIdx.x;
    const int op  = tid & 1;
    const int b   = tid >> 1;
    const int o0  = blockIdx.x * 4;

    unsigned long long acc[4] = {0ULL, 0ULL, 0ULL, 0ULL};
    gemm_acc(A1, W1 + o0, b, op, tid, Ws, acc);
    if (A2) gemm_acc(A2, W2 + o0, b, op, tid, Ws, acc);

    const int col = o0 + 2 * op;
    float gv[4][2];
#pragma unroll
    for (int g = 0; g < 4; g++) {
        float2 v = unpack2(acc[g]);
        gv[g][0] = v.x; gv[g][1] = v.y;
    }
    if (xw) {
        const float* xr = xw + b * NGATE;
#pragma unroll
        for (int g = 0; g < 4; g++) {
            gv[g][0] += xr[g * HID + col];
            gv[g][1] += xr[g * HID + col + 1];
        }
    }
#pragma unroll
    for (int oo = 0; oo < 2; oo++) {
        float ig = sigm(gv[0][oo]), fg = sigm(gv[1][oo]);
        float gg = tanhf(gv[2][oo]), og = sigm(gv[3][oo]);
        int idx = b * HID + col + oo;
        float cn = fg * cstate[idx] + ig * gg;
        float hn = og * tanhf(cn);
        cstate[idx] = cn;
        h_next[idx] = hn;
        if (h_copy) h_copy[idx] = hn;
    }
}

// ------------------------- decoder: H2 @ dec_w^T + dec_b ---------------------
__global__ __launch_bounds__(256) void decoder_gemm(
    const float* __restrict__ A,
    const float* __restrict__ Bw,
    const float* __restrict__ bias,
    float* __restrict__ out)
{
    __shared__ float As[8][128];
    __shared__ float Bs[8][128];

    const int tid = threadIdx.x;
    const int m0 = blockIdx.y * 128;
    const int n0 = blockIdx.x * 128;
    const int lr = tid >> 1;
    const int lk = (tid & 1) * 4;
    const int tx = tid & 15, ty = tid >> 4;

    unsigned long long acc[8][4];
#pragma unroll
    for (int i = 0; i < 8; i++)
#pragma unroll
        for (int j = 0; j < 4; j++) acc[i][j] = 0ULL;

    for (int k0 = 0; k0 < HID; k0 += 8) {
        float4 av = *(const float4*)(A + (size_t)(m0 + lr) * HID + k0 + lk);
        As[lk+0][lr] = av.x; As[lk+1][lr] = av.y; As[lk+2][lr] = av.z; As[lk+3][lr] = av.w;
        int nrow = n0 + lr;
        float4 bv = make_float4(0.f, 0.f, 0.f, 0.f);
        if (nrow < VOCAB)
            bv = *(const float4*)(Bw + (size_t)nrow * HID + k0 + lk);
        Bs[lk+0][lr] = bv.x; Bs[lk+1][lr] = bv.y; Bs[lk+2][lr] = bv.z; Bs[lk+3][lr] = bv.w;
        __syncthreads();
#pragma unroll
        for (int k = 0; k < 8; k++) {
            float4 a0 = *(float4*)&As[k][ty * 4];
            float4 a1 = *(float4*)&As[k][64 + ty * 4];
            float4 b0 = *(float4*)&Bs[k][tx * 4];
            float4 b1 = *(float4*)&Bs[k][64 + tx * 4];
            unsigned long long bp0 = pack2(b0.x, b0.y), bp1 = pack2(b0.z, b0.w);
            unsigned long long bp2 = pack2(b1.x, b1.y), bp3 = pack2(b1.z, b1.w);
            float ar[8] = {a0.x, a0.y, a0.z, a0.w, a1.x, a1.y, a1.z, a1.w};
#pragma unroll
            for (int i = 0; i < 8; i++) {
                unsigned long long ad = dup2(ar[i]);
                fma2(acc[i][0], ad, bp0);
                fma2(acc[i][1], ad, bp1);
                fma2(acc[i][2], ad, bp2);
                fma2(acc[i][3], ad, bp3);
            }
        }
        __syncthreads();
    }
#pragma unroll
    for (int i = 0; i < 8; i++) {
        int m = m0 + (i < 4 ? ty * 4 + i : 64 + ty * 4 + (i - 4));
#pragma unroll
        for (int j = 0; j < 4; j++) {
            float2 v = unpack2(acc[i][j]);
            int cb = n0 + ((j < 2) ? (tx * 4 + j * 2) : (64 + tx * 4 + (j - 2) * 2));
            if (cb < VOCAB) {
                out[(size_t)m * VOCAB + cb]     = v.x + bias[cb];
                out[(size_t)m * VOCAB + cb + 1] = v.y + bias[cb + 1];
            }
        }
    }
}

// ------------------------- finals ------------------------------------------
__global__ void write_finals(float* __restrict__ out, int cur) {
    int i = blockIdx.x * blockDim.x + threadIdx.x;
    if (i < BATCH * HID) {
        float* o = out + (size_t)T_STEPS * BATCH * VOCAB;
        o[i]                   = g_h1[cur * BATCH * HID + i];
        o[BATCH * HID + i]     = g_h2[cur * BATCH * HID + i];
        o[2 * BATCH * HID + i] = g_c1[i];
        o[3 * BATCH * HID + i] = g_c2[i];
    }
}

// ------------------------- launch ------------------------------------------
extern "C" void kernel_launch(void* const* d_in, const int* in_sizes, int n_in,
                              void* d_out, int out_size) {
    const int*   raw   = (const int*)  d_in[0];
    const float* h1    = (const float*)d_in[1];
    const float* h2    = (const float*)d_in[2];
    const float* c1    = (const float*)d_in[3];
    const float* c2    = (const float*)d_in[4];
    const float* emb   = (const float*)d_in[5];
    const float* wi1   = (const float*)d_in[6];
    const float* wh1   = (const float*)d_in[7];
    const float* wi2   = (const float*)d_in[8];
    const float* wh2   = (const float*)d_in[9];
    const float* dec_w = (const float*)d_in[10];
    const float* dec_b = (const float*)d_in[11];
    float* out = (float*)d_out;

    float *p_xw1, *p_h2buf, *p_h1s, *p_h2s, *p_c1, *p_c2;
    cudaGetSymbolAddress((void**)&p_xw1,   g_XW1);
    cudaGetSymbolAddress((void**)&p_h2buf, g_H2);
    cudaGetSymbolAddress((void**)&p_h1s,   g_h1);
    cudaGetSymbolAddress((void**)&p_h2s,   g_h2);
    cudaGetSymbolAddress((void**)&p_c1,    g_c1);
    cudaGetSymbolAddress((void**)&p_c2,    g_c2);

    init_state<<<128, 256>>>(h1, h2, c1, c2);
    precompute_xw1<<<dim3(16, 50), 256>>>(raw, emb, wi1);

    int cur = 0;
    for (int t = 0; t < T_STEPS; t++) {
        const float* xw_t = p_xw1 + (size_t)t * BATCH * NGATE;
        lstm_step<<<128, 128>>>(p_h1s + cur * BATCH * HID, wh1,
                                nullptr, nullptr,
                                xw_t, p_c1,
                                p_h1s + (cur ^ 1) * BATCH * HID, nullptr);
        lstm_step<<<128, 128>>>(p_h1s + (cur ^ 1) * BATCH * HID, wi2,
                                p_h2s + cur * BATCH * HID, wh2,
                                nullptr, p_c2,
                                p_h2s + (cur ^ 1) * BATCH * HID,
                                p_h2buf + (size_t)t * BATCH * HID);
        cur ^= 1;
    }

    decoder_gemm<<<dim3(79, 50), 256>>>(p_h2buf, dec_w, dec_b, out);
    write_finals<<<128, 256>>>(out, cur);
}

// round 3
// speedup vs baseline: 1.5876x; 1.5506x over previous
#include <cuda_runtime.h>
#include <cuda_bf16.h>
#include <math.h>

#define T_STEPS 100
#define BATCH   64
#define HID     512
#define NGATE   2048   // 4*512
#define VOCAB   10000
#define NBLK    128

typedef unsigned long long u64;

// ------------------------- scratch (static device memory) -------------------
__device__ float g_XW1[T_STEPS * BATCH * NGATE];   // [t][b][g*512+o]
__device__ float g_H2 [T_STEPS * BATCH * HID];     // [t][b][h]
__device__ float g_h1buf[2 * BATCH * HID];
__device__ float g_h2buf[2 * BATCH * HID];
__device__ float g_c1f[BATCH * HID];
__device__ float g_c2f[BATCH * HID];
__device__ unsigned g_bar_cnt;
__device__ volatile unsigned g_bar_flag;

// ------------------------- f32x2 helpers -------------------------------------
__device__ __forceinline__ u64 pack2(float x, float y) {
    u64 r;
    asm("mov.b64 %0, {%1, %2};" : "=l"(r)
        : "r"(__float_as_uint(x)), "r"(__float_as_uint(y)));
    return r;
}
__device__ __forceinline__ u64 dup2(float x) {
    u64 r;
    asm("mov.b64 %0, {%1, %1};" : "=l"(r) : "r"(__float_as_uint(x)));
    return r;
}
__device__ __forceinline__ void fma2(u64 &d, u64 a, u64 b) {
    asm("fma.rn.f32x2 %0, %1, %2, %0;" : "+l"(d) : "l"(a), "l"(b));
}
__device__ __forceinline__ void add2(u64 &d, u64 a) {
    asm("add.rn.f32x2 %0, %0, %1;" : "+l"(d) : "l"(a));
}
__device__ __forceinline__ float2 unpack2(u64 v) {
    float2 r;
    r.x = __uint_as_float((unsigned)(v & 0xFFFFFFFFu));
    r.y = __uint_as_float((unsigned)(v >> 32));
    return r;
}
__device__ __forceinline__ float sigm(float x) { return 1.f / (1.f + expf(-x)); }

// ------------------------- init ----------------------------------------------
__global__ void init_state(const float* __restrict__ h1, const float* __restrict__ h2) {
    int i = blockIdx.x * blockDim.x + threadIdx.x;
    if (i < BATCH * HID) {
        g_h1buf[i] = h1[i];   // parity-0 slot
        g_h2buf[i] = h2[i];
    }
    if (i == 0) { g_bar_cnt = 0; g_bar_flag = 0; }
}

// ------------------------- precompute XW1 = emb[tok] @ wi1 -------------------
__global__ __launch_bounds__(256) void precompute_xw1(
    const int* __restrict__ tok, const float* __restrict__ emb,
    const float* __restrict__ wi1)
{
    __shared__ float As[8][128];
    __shared__ float Bs[8][128];
    __shared__ int   toks[128];

    const int tid = threadIdx.x;
    const int m0 = blockIdx.y * 128;
    const int n0 = blockIdx.x * 128;
    const int g  = n0 >> 9;
    const float* wbase = wi1 + (size_t)g * HID * HID + (n0 & 511);

    if (tid < 128) toks[tid] = tok[m0 + tid];
    __syncthreads();

    const int lr = tid >> 1;
    const int lk = (tid & 1) * 4;
    const int bk = tid >> 5;
    const int bn = (tid & 31) * 4;
    const int tx = tid & 15, ty = tid >> 4;

    u64 acc[8][4];
#pragma unroll
    for (int i = 0; i < 8; i++)
#pragma unroll
        for (int j = 0; j < 4; j++) acc[i][j] = 0ULL;

    for (int k0 = 0; k0 < HID; k0 += 8) {
        float4 av = *(const float4*)(emb + (size_t)toks[lr] * HID + k0 + lk);
        As[lk+0][lr] = av.x; As[lk+1][lr] = av.y; As[lk+2][lr] = av.z; As[lk+3][lr] = av.w;
        float4 bv = *(const float4*)(wbase + (size_t)(k0 + bk) * HID + bn);
        *(float4*)&Bs[bk][bn] = bv;
        __syncthreads();
#pragma unroll
        for (int k = 0; k < 8; k++) {
            float4 a0 = *(float4*)&As[k][ty * 4];
            float4 a1 = *(float4*)&As[k][64 + ty * 4];
            float4 b0 = *(float4*)&Bs[k][tx * 4];
            float4 b1 = *(float4*)&Bs[k][64 + tx * 4];
            u64 bp0 = pack2(b0.x, b0.y), bp1 = pack2(b0.z, b0.w);
            u64 bp2 = pack2(b1.x, b1.y), bp3 = pack2(b1.z, b1.w);
            float ar[8] = {a0.x, a0.y, a0.z, a0.w, a1.x, a1.y, a1.z, a1.w};
#pragma unroll
            for (int i = 0; i < 8; i++) {
                u64 ad = dup2(ar[i]);
                fma2(acc[i][0], ad, bp0);
                fma2(acc[i][1], ad, bp1);
                fma2(acc[i][2], ad, bp2);
                fma2(acc[i][3], ad, bp3);
            }
        }
        __syncthreads();
    }
#pragma unroll
    for (int i = 0; i < 8; i++) {
        int m = m0 + (i < 4 ? ty * 4 + i : 64 + ty * 4 + (i - 4));
        float* orow = g_XW1 + (size_t)m * NGATE + n0;
#pragma unroll
        for (int j = 0; j < 4; j++) {
            float2 v = unpack2(acc[i][j]);
            int cb = (j < 2) ? (tx * 4 + j * 2) : (64 + tx * 4 + (j - 2) * 2);
            orow[cb] = v.x; orow[cb + 1] = v.y;
        }
    }
}

// ------------------------- persistent recurrence kernel ----------------------
struct SmemT {
    float w1 [HID * 16];    // [k][oo][g]
    float wi2[HID * 16];
    float wh2[HID * 16];
    u64   xch[512];         // [bp*4+oo][4]
    float c1s[256];         // [b][oo]
    float c2s[256];
};

__device__ __forceinline__ void grid_barrier(int t) {
    __threadfence();
    __syncthreads();
    if (threadIdx.x == 0) {
        unsigned prev = atomicAdd(&g_bar_cnt, 1u);
        if (prev == (unsigned)NBLK * (unsigned)(t + 1) - 1u) {
            __threadfence();
            g_bar_flag = (unsigned)(t + 1);
        } else {
            while (g_bar_flag < (unsigned)(t + 1)) { }
        }
        __threadfence();   // also invalidates this SM's L1D (gpu-scope fence)
    }
    __syncthreads();
}

__device__ __forceinline__ void gemm_range(
    const float* __restrict__ a0, const float* __restrict__ a1,
    const float* __restrict__ w, int klen,
    u64 &c00, u64 &c01, u64 &c10, u64 &c11)
{
#pragma unroll 2
    for (int kk = 0; kk < klen; kk += 8) {
        float ar0[8], ar1[8];
        *(float4*)&ar0[0] = __ldcg((const float4*)(a0 + kk));
        *(float4*)&ar0[4] = __ldcg((const float4*)(a0 + kk + 4));
        *(float4*)&ar1[0] = __ldcg((const float4*)(a1 + kk));
        *(float4*)&ar1[4] = __ldcg((const float4*)(a1 + kk + 4));
#pragma unroll
        for (int j = 0; j < 8; j++) {
            const float* wk = w + (kk + j) * 16;
            u64 w0 = *(const u64*)wk;
            u64 w1 = *(const u64*)(wk + 2);
            u64 d0 = dup2(ar0[j]), d1 = dup2(ar1[j]);
            fma2(c00, d0, w0); fma2(c01, d0, w1);
            fma2(c10, d1, w0); fma2(c11, d1, w1);
        }
    }
}

__global__ __launch_bounds__(256, 1) void lstm_recur(
    const float* __restrict__ wh1, const float* __restrict__ wi2g,
    const float* __restrict__ wh2g,
    const float* __restrict__ c1in, const float* __restrict__ c2in)
{
    extern __shared__ char smraw[];
    SmemT* sm = (SmemT*)smraw;
    const int tid = threadIdx.x;
    const int bi  = blockIdx.x;
    const int o0  = bi * 4;

    // weights: [k][oo][g] <- W[g][k][o0+oo], once for all 100 steps
    for (int idx = tid; idx < HID * 16; idx += 256) {
        int k = idx >> 4, c = idx & 15;
        int oo = c >> 2, g = c & 3;
        size_t src = ((size_t)g * HID + k) * HID + o0 + oo;
        sm->w1 [idx] = wh1 [src];
        sm->wi2[idx] = wi2g[src];
        sm->wh2[idx] = wh2g[src];
    }
    {   // c state slice
        int b = tid >> 2, oo = tid & 3;
        sm->c1s[tid] = c1in[b * HID + o0 + oo];
        sm->c2s[tid] = c2in[b * HID + o0 + oo];
    }
    __syncthreads();

    const int ks = tid >> 7;        // k-split half
    const int r  = tid & 127;
    const int oo = r & 3;
    const int bp = r >> 2;
    const int b0 = bp * 2;
    const int col = o0 + oo;
    u64* xc = sm->xch + r * 4;

    for (int t = 0; t < T_STEPS; t++) {
        const int rp = t & 1, wp = rp ^ 1;

        // ---------------- Phase A: layer1 (h1 @ wh1 + XW1) ----------------
        float xwv[8];
        if (ks == 0) {
            const float* xr = g_XW1 + ((size_t)t * BATCH + b0) * NGATE + col;
#pragma unroll
            for (int g = 0; g < 4; g++) {
                xwv[g]     = xr[g * HID];
                xwv[4 + g] = xr[NGATE + g * HID];
            }
        }
        u64 c00 = 0, c01 = 0, c10 = 0, c11 = 0;
        {
            const float* a0 = g_h1buf + rp * (BATCH * HID) + b0 * HID + ks * 256;
            const float* w  = sm->w1 + (ks * 256) * 16 + oo * 4;
            gemm_range(a0, a0 + HID, w, 256, c00, c01, c10, c11);
        }
        if (ks == 1) { xc[0] = c00; xc[1] = c01; xc[2] = c10; xc[3] = c11; }
        __syncthreads();
        if (ks == 0) {
            add2(c00, xc[0]); add2(c01, xc[1]); add2(c10, xc[2]); add2(c11, xc[3]);
            float2 if0 = unpack2(c00), go0 = unpack2(c01);
            float2 if1 = unpack2(c10), go1 = unpack2(c11);
            float iv0 = if0.x + xwv[0], fv0 = if0.y + xwv[1];
            float gv0 = go0.x + xwv[2], ov0 = go0.y + xwv[3];
            float iv1 = if1.x + xwv[4], fv1 = if1.y + xwv[5];
            float gv1 = go1.x + xwv[6], ov1 = go1.y + xwv[7];
            float cA = sm->c1s[b0 * 4 + oo], cB = sm->c1s[(b0 + 1) * 4 + oo];
            float cn0 = sigm(fv0) * cA + sigm(iv0) * tanhf(gv0);
            float cn1 = sigm(fv1) * cB + sigm(iv1) * tanhf(gv1);
            sm->c1s[b0 * 4 + oo] = cn0;
            sm->c1s[(b0 + 1) * 4 + oo] = cn1;
            g_h1buf[wp * (BATCH * HID) + b0 * HID + col]       = sigm(ov0) * tanhf(cn0);
            g_h1buf[wp * (BATCH * HID) + (b0 + 1) * HID + col] = sigm(ov1) * tanhf(cn1);
        }

        grid_barrier(t);

        // ---------------- Phase B: layer2 (h1new @ wi2 + h2 @ wh2) --------
        c00 = 0; c01 = 0; c10 = 0; c11 = 0;
        if (ks == 0) {
            const float* a0 = g_h1buf + wp * (BATCH * HID) + b0 * HID;
            gemm_range(a0, a0 + HID, sm->wi2 + oo * 4, HID, c00, c01, c10, c11);
        } else {
            const float* a0 = g_h2buf + rp * (BATCH * HID) + b0 * HID;
            gemm_range(a0, a0 + HID, sm->wh2 + oo * 4, HID, c00, c01, c10, c11);
        }
        if (ks == 1) { xc[0] = c00; xc[1] = c01; xc[2] = c10; xc[3] = c11; }
        __syncthreads();
        if (ks == 0) {
            add2(c00, xc[0]); add2(c01, xc[1]); add2(c10, xc[2]); add2(c11, xc[3]);
            float2 if0 = unpack2(c00), go0 = unpack2(c01);
            float2 if1 = unpack2(c10), go1 = unpack2(c11);
            float cA = sm->c2s[b0 * 4 + oo], cB = sm->c2s[(b0 + 1) * 4 + oo];
            float cn0 = sigm(if0.y) * cA + sigm(if0.x) * tanhf(go0.x);
            float cn1 = sigm(if1.y) * cB + sigm(if1.x) * tanhf(go1.x);
            sm->c2s[b0 * 4 + oo] = cn0;
            sm->c2s[(b0 + 1) * 4 + oo] = cn1;
            float hn0 = sigm(go0.y) * tanhf(cn0);
            float hn1 = sigm(go1.y) * tanhf(cn1);
            g_h2buf[wp * (BATCH * HID) + b0 * HID + col]       = hn0;
            g_h2buf[wp * (BATCH * HID) + (b0 + 1) * HID + col] = hn1;
            g_H2[((size_t)t * BATCH + b0) * HID + col]     = hn0;
            g_H2[((size_t)t * BATCH + b0 + 1) * HID + col] = hn1;
        }
        __syncthreads();   // protect xch before next step's phase A store
    }

    // final c slices
    {
        int b = tid >> 2, oo2 = tid & 3;
        g_c1f[b * HID + o0 + oo2] = sm->c1s[tid];
        g_c2f[b * HID + o0 + oo2] = sm->c2s[tid];
    }
}

// ------------------------- decoder: H2 @ dec_w^T + dec_b ---------------------
__global__ __launch_bounds__(256) void decoder_gemm(
    const float* __restrict__ A,
    const float* __restrict__ Bw,
    const float* __restrict__ bias,
    float* __restrict__ out)
{
    __shared__ float As[8][128];
    __shared__ float Bs[8][128];

    const int tid = threadIdx.x;
    const int m0 = blockIdx.y * 128;
    const int n0 = blockIdx.x * 128;
    const int lr = tid >> 1;
    const int lk = (tid & 1) * 4;
    const int tx = tid & 15, ty = tid >> 4;

    u64 acc[8][4];
#pragma unroll
    for (int i = 0; i < 8; i++)
#pragma unroll
        for (int j = 0; j < 4; j++) acc[i][j] = 0ULL;

    for (int k0 = 0; k0 < HID; k0 += 8) {
        float4 av = *(const float4*)(A + (size_t)(m0 + lr) * HID + k0 + lk);
        As[lk+0][lr] = av.x; As[lk+1][lr] = av.y; As[lk+2][lr] = av.z; As[lk+3][lr] = av.w;
        int nrow = n0 + lr;
        float4 bv = make_float4(0.f, 0.f, 0.f, 0.f);
        if (nrow < VOCAB)
            bv = *(const float4*)(Bw + (size_t)nrow * HID + k0 + lk);
        Bs[lk+0][lr] = bv.x; Bs[lk+1][lr] = bv.y; Bs[lk+2][lr] = bv.z; Bs[lk+3][lr] = bv.w;
        __syncthreads();
#pragma unroll
        for (int k = 0; k < 8; k++) {
            float4 a0 = *(float4*)&As[k][ty * 4];
            float4 a1 = *(float4*)&As[k][64 + ty * 4];
            float4 b0 = *(float4*)&Bs[k][tx * 4];
            float4 b1 = *(float4*)&Bs[k][64 + tx * 4];
            u64 bp0 = pack2(b0.x, b0.y), bp1 = pack2(b0.z, b0.w);
            u64 bp2 = pack2(b1.x, b1.y), bp3 = pack2(b1.z, b1.w);
            float ar[8] = {a0.x, a0.y, a0.z, a0.w, a1.x, a1.y, a1.z, a1.w};
#pragma unroll
            for (int i = 0; i < 8; i++) {
                u64 ad = dup2(ar[i]);
                fma2(acc[i][0], ad, bp0);
                fma2(acc[i][1], ad, bp1);
                fma2(acc[i][2], ad, bp2);
                fma2(acc[i][3], ad, bp3);
            }
        }
        __syncthreads();
    }
#pragma unroll
    for (int i = 0; i < 8; i++) {
        int m = m0 + (i < 4 ? ty * 4 + i : 64 + ty * 4 + (i - 4));
#pragma unroll
        for (int j = 0; j < 4; j++) {
            float2 v = unpack2(acc[i][j]);
            int cb = n0 + ((j < 2) ? (tx * 4 + j * 2) : (64 + tx * 4 + (j - 2) * 2));
            if (cb < VOCAB) {
                out[(size_t)m * VOCAB + cb]     = v.x + bias[cb];
                out[(size_t)m * VOCAB + cb + 1] = v.y + bias[cb + 1];
            }
        }
    }
}

// ------------------------- finals -------------------------------------------
__global__ void write_finals(float* __restrict__ out) {
    int i = blockIdx.x * blockDim.x + threadIdx.x;
    if (i < BATCH * HID) {
        float* o = out + (size_t)T_STEPS * BATCH * VOCAB;
        o[i]                   = g_h1buf[i];    // T even -> parity 0 slot
        o[BATCH * HID + i]     = g_h2buf[i];
        o[2 * BATCH * HID + i] = g_c1f[i];
        o[3 * BATCH * HID + i] = g_c2f[i];
    }
}

// ------------------------- launch -------------------------------------------
extern "C" void kernel_launch(void* const* d_in, const int* in_sizes, int n_in,
                              void* d_out, int out_size) {
    const int*   raw   = (const int*)  d_in[0];
    const float* h1    = (const float*)d_in[1];
    const float* h2    = (const float*)d_in[2];
    const float* c1    = (const float*)d_in[3];
    const float* c2    = (const float*)d_in[4];
    const float* emb   = (const float*)d_in[5];
    const float* wi1   = (const float*)d_in[6];
    const float* wh1   = (const float*)d_in[7];
    const float* wi2   = (const float*)d_in[8];
    const float* wh2   = (const float*)d_in[9];
    const float* dec_w = (const float*)d_in[10];
    const float* dec_b = (const float*)d_in[11];
    float* out = (float*)d_out;

    float* p_h2buf;
    cudaGetSymbolAddress((void**)&p_h2buf, g_H2);

    static int smem_set = 0;
    if (!smem_set) {
        cudaFuncSetAttribute(lstm_recur, cudaFuncAttributeMaxDynamicSharedMemorySize,
                             (int)sizeof(SmemT));
        smem_set = 1;
    }

    init_state<<<128, 256>>>(h1, h2);
    precompute_xw1<<<dim3(16, 50), 256>>>(raw, emb, wi1);
    lstm_recur<<<NBLK, 256, sizeof(SmemT)>>>(wh1, wi2, wh2, c1, c2);
    decoder_gemm<<<dim3(79, 50), 256>>>(p_h2buf, dec_w, dec_b, out);
    write_finals<<<128, 256>>>(out);
}

// round 4
// speedup vs baseline: 1.8447x; 1.1619x over previous
#include <cuda_runtime.h>
#include <cuda_bf16.h>
#include <math.h>

#define T_STEPS 100
#define BATCH   64
#define HID     512
#define NGATE   2048   // 4*512
#define VOCAB   10000
#define NBLK    128

typedef unsigned long long u64;

// ------------------------- scratch (static device memory) -------------------
__device__ float g_XW1[T_STEPS * BATCH * NGATE];   // [t][b][g*512+o]
__device__ float g_H2 [T_STEPS * BATCH * HID];     // [t][b][h]
__device__ float g_h1buf[2 * BATCH * HID];
__device__ float g_h2buf[2 * BATCH * HID];
__device__ float g_c1f[BATCH * HID];
__device__ float g_c2f[BATCH * HID];
__device__ unsigned g_bar_cnt;
__device__ volatile unsigned g_bar_flag;

// ------------------------- f32x2 helpers -------------------------------------
__device__ __forceinline__ u64 pack2(float x, float y) {
    u64 r;
    asm("mov.b64 %0, {%1, %2};" : "=l"(r)
        : "r"(__float_as_uint(x)), "r"(__float_as_uint(y)));
    return r;
}
__device__ __forceinline__ u64 dup2(float x) {
    u64 r;
    asm("mov.b64 %0, {%1, %1};" : "=l"(r) : "r"(__float_as_uint(x)));
    return r;
}
__device__ __forceinline__ void fma2(u64 &d, u64 a, u64 b) {
    asm("fma.rn.f32x2 %0, %1, %2, %0;" : "+l"(d) : "l"(a), "l"(b));
}
__device__ __forceinline__ void add2(u64 &d, u64 a) {
    asm("add.rn.f32x2 %0, %0, %1;" : "+l"(d) : "l"(a));
}
__device__ __forceinline__ float2 unpack2(u64 v) {
    float2 r;
    r.x = __uint_as_float((unsigned)(v & 0xFFFFFFFFu));
    r.y = __uint_as_float((unsigned)(v >> 32));
    return r;
}
__device__ __forceinline__ float sigm(float x) { return 1.f / (1.f + expf(-x)); }

// ------------------------- tf32 mma helpers ----------------------------------
__device__ __forceinline__ float cvt_tf32(float x) {
    unsigned r;
    asm("cvt.rn.tf32.f32 %0, %1;" : "=r"(r) : "f"(x));
    return __uint_as_float(r);
}
__device__ __forceinline__ void mma_tf32(float* d, const uint4& a, const uint2& b) {
    asm("mma.sync.aligned.m16n8k8.row.col.f32.tf32.tf32.f32 "
        "{%0,%1,%2,%3}, {%4,%5,%6,%7}, {%8,%9}, {%0,%1,%2,%3};"
        : "+f"(d[0]), "+f"(d[1]), "+f"(d[2]), "+f"(d[3])
        : "r"(a.x), "r"(a.y), "r"(a.z), "r"(a.w), "r"(b.x), "r"(b.y));
}

// ------------------------- init ----------------------------------------------
__global__ void init_state(const float* __restrict__ h1, const float* __restrict__ h2) {
    int i = blockIdx.x * blockDim.x + threadIdx.x;
    if (i < BATCH * HID) {
        g_h1buf[i] = h1[i];   // parity-0 slot
        g_h2buf[i] = h2[i];
    }
    if (i == 0) { g_bar_cnt = 0; g_bar_flag = 0; }
}

// ------------------------- precompute XW1 = emb[tok] @ wi1 -------------------
__global__ __launch_bounds__(256) void precompute_xw1(
    const int* __restrict__ tok, const float* __restrict__ emb,
    const float* __restrict__ wi1)
{
    __shared__ float As[8][128];
    __shared__ float Bs[8][128];
    __shared__ int   toks[128];

    const int tid = threadIdx.x;
    const int m0 = blockIdx.y * 128;
    const int n0 = blockIdx.x * 128;
    const int g  = n0 >> 9;
    const float* wbase = wi1 + (size_t)g * HID * HID + (n0 & 511);

    if (tid < 128) toks[tid] = tok[m0 + tid];
    __syncthreads();

    const int lr = tid >> 1;
    const int lk = (tid & 1) * 4;
    const int bk = tid >> 5;
    const int bn = (tid & 31) * 4;
    const int tx = tid & 15, ty = tid >> 4;

    u64 acc[8][4];
#pragma unroll
    for (int i = 0; i < 8; i++)
#pragma unroll
        for (int j = 0; j < 4; j++) acc[i][j] = 0ULL;

    for (int k0 = 0; k0 < HID; k0 += 8) {
        float4 av = *(const float4*)(emb + (size_t)toks[lr] * HID + k0 + lk);
        As[lk+0][lr] = av.x; As[lk+1][lr] = av.y; As[lk+2][lr] = av.z; As[lk+3][lr] = av.w;
        float4 bv = *(const float4*)(wbase + (size_t)(k0 + bk) * HID + bn);
        *(float4*)&Bs[bk][bn] = bv;
        __syncthreads();
#pragma unroll
        for (int k = 0; k < 8; k++) {
            float4 a0 = *(float4*)&As[k][ty * 4];
            float4 a1 = *(float4*)&As[k][64 + ty * 4];
            float4 b0 = *(float4*)&Bs[k][tx * 4];
            float4 b1 = *(float4*)&Bs[k][64 + tx * 4];
            u64 bp0 = pack2(b0.x, b0.y), bp1 = pack2(b0.z, b0.w);
            u64 bp2 = pack2(b1.x, b1.y), bp3 = pack2(b1.z, b1.w);
            float ar[8] = {a0.x, a0.y, a0.z, a0.w, a1.x, a1.y, a1.z, a1.w};
#pragma unroll
            for (int i = 0; i < 8; i++) {
                u64 ad = dup2(ar[i]);
                fma2(acc[i][0], ad, bp0);
                fma2(acc[i][1], ad, bp1);
                fma2(acc[i][2], ad, bp2);
                fma2(acc[i][3], ad, bp3);
            }
        }
        __syncthreads();
    }
#pragma unroll
    for (int i = 0; i < 8; i++) {
        int m = m0 + (i < 4 ? ty * 4 + i : 64 + ty * 4 + (i - 4));
        float* orow = g_XW1 + (size_t)m * NGATE + n0;
#pragma unroll
        for (int j = 0; j < 4; j++) {
            float2 v = unpack2(acc[i][j]);
            int cb = (j < 2) ? (tx * 4 + j * 2) : (64 + tx * 4 + (j - 2) * 2);
            orow[cb] = v.x; orow[cb + 1] = v.y;
        }
    }
}

// ------------------------- persistent recurrence kernel ----------------------
struct SmemT {
    float w1 [HID * 16];    // [k][oo][g]
    float wi2[HID * 16];
    float wh2[HID * 16];
    u64   xch[512];         // [bp*4+oo][4]
    float c1s[256];         // [b][oo]
    float c2s[256];
};

__device__ __forceinline__ void grid_barrier(int t) {
    __syncthreads();
    if (threadIdx.x == 0) {
        __threadfence();   // release (emits CCTL.IVALL too)
        unsigned prev = atomicAdd(&g_bar_cnt, 1u);
        if (prev == (unsigned)NBLK * (unsigned)(t + 1) - 1u) {
            g_bar_flag = (unsigned)(t + 1);
        } else {
            while (g_bar_flag < (unsigned)(t + 1)) { }
        }
        __threadfence();   // acquire + invalidate this SM's L1D
    }
    __syncthreads();
}

__device__ __forceinline__ void gemm_range(
    const float* __restrict__ a0, const float* __restrict__ a1,
    const float* __restrict__ w, int klen,
    u64 &c00, u64 &c01, u64 &c10, u64 &c11)
{
#pragma unroll 2
    for (int kk = 0; kk < klen; kk += 8) {
        float ar0[8], ar1[8];
        *(float4*)&ar0[0] = *(const float4*)(a0 + kk);
        *(float4*)&ar0[4] = *(const float4*)(a0 + kk + 4);
        *(float4*)&ar1[0] = *(const float4*)(a1 + kk);
        *(float4*)&ar1[4] = *(const float4*)(a1 + kk + 4);
#pragma unroll
        for (int j = 0; j < 8; j++) {
            const float* wk = w + (kk + j) * 16;
            u64 w0 = *(const u64*)wk;
            u64 w1 = *(const u64*)(wk + 2);
            u64 d0 = dup2(ar0[j]), d1 = dup2(ar1[j]);
            fma2(c00, d0, w0); fma2(c01, d0, w1);
            fma2(c10, d1, w0); fma2(c11, d1, w1);
        }
    }
}

__global__ __launch_bounds__(256, 1) void lstm_recur(
    const float* __restrict__ wh1, const float* __restrict__ wi2g,
    const float* __restrict__ wh2g,
    const float* __restrict__ c1in, const float* __restrict__ c2in)
{
    extern __shared__ char smraw[];
    SmemT* sm = (SmemT*)smraw;
    const int tid = threadIdx.x;
    const int bi  = blockIdx.x;
    const int o0  = bi * 4;

    // weights: [k][oo][g] <- W[g][k][o0+oo], once for all 100 steps
    for (int idx = tid; idx < HID * 16; idx += 256) {
        int k = idx >> 4, c = idx & 15;
        int oo = c >> 2, g = c & 3;
        size_t src = ((size_t)g * HID + k) * HID + o0 + oo;
        sm->w1 [idx] = wh1 [src];
        sm->wi2[idx] = wi2g[src];
        sm->wh2[idx] = wh2g[src];
    }
    {   // c state slice
        int b = tid >> 2, oo = tid & 3;
        sm->c1s[tid] = c1in[b * HID + o0 + oo];
        sm->c2s[tid] = c2in[b * HID + o0 + oo];
    }
    __syncthreads();

    const int ks = tid >> 7;        // k-split half
    const int r  = tid & 127;
    const int oo = r & 3;
    const int bp = r >> 2;
    const int b0 = bp * 2;
    const int col = o0 + oo;
    u64* xc = sm->xch + r * 4;

    for (int t = 0; t < T_STEPS; t++) {
        const int rp = t & 1, wp = rp ^ 1;

        // ---------------- Phase A: layer1 (h1 @ wh1 + XW1) ----------------
        float xwv[8];
        if (ks == 0) {
            const float* xr = g_XW1 + ((size_t)t * BATCH + b0) * NGATE + col;
#pragma unroll
            for (int g = 0; g < 4; g++) {
                xwv[g]     = xr[g * HID];
                xwv[4 + g] = xr[NGATE + g * HID];
            }
        }
        u64 c00 = 0, c01 = 0, c10 = 0, c11 = 0;
        {
            const float* a0 = g_h1buf + rp * (BATCH * HID) + b0 * HID + ks * 256;
            const float* w  = sm->w1 + (ks * 256) * 16 + oo * 4;
            gemm_range(a0, a0 + HID, w, 256, c00, c01, c10, c11);
        }
        if (ks == 1) { xc[0] = c00; xc[1] = c01; xc[2] = c10; xc[3] = c11; }
        __syncthreads();
        if (ks == 0) {
            add2(c00, xc[0]); add2(c01, xc[1]); add2(c10, xc[2]); add2(c11, xc[3]);
            float2 if0 = unpack2(c00), go0 = unpack2(c01);
            float2 if1 = unpack2(c10), go1 = unpack2(c11);
            float iv0 = if0.x + xwv[0], fv0 = if0.y + xwv[1];
            float gv0 = go0.x + xwv[2], ov0 = go0.y + xwv[3];
            float iv1 = if1.x + xwv[4], fv1 = if1.y + xwv[5];
            float gv1 = go1.x + xwv[6], ov1 = go1.y + xwv[7];
            float cA = sm->c1s[b0 * 4 + oo], cB = sm->c1s[(b0 + 1) * 4 + oo];
            float cn0 = sigm(fv0) * cA + sigm(iv0) * tanhf(gv0);
            float cn1 = sigm(fv1) * cB + sigm(iv1) * tanhf(gv1);
            sm->c1s[b0 * 4 + oo] = cn0;
            sm->c1s[(b0 + 1) * 4 + oo] = cn1;
            g_h1buf[wp * (BATCH * HID) + b0 * HID + col]       = sigm(ov0) * tanhf(cn0);
            g_h1buf[wp * (BATCH * HID) + (b0 + 1) * HID + col] = sigm(ov1) * tanhf(cn1);
        }

        grid_barrier(t);

        // ---------------- Phase B: layer2 (h1new @ wi2 + h2 @ wh2) --------
        c00 = 0; c01 = 0; c10 = 0; c11 = 0;
        if (ks == 0) {
            const float* a0 = g_h1buf + wp * (BATCH * HID) + b0 * HID;
            gemm_range(a0, a0 + HID, sm->wi2 + oo * 4, HID, c00, c01, c10, c11);
        } else {
            const float* a0 = g_h2buf + rp * (BATCH * HID) + b0 * HID;
            gemm_range(a0, a0 + HID, sm->wh2 + oo * 4, HID, c00, c01, c10, c11);
        }
        if (ks == 1) { xc[0] = c00; xc[1] = c01; xc[2] = c10; xc[3] = c11; }
        __syncthreads();
        if (ks == 0) {
            add2(c00, xc[0]); add2(c01, xc[1]); add2(c10, xc[2]); add2(c11, xc[3]);
            float2 if0 = unpack2(c00), go0 = unpack2(c01);
            float2 if1 = unpack2(c10), go1 = unpack2(c11);
            float cA = sm->c2s[b0 * 4 + oo], cB = sm->c2s[(b0 + 1) * 4 + oo];
            float cn0 = sigm(if0.y) * cA + sigm(if0.x) * tanhf(go0.x);
            float cn1 = sigm(if1.y) * cB + sigm(if1.x) * tanhf(go1.x);
            sm->c2s[b0 * 4 + oo] = cn0;
            sm->c2s[(b0 + 1) * 4 + oo] = cn1;
            float hn0 = sigm(go0.y) * tanhf(cn0);
            float hn1 = sigm(go1.y) * tanhf(cn1);
            g_h2buf[wp * (BATCH * HID) + b0 * HID + col]       = hn0;
            g_h2buf[wp * (BATCH * HID) + (b0 + 1) * HID + col] = hn1;
            g_H2[((size_t)t * BATCH + b0) * HID + col]     = hn0;
            g_H2[((size_t)t * BATCH + b0 + 1) * HID + col] = hn1;
        }
        __syncthreads();   // protect xch before next step's phase A store
    }

    // final c slices
    {
        int b = tid >> 2, oo2 = tid & 3;
        g_c1f[b * HID + o0 + oo2] = sm->c1s[tid];
        g_c2f[b * HID + o0 + oo2] = sm->c2s[tid];
    }
}

// ------------------------- decoder: tf32 tensor-core GEMM --------------------
// D[m, v] = H2[m, :] . dec_w[v, :] + dec_b[v]
// Block tile 128m x 256n, K-chunk 32, 8 warps of 64x64 (m16n8k8 atoms).
// SMEM holds fragment-order tiles so mainloop loads are LDS.128 / LDS.64.
#define DEC_SM_FLOATS (2 * (4096 + 8192))

__global__ __launch_bounds__(256, 1) void decoder_tf32(
    const float* __restrict__ A,      // g_H2 [6400][512]
    const float* __restrict__ Bw,     // dec_w [10000][512]
    const float* __restrict__ bias,
    float* __restrict__ out)
{
    extern __shared__ float smf[];
    float* Af = smf;            // [2][4096]  A frags: ((m_atom*4+ka)*32+lane)*4+reg
    float* Bf = smf + 8192;     // [2][8192]  B frags: ((n_atom*4+ka)*32+lane)*2+reg

    const int tid  = threadIdx.x;
    const int m0   = blockIdx.y * 128;
    const int n0   = blockIdx.x * 256;
    const int warp = tid >> 5, lane = tid & 31;
    const int wm = warp >> 2, wn = warp & 3;
    const int g  = lane >> 2, t4 = lane & 3;

    float acc[4][8][4];
#pragma unroll
    for (int i = 0; i < 4; i++)
#pragma unroll
        for (int j = 0; j < 8; j++)
#pragma unroll
            for (int q = 0; q < 4; q++) acc[i][j][q] = 0.f;

    // staging thread mapping
    const int ar = tid >> 1;                 // A row 0..127
    const int ah = (tid & 1) * 16;           // A k-half
    const int a_matom = ar >> 4;
    const int a_g = (ar & 15) & 7, a_hi = (ar & 15) >> 3;
    const float* a_src = A + (size_t)(m0 + ar) * HID + ah;

    const int bv = n0 + tid;                 // B row (vocab)
    const int b_natom = tid >> 3, b_g = tid & 7;
    const bool b_ok = bv < VOCAB;
    const float* b_src = Bw + (size_t)bv * HID;

#define STAGE(k0, buf)                                                         \
    {                                                                          \
        float* da = Af + (buf) * 4096;                                         \
        _Pragma("unroll")                                                      \
        for (int q = 0; q < 4; q++) {                                          \
            float4 v = *(const float4*)(a_src + (k0) + 4 * q);                 \
            int kk = ah + 4 * q;                                               \
            int ka = kk >> 3, khi = (kk >> 2) & 1;                             \
            float* d = da + ((a_matom * 4 + ka) * 32 + a_g * 4) * 4            \
                          + a_hi + 2 * khi;                                    \
            d[0]  = cvt_tf32(v.x); d[4]  = cvt_tf32(v.y);                      \
            d[8]  = cvt_tf32(v.z); d[12] = cvt_tf32(v.w);                      \
        }                                                                      \
        float* db = Bf + (buf) * 8192;                                         \
        _Pragma("unroll")                                                      \
        for (int q = 0; q < 8; q++) {                                          \
            float4 v = b_ok ? *(const float4*)(b_src + (k0) + 4 * q)           \
                            : make_float4(0.f, 0.f, 0.f, 0.f);                 \
            int kk = 4 * q;                                                    \
            int ka = kk >> 3, khi = (kk >> 2) & 1;                             \
            float* d = db + ((b_natom * 4 + ka) * 32 + b_g * 4) * 2 + khi;     \
            d[0] = cvt_tf32(v.x); d[2] = cvt_tf32(v.y);                        \
            d[4] = cvt_tf32(v.z); d[6] = cvt_tf32(v.w);                        \
        }                                                                      \
    }

    STAGE(0, 0);
    __syncthreads();

    for (int c = 0; c < 16; c++) {
        const int cur = c & 1, nxt = cur ^ 1;
        if (c < 15) STAGE((c + 1) * 32, nxt);
        const float* Ab = Af + cur * 4096;
        const float* Bb = Bf + cur * 8192;
#pragma unroll
        for (int ka = 0; ka < 4; ka++) {
            uint4 af[4];
            uint2 bf[8];
#pragma unroll
            for (int i = 0; i < 4; i++)
                af[i] = *(const uint4*)(Ab + (((wm * 4 + i) * 4 + ka) * 32 + lane) * 4);
#pragma unroll
            for (int j = 0; j < 8; j++)
                bf[j] = *(const uint2*)(Bb + (((wn * 8 + j) * 4 + ka) * 32 + lane) * 2);
#pragma unroll
            for (int i = 0; i < 4; i++)
#pragma unroll
                for (int j = 0; j < 8; j++)
                    mma_tf32(acc[i][j], af[i], bf[j]);
        }
        __syncthreads();
    }
#undef STAGE

    // epilogue: + bias, guarded float2 stores
#pragma unroll
    for (int i = 0; i < 4; i++) {
        int mrow = m0 + wm * 64 + i * 16 + g;
#pragma unroll
        for (int j = 0; j < 8; j++) {
            int cb = n0 + wn * 64 + j * 8 + t4 * 2;
            if (cb < VOCAB) {
                float bb0 = bias[cb], bb1 = bias[cb + 1];
                float2 v0 = make_float2(acc[i][j][0] + bb0, acc[i][j][1] + bb1);
                float2 v1 = make_float2(acc[i][j][2] + bb0, acc[i][j][3] + bb1);
                *(float2*)&out[(size_t)mrow * VOCAB + cb]       = v0;
                *(float2*)&out[(size_t)(mrow + 8) * VOCAB + cb] = v1;
            }
        }
    }
}

// ------------------------- finals -------------------------------------------
__global__ void write_finals(float* __restrict__ out) {
    int i = blockIdx.x * blockDim.x + threadIdx.x;
    if (i < BATCH * HID) {
        float* o = out + (size_t)T_STEPS * BATCH * VOCAB;
        o[i]                   = g_h1buf[i];    // T even -> parity 0 slot
        o[BATCH * HID + i]     = g_h2buf[i];
        o[2 * BATCH * HID + i] = g_c1f[i];
        o[3 * BATCH * HID + i] = g_c2f[i];
    }
}

// ------------------------- launch -------------------------------------------
extern "C" void kernel_launch(void* const* d_in, const int* in_sizes, int n_in,
                              void* d_out, int out_size) {
    const int*   raw   = (const int*)  d_in[0];
    const float* h1    = (const float*)d_in[1];
    const float* h2    = (const float*)d_in[2];
    const float* c1    = (const float*)d_in[3];
    const float* c2    = (const float*)d_in[4];
    const float* emb   = (const float*)d_in[5];
    const float* wi1   = (const float*)d_in[6];
    const float* wh1   = (const float*)d_in[7];
    const float* wi2   = (const float*)d_in[8];
    const float* wh2   = (const float*)d_in[9];
    const float* dec_w = (const float*)d_in[10];
    const float* dec_b = (const float*)d_in[11];
    float* out = (float*)d_out;

    float* p_h2buf;
    cudaGetSymbolAddress((void**)&p_h2buf, g_H2);

    static int attr_set = 0;
    if (!attr_set) {
        cudaFuncSetAttribute(lstm_recur, cudaFuncAttributeMaxDynamicSharedMemorySize,
                             (int)sizeof(SmemT));
        cudaFuncSetAttribute(decoder_tf32, cudaFuncAttributeMaxDynamicSharedMemorySize,
                             DEC_SM_FLOATS * 4);
        attr_set = 1;
    }

    init_state<<<128, 256>>>(h1, h2);
    precompute_xw1<<<dim3(16, 50), 256>>>(raw, emb, wi1);
    lstm_recur<<<NBLK, 256, sizeof(SmemT)>>>(wh1, wi2, wh2, c1, c2);
    decoder_tf32<<<dim3(40, 50), 256, DEC_SM_FLOATS * 4>>>(p_h2buf, dec_w, dec_b, out);
    write_finals<<<128, 256>>>(out);
}

// round 6
// speedup vs baseline: 2.1841x; 1.1840x over previous
#include <cuda_runtime.h>
#include <cuda_bf16.h>
#include <math.h>

#define T_STEPS 100
#define BATCH   64
#define HID     512
#define NGATE   2048   // 4*512
#define VOCAB   10000
#define NVPAD   10240  // vocab padded to 256
#define NBLK    128

typedef unsigned long long u64;

// ------------------------- scratch (static device memory) -------------------
__device__ float g_XW1[T_STEPS * BATCH * NGATE];       // [t][b][g*512+o]
__device__ float g_AfragH2[T_STEPS * BATCH * HID];     // h2 in A-fragment order
__device__ float g_BfragDec[NVPAD * HID];              // dec_w in B-fragment order
__device__ float g_h1buf[2 * BATCH * HID];
__device__ float g_h2buf[2 * BATCH * HID];
__device__ float g_c1f[BATCH * HID];
__device__ float g_c2f[BATCH * HID];
__device__ unsigned g_bar_cnt;
__device__ volatile unsigned g_bar_flag;

// ------------------------- f32x2 helpers -------------------------------------
__device__ __forceinline__ u64 pack2(float x, float y) {
    u64 r;
    asm("mov.b64 %0, {%1, %2};" : "=l"(r)
        : "r"(__float_as_uint(x)), "r"(__float_as_uint(y)));
    return r;
}
__device__ __forceinline__ u64 dup2(float x) {
    u64 r;
    asm("mov.b64 %0, {%1, %1};" : "=l"(r) : "r"(__float_as_uint(x)));
    return r;
}
__device__ __forceinline__ void fma2(u64 &d, u64 a, u64 b) {
    asm("fma.rn.f32x2 %0, %1, %2, %0;" : "+l"(d) : "l"(a), "l"(b));
}
__device__ __forceinline__ void add2(u64 &d, u64 a) {
    asm("add.rn.f32x2 %0, %0, %1;" : "+l"(d) : "l"(a));
}
__device__ __forceinline__ float2 unpack2(u64 v) {
    float2 r;
    r.x = __uint_as_float((unsigned)(v & 0xFFFFFFFFu));
    r.y = __uint_as_float((unsigned)(v >> 32));
    return r;
}
__device__ __forceinline__ float sigm(float x) { return 1.f / (1.f + expf(-x)); }

// ------------------------- tf32 mma helpers ----------------------------------
__device__ __forceinline__ float cvt_tf32(float x) {
    unsigned r;
    asm("cvt.rn.tf32.f32 %0, %1;" : "=r"(r) : "f"(x));
    return __uint_as_float(r);
}
__device__ __forceinline__ void mma_tf32(float* d, const uint4& a, const uint2& b) {
    asm("mma.sync.aligned.m16n8k8.row.col.f32.tf32.tf32.f32 "
        "{%0,%1,%2,%3}, {%4,%5,%6,%7}, {%8,%9}, {%0,%1,%2,%3};"
        : "+f"(d[0]), "+f"(d[1]), "+f"(d[2]), "+f"(d[3])
        : "r"(a.x), "r"(a.y), "r"(a.z), "r"(a.w), "r"(b.x), "r"(b.y));
}

// ------------------------- cp.async helpers ----------------------------------
__device__ __forceinline__ void cp_async16(void* dst, const void* src) {
    unsigned d = (unsigned)__cvta_generic_to_shared(dst);
    asm volatile("cp.async.cg.shared.global [%0], [%1], 16;" :: "r"(d), "l"(src));
}
__device__ __forceinline__ void cp_commit() {
    asm volatile("cp.async.commit_group;");
}
template<int N> __device__ __forceinline__ void cp_wait() {
    asm volatile("cp.async.wait_group %0;" :: "n"(N));
}

// ------------------------- init ----------------------------------------------
__global__ void init_state(const float* __restrict__ h1, const float* __restrict__ h2) {
    int i = blockIdx.x * blockDim.x + threadIdx.x;
    if (i < BATCH * HID) {
        g_h1buf[i] = h1[i];   // parity-0 slot
        g_h2buf[i] = h2[i];
    }
    if (i == 0) { g_bar_cnt = 0; g_bar_flag = 0; }
}

// ------------------------- conv: dec_w -> B-fragment order -------------------
// Bfrag[nb][kc][natom 32][ka 4][lane 32][reg 2]; per (nb,kc) = 32KB contiguous.
// lane = (n&7)*4 + (k&3); reg = (k>>2)&1.
__global__ __launch_bounds__(256) void conv_b_dec(const float* __restrict__ Bw) {
    const int n  = blockIdx.x * 256 + threadIdx.x;   // 0..10239
    const int kg = blockIdx.y;                       // 0..63
    const int k0 = kg * 8;

    float v[8];
    if (n < VOCAB) {
        float4 a = *(const float4*)(Bw + (size_t)n * HID + k0);
        float4 b = *(const float4*)(Bw + (size_t)n * HID + k0 + 4);
        v[0]=a.x; v[1]=a.y; v[2]=a.z; v[3]=a.w;
        v[4]=b.x; v[5]=b.y; v[6]=b.z; v[7]=b.w;
    } else {
#pragma unroll
        for (int j = 0; j < 8; j++) v[j] = 0.f;
    }
    const int nb = n >> 8, nn = n & 255, natom = nn >> 3, g = nn & 7;
    const int kc = k0 >> 5, ka = (k0 & 31) >> 3;
    float* dst = g_BfragDec +
        ((((size_t)(nb * 16 + kc) * 32 + natom) * 4 + ka) * 32 + g * 4) * 2;
    // offset(j) = 2*(j&3) + (j>>2)  -> {v0,v4,v1,v5} {v2,v6,v3,v7}
    float4 o0 = make_float4(cvt_tf32(v[0]), cvt_tf32(v[4]), cvt_tf32(v[1]), cvt_tf32(v[5]));
    float4 o1 = make_float4(cvt_tf32(v[2]), cvt_tf32(v[6]), cvt_tf32(v[3]), cvt_tf32(v[7]));
    *(float4*)dst       = o0;
    *(float4*)(dst + 4) = o1;
}

// ------------------------- precompute XW1 = emb[tok] @ wi1 -------------------
__global__ __launch_bounds__(256) void precompute_xw1(
    const int* __restrict__ tok, const float* __restrict__ emb,
    const float* __restrict__ wi1)
{
    __shared__ float As[8][128];
    __shared__ float Bs[8][128];
    __shared__ int   toks[128];

    const int tid = threadIdx.x;
    const int m0 = blockIdx.y * 128;
    const int n0 = blockIdx.x * 128;
    const int g  = n0 >> 9;
    const float* wbase = wi1 + (size_t)g * HID * HID + (n0 & 511);

    if (tid < 128) toks[tid] = tok[m0 + tid];
    __syncthreads();

    const int lr = tid >> 1;
    const int lk = (tid & 1) * 4;
    const int bk = tid >> 5;
    const int bn = (tid & 31) * 4;
    const int tx = tid & 15, ty = tid >> 4;

    u64 acc[8][4];
#pragma unroll
    for (int i = 0; i < 8; i++)
#pragma unroll
        for (int j = 0; j < 4; j++) acc[i][j] = 0ULL;

    for (int k0 = 0; k0 < HID; k0 += 8) {
        float4 av = *(const float4*)(emb + (size_t)toks[lr] * HID + k0 + lk);
        As[lk+0][lr] = av.x; As[lk+1][lr] = av.y; As[lk+2][lr] = av.z; As[lk+3][lr] = av.w;
        float4 bv = *(const float4*)(wbase + (size_t)(k0 + bk) * HID + bn);
        *(float4*)&Bs[bk][bn] = bv;
        __syncthreads();
#pragma unroll
        for (int k = 0; k < 8; k++) {
            float4 a0 = *(float4*)&As[k][ty * 4];
            float4 a1 = *(float4*)&As[k][64 + ty * 4];
            float4 b0 = *(float4*)&Bs[k][tx * 4];
            float4 b1 = *(float4*)&Bs[k][64 + tx * 4];
            u64 bp0 = pack2(b0.x, b0.y), bp1 = pack2(b0.z, b0.w);
            u64 bp2 = pack2(b1.x, b1.y), bp3 = pack2(b1.z, b1.w);
            float ar[8] = {a0.x, a0.y, a0.z, a0.w, a1.x, a1.y, a1.z, a1.w};
#pragma unroll
            for (int i = 0; i < 8; i++) {
                u64 ad = dup2(ar[i]);
                fma2(acc[i][0], ad, bp0);
                fma2(acc[i][1], ad, bp1);
                fma2(acc[i][2], ad, bp2);
                fma2(acc[i][3], ad, bp3);
            }
        }
        __syncthreads();
    }
#pragma unroll
    for (int i = 0; i < 8; i++) {
        int m = m0 + (i < 4 ? ty * 4 + i : 64 + ty * 4 + (i - 4));
        float* orow = g_XW1 + (size_t)m * NGATE + n0;
#pragma unroll
        for (int j = 0; j < 4; j++) {
            float2 v = unpack2(acc[i][j]);
            int cb = (j < 2) ? (tx * 4 + j * 2) : (64 + tx * 4 + (j - 2) * 2);
            orow[cb] = v.x; orow[cb + 1] = v.y;
        }
    }
}

// ------------------------- persistent recurrence kernel ----------------------
// (identical to round 4 except the g_H2 stores are replaced by A-fragment stores)
struct SmemT {
    float w1 [HID * 16];    // [k][oo][g]
    float wi2[HID * 16];
    float wh2[HID * 16];
    u64   xch[512];         // [bp*4+oo][4]
    float c1s[256];         // [b][oo]
    float c2s[256];
};

__device__ __forceinline__ void grid_barrier(int t) {
    __syncthreads();
    if (threadIdx.x == 0) {
        __threadfence();   // release (emits CCTL.IVALL too)
        unsigned prev = atomicAdd(&g_bar_cnt, 1u);
        if (prev == (unsigned)NBLK * (unsigned)(t + 1) - 1u) {
            g_bar_flag = (unsigned)(t + 1);
        } else {
            while (g_bar_flag < (unsigned)(t + 1)) { }
        }
        __threadfence();   // acquire + invalidate this SM's L1D
    }
    __syncthreads();
}

__device__ __forceinline__ void gemm_range(
    const float* __restrict__ a0, const float* __restrict__ a1,
    const float* __restrict__ w, int klen,
    u64 &c00, u64 &c01, u64 &c10, u64 &c11)
{
#pragma unroll 2
    for (int kk = 0; kk < klen; kk += 8) {
        float ar0[8], ar1[8];
        *(float4*)&ar0[0] = *(const float4*)(a0 + kk);
        *(float4*)&ar0[4] = *(const float4*)(a0 + kk + 4);
        *(float4*)&ar1[0] = *(const float4*)(a1 + kk);
        *(float4*)&ar1[4] = *(const float4*)(a1 + kk + 4);
#pragma unroll
        for (int j = 0; j < 8; j++) {
            const float* wk = w + (kk + j) * 16;
            u64 w0 = *(const u64*)wk;
            u64 w1 = *(const u64*)(wk + 2);
            u64 d0 = dup2(ar0[j]), d1 = dup2(ar1[j]);
            fma2(c00, d0, w0); fma2(c01, d0, w1);
            fma2(c10, d1, w0); fma2(c11, d1, w1);
        }
    }
}

// h2 value (m = t*64+b, k = col) -> A-fragment global index
__device__ __forceinline__ size_t afrag_idx(int m, int kc, int ka, int lk, int khi) {
    int mb = m >> 7, mm = m & 127, matom = mm >> 4, r16 = mm & 15;
    int lane = (r16 & 7) * 4 + lk;
    int reg  = (r16 >> 3) + 2 * khi;
    return ((((size_t)(mb * 16 + kc) * 8 + matom) * 4 + ka) * 32 + lane) * 4 + reg;
}

__global__ __launch_bounds__(256, 1) void lstm_recur(
    const float* __restrict__ wh1, const float* __restrict__ wi2g,
    const float* __restrict__ wh2g,
    const float* __restrict__ c1in, const float* __restrict__ c2in)
{
    extern __shared__ char smraw[];
    SmemT* sm = (SmemT*)smraw;
    const int tid = threadIdx.x;
    const int bi  = blockIdx.x;
    const int o0  = bi * 4;

    // weights: [k][oo][g] <- W[g][k][o0+oo], once for all 100 steps
    for (int idx = tid; idx < HID * 16; idx += 256) {
        int k = idx >> 4, c = idx & 15;
        int oo = c >> 2, g = c & 3;
        size_t src = ((size_t)g * HID + k) * HID + o0 + oo;
        sm->w1 [idx] = wh1 [src];
        sm->wi2[idx] = wi2g[src];
        sm->wh2[idx] = wh2g[src];
    }
    {   // c state slice
        int b = tid >> 2, oo = tid & 3;
        sm->c1s[tid] = c1in[b * HID + o0 + oo];
        sm->c2s[tid] = c2in[b * HID + o0 + oo];
    }
    __syncthreads();

    const int ks = tid >> 7;        // k-split half
    const int r  = tid & 127;
    const int oo = r & 3;
    const int bp = r >> 2;
    const int b0 = bp * 2;
    const int col = o0 + oo;
    u64* xc = sm->xch + r * 4;

    // A-fragment constants for (k = col)
    const int f_kc = col >> 5, f_kk = col & 31;
    const int f_ka = f_kk >> 3, f_lk = f_kk & 3, f_khi = (f_kk >> 2) & 1;

    for (int t = 0; t < T_STEPS; t++) {
        const int rp = t & 1, wp = rp ^ 1;

        // ---------------- Phase A: layer1 (h1 @ wh1 + XW1) ----------------
        float xwv[8];
        if (ks == 0) {
            const float* xr = g_XW1 + ((size_t)t * BATCH + b0) * NGATE + col;
#pragma unroll
            for (int g = 0; g < 4; g++) {
                xwv[g]     = xr[g * HID];
                xwv[4 + g] = xr[NGATE + g * HID];
            }
        }
        u64 c00 = 0, c01 = 0, c10 = 0, c11 = 0;
        {
            const float* a0 = g_h1buf + rp * (BATCH * HID) + b0 * HID + ks * 256;
            const float* w  = sm->w1 + (ks * 256) * 16 + oo * 4;
            gemm_range(a0, a0 + HID, w, 256, c00, c01, c10, c11);
        }
        if (ks == 1) { xc[0] = c00; xc[1] = c01; xc[2] = c10; xc[3] = c11; }
        __syncthreads();
        if (ks == 0) {
            add2(c00, xc[0]); add2(c01, xc[1]); add2(c10, xc[2]); add2(c11, xc[3]);
            float2 if0 = unpack2(c00), go0 = unpack2(c01);
            float2 if1 = unpack2(c10), go1 = unpack2(c11);
            float iv0 = if0.x + xwv[0], fv0 = if0.y + xwv[1];
            float gv0 = go0.x + xwv[2], ov0 = go0.y + xwv[3];
            float iv1 = if1.x + xwv[4], fv1 = if1.y + xwv[5];
            float gv1 = go1.x + xwv[6], ov1 = go1.y + xwv[7];
            float cA = sm->c1s[b0 * 4 + oo], cB = sm->c1s[(b0 + 1) * 4 + oo];
            float cn0 = sigm(fv0) * cA + sigm(iv0) * tanhf(gv0);
            float cn1 = sigm(fv1) * cB + sigm(iv1) * tanhf(gv1);
            sm->c1s[b0 * 4 + oo] = cn0;
            sm->c1s[(b0 + 1) * 4 + oo] = cn1;
            g_h1buf[wp * (BATCH * HID) + b0 * HID + col]       = sigm(ov0) * tanhf(cn0);
            g_h1buf[wp * (BATCH * HID) + (b0 + 1) * HID + col] = sigm(ov1) * tanhf(cn1);
        }

        grid_barrier(t);

        // ---------------- Phase B: layer2 (h1new @ wi2 + h2 @ wh2) --------
        c00 = 0; c01 = 0; c10 = 0; c11 = 0;
        if (ks == 0) {
            const float* a0 = g_h1buf + wp * (BATCH * HID) + b0 * HID;
            gemm_range(a0, a0 + HID, sm->wi2 + oo * 4, HID, c00, c01, c10, c11);
        } else {
            const float* a0 = g_h2buf + rp * (BATCH * HID) + b0 * HID;
            gemm_range(a0, a0 + HID, sm->wh2 + oo * 4, HID, c00, c01, c10, c11);
        }
        if (ks == 1) { xc[0] = c00; xc[1] = c01; xc[2] = c10; xc[3] = c11; }
        __syncthreads();
        if (ks == 0) {
            add2(c00, xc[0]); add2(c01, xc[1]); add2(c10, xc[2]); add2(c11, xc[3]);
            float2 if0 = unpack2(c00), go0 = unpack2(c01);
            float2 if1 = unpack2(c10), go1 = unpack2(c11);
            float cA = sm->c2s[b0 * 4 + oo], cB = sm->c2s[(b0 + 1) * 4 + oo];
            float cn0 = sigm(if0.y) * cA + sigm(if0.x) * tanhf(go0.x);
            float cn1 = sigm(if1.y) * cB + sigm(if1.x) * tanhf(go1.x);
            sm->c2s[b0 * 4 + oo] = cn0;
            sm->c2s[(b0 + 1) * 4 + oo] = cn1;
            float hn0 = sigm(go0.y) * tanhf(cn0);
            float hn1 = sigm(go1.y) * tanhf(cn1);
            g_h2buf[wp * (BATCH * HID) + b0 * HID + col]       = hn0;
            g_h2buf[wp * (BATCH * HID) + (b0 + 1) * HID + col] = hn1;
            int m0 = t * BATCH + b0;
            g_AfragH2[afrag_idx(m0,     f_kc, f_ka, f_lk, f_khi)] = cvt_tf32(hn0);
            g_AfragH2[afrag_idx(m0 + 1, f_kc, f_ka, f_lk, f_khi)] = cvt_tf32(hn1);
        }
        __syncthreads();   // protect xch before next step's phase A store
    }

    // final c slices
    {
        int b = tid >> 2, oo2 = tid & 3;
        g_c1f[b * HID + o0 + oo2] = sm->c1s[tid];
        g_c2f[b * HID + o0 + oo2] = sm->c2s[tid];
    }
}

// ------------------------- decoder: tf32 mma, fragment-order + cp.async ------
// A frag: [mb][kc][matom 8][ka 4][lane][4]  (16KB / (mb,kc))
// B frag: [nb][kc][natom 32][ka 4][lane][2] (32KB / (nb,kc))
#define DEC_SM_FLOATS (2 * 4096 + 2 * 8192)

__global__ __launch_bounds__(256, 1) void decoder_frag(
    const float* __restrict__ Afrag,
    const float* __restrict__ Bfrag,
    const float* __restrict__ bias,
    float* __restrict__ out)
{
    extern __shared__ float smf[];
    float* As = smf;            // [2][4096]
    float* Bs = smf + 8192;     // [2][8192]

    const int tid  = threadIdx.x;
    const int mb   = blockIdx.y;
    const int nb   = blockIdx.x;
    const int warp = tid >> 5, lane = tid & 31;
    const int wm = warp >> 2, wn = warp & 3;

    const float* Ag = Afrag + (size_t)mb * 16 * 4096;
    const float* Bg = Bfrag + (size_t)nb * 16 * 8192;

    float acc[4][8][4];
#pragma unroll
    for (int i = 0; i < 4; i++)
#pragma unroll
        for (int j = 0; j < 8; j++)
#pragma unroll
            for (int q = 0; q < 4; q++) acc[i][j][q] = 0.f;

#define DSTAGE(kc, buf)                                                        \
    {                                                                          \
        _Pragma("unroll")                                                      \
        for (int i = 0; i < 4; i++)                                            \
            cp_async16(As + (buf) * 4096 + (i * 256 + tid) * 4,                \
                       Ag + (kc) * 4096 + (i * 256 + tid) * 4);                \
        _Pragma("unroll")                                                      \
        for (int i = 0; i < 8; i++)                                            \
            cp_async16(Bs + (buf) * 8192 + (i * 256 + tid) * 4,                \
                       Bg + (kc) * 8192 + (i * 256 + tid) * 4);                \
    }

    DSTAGE(0, 0);
    cp_commit();

    for (int c = 0; c < 16; c++) {
        const int cur = c & 1, nxt = cur ^ 1;
        if (c < 15) { DSTAGE(c + 1, nxt); cp_commit(); cp_wait<1>(); }
        else        { cp_wait<0>(); }
        __syncthreads();
        const float* Ab = As + cur * 4096;
        const float* Bb = Bs + cur * 8192;
#pragma unroll
        for (int ka = 0; ka < 4; ka++) {
            uint4 af[4];
            uint2 bf[8];
#pragma unroll
            for (int i = 0; i < 4; i++)
                af[i] = *(const uint4*)(Ab + (((wm * 4 + i) * 4 + ka) * 32 + lane) * 4);
#pragma unroll
            for (int j = 0; j < 8; j++)
                bf[j] = *(const uint2*)(Bb + (((wn * 8 + j) * 4 + ka) * 32 + lane) * 2);
#pragma unroll
            for (int i = 0; i < 4; i++)
#pragma unroll
                for (int j = 0; j < 8; j++)
                    mma_tf32(acc[i][j], af[i], bf[j]);
        }
        __syncthreads();
    }
#undef DSTAGE

    const int g = lane >> 2, t4 = lane & 3;
#pragma unroll
    for (int i = 0; i < 4; i++) {
        int mrow = mb * 128 + wm * 64 + i * 16 + g;
#pragma unroll
        for (int j = 0; j < 8; j++) {
            int cb = nb * 256 + wn * 64 + j * 8 + t4 * 2;
            if (cb < VOCAB) {
                float bb0 = bias[cb], bb1 = bias[cb + 1];
                float2 v0 = make_float2(acc[i][j][0] + bb0, acc[i][j][1] + bb1);
                float2 v1 = make_float2(acc[i][j][2] + bb0, acc[i][j][3] + bb1);
                *(float2*)&out[(size_t)mrow * VOCAB + cb]       = v0;
                *(float2*)&out[(size_t)(mrow + 8) * VOCAB + cb] = v1;
            }
        }
    }
}

// ------------------------- finals -------------------------------------------
__global__ void write_finals(float* __restrict__ out) {
    int i = blockIdx.x * blockDim.x + threadIdx.x;
    if (i < BATCH * HID) {
        float* o = out + (size_t)T_STEPS * BATCH * VOCAB;
        o[i]                   = g_h1buf[i];    // T even -> parity 0 slot
        o[BATCH * HID + i]     = g_h2buf[i];
        o[2 * BATCH * HID + i] = g_c1f[i];
        o[3 * BATCH * HID + i] = g_c2f[i];
    }
}

// ------------------------- launch -------------------------------------------
extern "C" void kernel_launch(void* const* d_in, const int* in_sizes, int n_in,
                              void* d_out, int out_size) {
    const int*   raw   = (const int*)  d_in[0];
    const float* h1    = (const float*)d_in[1];
    const float* h2    = (const float*)d_in[2];
    const float* c1    = (const float*)d_in[3];
    const float* c2    = (const float*)d_in[4];
    const float* emb   = (const float*)d_in[5];
    const float* wi1   = (const float*)d_in[6];
    const float* wh1   = (const float*)d_in[7];
    const float* wi2   = (const float*)d_in[8];
    const float* wh2   = (const float*)d_in[9];
    const float* dec_w = (const float*)d_in[10];
    const float* dec_b = (const float*)d_in[11];
    float* out = (float*)d_out;

    float *p_afrag, *p_bfrag;
    cudaGetSymbolAddress((void**)&p_afrag, g_AfragH2);
    cudaGetSymbolAddress((void**)&p_bfrag, g_BfragDec);

    static int attr_set = 0;
    if (!attr_set) {
        cudaFuncSetAttribute(lstm_recur, cudaFuncAttributeMaxDynamicSharedMemorySize,
                             (int)sizeof(SmemT));
        cudaFuncSetAttribute(decoder_frag, cudaFuncAttributeMaxDynamicSharedMemorySize,
                             DEC_SM_FLOATS * 4);
        attr_set = 1;
    }

    init_state<<<128, 256>>>(h1, h2);
    conv_b_dec<<<dim3(40, 64), 256>>>(dec_w);
    precompute_xw1<<<dim3(16, 50), 256>>>(raw, emb, wi1);
    lstm_recur<<<NBLK, 256, sizeof(SmemT)>>>(wh1, wi2, wh2, c1, c2);
    decoder_frag<<<dim3(40, 50), 256, DEC_SM_FLOATS * 4>>>(p_afrag, p_bfrag, dec_b, out);
    write_finals<<<128, 256>>>(out);
}

// round 7
// speedup vs baseline: 2.2048x; 1.0095x over previous
#include <cuda_runtime.h>
#include <cuda_bf16.h>
#include <math.h>

#define T_STEPS 100
#define BATCH   64
#define HID     512
#define NGATE   2048   // 4*512
#define VOCAB   10000
#define NVPAD   10240  // vocab padded to 256
#define NBLK    128

typedef unsigned long long u64;

// ------------------------- scratch (static device memory) -------------------
__device__ float g_XW1[T_STEPS * BATCH * NGATE];       // [t][b][g*512+o]
__device__ float g_AfragH2[T_STEPS * BATCH * HID];     // h2 in A-fragment order
__device__ float g_BfragDec[NVPAD * HID];              // dec_w in B-fragment order
__device__ float g_h1buf[2 * BATCH * HID];
__device__ float g_h2buf[2 * BATCH * HID];
__device__ float g_c1f[BATCH * HID];
__device__ float g_c2f[BATCH * HID];
__device__ unsigned g_bar_cnt;
__device__ volatile unsigned g_bar_flag;

// ------------------------- f32x2 helpers -------------------------------------
__device__ __forceinline__ u64 pack2(float x, float y) {
    u64 r;
    asm("mov.b64 %0, {%1, %2};" : "=l"(r)
        : "r"(__float_as_uint(x)), "r"(__float_as_uint(y)));
    return r;
}
__device__ __forceinline__ u64 dup2(float x) {
    u64 r;
    asm("mov.b64 %0, {%1, %1};" : "=l"(r) : "r"(__float_as_uint(x)));
    return r;
}
__device__ __forceinline__ void fma2(u64 &d, u64 a, u64 b) {
    asm("fma.rn.f32x2 %0, %1, %2, %0;" : "+l"(d) : "l"(a), "l"(b));
}
__device__ __forceinline__ void add2(u64 &d, u64 a) {
    asm("add.rn.f32x2 %0, %0, %1;" : "+l"(d) : "l"(a));
}
__device__ __forceinline__ float2 unpack2(u64 v) {
    float2 r;
    r.x = __uint_as_float((unsigned)(v & 0xFFFFFFFFu));
    r.y = __uint_as_float((unsigned)(v >> 32));
    return r;
}
__device__ __forceinline__ float sigm(float x) { return 1.f / (1.f + expf(-x)); }

// ------------------------- tf32 mma helpers ----------------------------------
__device__ __forceinline__ float cvt_tf32(float x) {
    unsigned r;
    asm("cvt.rn.tf32.f32 %0, %1;" : "=r"(r) : "f"(x));
    return __uint_as_float(r);
}
__device__ __forceinline__ void mma_tf32(float* d, const uint4& a, const uint2& b) {
    asm("mma.sync.aligned.m16n8k8.row.col.f32.tf32.tf32.f32 "
        "{%0,%1,%2,%3}, {%4,%5,%6,%7}, {%8,%9}, {%0,%1,%2,%3};"
        : "+f"(d[0]), "+f"(d[1]), "+f"(d[2]), "+f"(d[3])
        : "r"(a.x), "r"(a.y), "r"(a.z), "r"(a.w), "r"(b.x), "r"(b.y));
}

// ------------------------- cp.async helpers ----------------------------------
__device__ __forceinline__ void cp_async16(void* dst, const void* src) {
    unsigned d = (unsigned)__cvta_generic_to_shared(dst);
    asm volatile("cp.async.cg.shared.global [%0], [%1], 16;" :: "r"(d), "l"(src));
}
__device__ __forceinline__ void cp_commit() {
    asm volatile("cp.async.commit_group;");
}
template<int N> __device__ __forceinline__ void cp_wait() {
    asm volatile("cp.async.wait_group %0;" :: "n"(N));
}

// ------------------------- init ----------------------------------------------
__global__ void init_state(const float* __restrict__ h1, const float* __restrict__ h2) {
    int i = blockIdx.x * blockDim.x + threadIdx.x;
    if (i < BATCH * HID) {
        g_h1buf[i] = h1[i];   // parity-0 slot
        g_h2buf[i] = h2[i];
    }
    if (i == 0) { g_bar_cnt = 0; g_bar_flag = 0; }
}

// ------------------------- conv: dec_w -> B-fragment order -------------------
__global__ __launch_bounds__(256) void conv_b_dec(const float* __restrict__ Bw) {
    const int n  = blockIdx.x * 256 + threadIdx.x;   // 0..10239
    const int kg = blockIdx.y;                       // 0..63
    const int k0 = kg * 8;

    float v[8];
    if (n < VOCAB) {
        float4 a = *(const float4*)(Bw + (size_t)n * HID + k0);
        float4 b = *(const float4*)(Bw + (size_t)n * HID + k0 + 4);
        v[0]=a.x; v[1]=a.y; v[2]=a.z; v[3]=a.w;
        v[4]=b.x; v[5]=b.y; v[6]=b.z; v[7]=b.w;
    } else {
#pragma unroll
        for (int j = 0; j < 8; j++) v[j] = 0.f;
    }
    const int nb = n >> 8, nn = n & 255, natom = nn >> 3, g = nn & 7;
    const int kc = k0 >> 5, ka = (k0 & 31) >> 3;
    float* dst = g_BfragDec +
        ((((size_t)(nb * 16 + kc) * 32 + natom) * 4 + ka) * 32 + g * 4) * 2;
    float4 o0 = make_float4(cvt_tf32(v[0]), cvt_tf32(v[4]), cvt_tf32(v[1]), cvt_tf32(v[5]));
    float4 o1 = make_float4(cvt_tf32(v[2]), cvt_tf32(v[6]), cvt_tf32(v[3]), cvt_tf32(v[7]));
    *(float4*)dst       = o0;
    *(float4*)(dst + 4) = o1;
}

// ------------------------- precompute XW1 = emb[tok] @ wi1 -------------------
__global__ __launch_bounds__(256) void precompute_xw1(
    const int* __restrict__ tok, const float* __restrict__ emb,
    const float* __restrict__ wi1)
{
    __shared__ float As[8][128];
    __shared__ float Bs[8][128];
    __shared__ int   toks[128];

    const int tid = threadIdx.x;
    const int m0 = blockIdx.y * 128;
    const int n0 = blockIdx.x * 128;
    const int g  = n0 >> 9;
    const float* wbase = wi1 + (size_t)g * HID * HID + (n0 & 511);

    if (tid < 128) toks[tid] = tok[m0 + tid];
    __syncthreads();

    const int lr = tid >> 1;
    const int lk = (tid & 1) * 4;
    const int bk = tid >> 5;
    const int bn = (tid & 31) * 4;
    const int tx = tid & 15, ty = tid >> 4;

    u64 acc[8][4];
#pragma unroll
    for (int i = 0; i < 8; i++)
#pragma unroll
        for (int j = 0; j < 4; j++) acc[i][j] = 0ULL;

    for (int k0 = 0; k0 < HID; k0 += 8) {
        float4 av = *(const float4*)(emb + (size_t)toks[lr] * HID + k0 + lk);
        As[lk+0][lr] = av.x; As[lk+1][lr] = av.y; As[lk+2][lr] = av.z; As[lk+3][lr] = av.w;
        float4 bv = *(const float4*)(wbase + (size_t)(k0 + bk) * HID + bn);
        *(float4*)&Bs[bk][bn] = bv;
        __syncthreads();
#pragma unroll
        for (int k = 0; k < 8; k++) {
            float4 a0 = *(float4*)&As[k][ty * 4];
            float4 a1 = *(float4*)&As[k][64 + ty * 4];
            float4 b0 = *(float4*)&Bs[k][tx * 4];
            float4 b1 = *(float4*)&Bs[k][64 + tx * 4];
            u64 bp0 = pack2(b0.x, b0.y), bp1 = pack2(b0.z, b0.w);
            u64 bp2 = pack2(b1.x, b1.y), bp3 = pack2(b1.z, b1.w);
            float ar[8] = {a0.x, a0.y, a0.z, a0.w, a1.x, a1.y, a1.z, a1.w};
#pragma unroll
            for (int i = 0; i < 8; i++) {
                u64 ad = dup2(ar[i]);
                fma2(acc[i][0], ad, bp0);
                fma2(acc[i][1], ad, bp1);
                fma2(acc[i][2], ad, bp2);
                fma2(acc[i][3], ad, bp3);
            }
        }
        __syncthreads();
    }
#pragma unroll
    for (int i = 0; i < 8; i++) {
        int m = m0 + (i < 4 ? ty * 4 + i : 64 + ty * 4 + (i - 4));
        float* orow = g_XW1 + (size_t)m * NGATE + n0;
#pragma unroll
        for (int j = 0; j < 4; j++) {
            float2 v = unpack2(acc[i][j]);
            int cb = (j < 2) ? (tx * 4 + j * 2) : (64 + tx * 4 + (j - 2) * 2);
            orow[cb] = v.x; orow[cb + 1] = v.y;
        }
    }
}

// ------------------------- persistent recurrence kernel ----------------------
// 512 threads: 4-way K-split (ks = tid>>7), r = tid&127 owns (bp, oo).
struct SmemT {
    float w1 [HID * 16];    // [k][oo][g]
    float wi2[HID * 16];
    float wh2[HID * 16];
    u64   xch[3 * 512];     // [writer ks-1][r*4 + acc]
    float c1s[256];         // [b][oo]
    float c2s[256];
};

__device__ __forceinline__ void grid_barrier(int t) {
    __syncthreads();
    if (threadIdx.x == 0) {
        __threadfence();   // release (emits CCTL.IVALL too)
        unsigned prev = atomicAdd(&g_bar_cnt, 1u);
        if (prev == (unsigned)NBLK * (unsigned)(t + 1) - 1u) {
            g_bar_flag = (unsigned)(t + 1);
        } else {
            while (g_bar_flag < (unsigned)(t + 1)) { }
        }
        __threadfence();   // acquire + invalidate this SM's L1D
    }
    __syncthreads();
}

// round-4 structure; weight read is one LDS.128 (layout-equivalent to 2 LDS.64)
__device__ __forceinline__ void gemm_range(
    const float* __restrict__ a0, const float* __restrict__ a1,
    const float* __restrict__ w, int klen,
    u64 &c00, u64 &c01, u64 &c10, u64 &c11)
{
#pragma unroll 2
    for (int kk = 0; kk < klen; kk += 8) {
        float ar0[8], ar1[8];
        *(float4*)&ar0[0] = *(const float4*)(a0 + kk);
        *(float4*)&ar0[4] = *(const float4*)(a0 + kk + 4);
        *(float4*)&ar1[0] = *(const float4*)(a1 + kk);
        *(float4*)&ar1[4] = *(const float4*)(a1 + kk + 4);
#pragma unroll
        for (int j = 0; j < 8; j++) {
            float4 wv = *(const float4*)(w + (kk + j) * 16);
            u64 w0 = pack2(wv.x, wv.y);
            u64 w1 = pack2(wv.z, wv.w);
            u64 d0 = dup2(ar0[j]), d1 = dup2(ar1[j]);
            fma2(c00, d0, w0); fma2(c01, d0, w1);
            fma2(c10, d1, w0); fma2(c11, d1, w1);
        }
    }
}

// h2 value (m = t*64+b, k = col) -> A-fragment global index
__device__ __forceinline__ size_t afrag_idx(int m, int kc, int ka, int lk, int khi) {
    int mb = m >> 7, mm = m & 127, matom = mm >> 4, r16 = mm & 15;
    int lane = (r16 & 7) * 4 + lk;
    int reg  = (r16 >> 3) + 2 * khi;
    return ((((size_t)(mb * 16 + kc) * 8 + matom) * 4 + ka) * 32 + lane) * 4 + reg;
}

__global__ __launch_bounds__(512, 1) void lstm_recur(
    const float* __restrict__ wh1, const float* __restrict__ wi2g,
    const float* __restrict__ wh2g,
    const float* __restrict__ c1in, const float* __restrict__ c2in)
{
    extern __shared__ char smraw[];
    SmemT* sm = (SmemT*)smraw;
    const int tid = threadIdx.x;
    const int bi  = blockIdx.x;
    const int o0  = bi * 4;

    // weights: [k][oo][g] <- W[g][k][o0+oo], once for all 100 steps
    for (int idx = tid; idx < HID * 16; idx += 512) {
        int k = idx >> 4, c = idx & 15;
        int oo = c >> 2, g = c & 3;
        size_t src = ((size_t)g * HID + k) * HID + o0 + oo;
        sm->w1 [idx] = wh1 [src];
        sm->wi2[idx] = wi2g[src];
        sm->wh2[idx] = wh2g[src];
    }
    if (tid < 256) {   // c state slice
        int b = tid >> 2, oo = tid & 3;
        sm->c1s[tid] = c1in[b * HID + o0 + oo];
        sm->c2s[tid] = c2in[b * HID + o0 + oo];
    }
    __syncthreads();

    const int ks = tid >> 7;        // k-split quarter: 0..3
    const int r  = tid & 127;
    const int oo = r & 3;
    const int bp = r >> 2;
    const int b0 = bp * 2;
    const int col = o0 + oo;

    // A-fragment constants for (k = col)
    const int f_kc = col >> 5, f_kk = col & 31;
    const int f_ka = f_kk >> 3, f_lk = f_kk & 3, f_khi = (f_kk >> 2) & 1;

    for (int t = 0; t < T_STEPS; t++) {
        const int rp = t & 1, wp = rp ^ 1;

        // ---------------- Phase A: layer1 (h1 @ wh1 + XW1), K split 4x128 --
        float xwv[8];
        if (ks == 0) {
            const float* xr = g_XW1 + ((size_t)t * BATCH + b0) * NGATE + col;
#pragma unroll
            for (int g = 0; g < 4; g++) {
                xwv[g]     = xr[g * HID];
                xwv[4 + g] = xr[NGATE + g * HID];
            }
        }
        u64 c00 = 0, c01 = 0, c10 = 0, c11 = 0;
        {
            const float* a0 = g_h1buf + rp * (BATCH * HID) + b0 * HID + ks * 128;
            const float* w  = sm->w1 + (ks * 128) * 16 + oo * 4;
            gemm_range(a0, a0 + HID, w, 128, c00, c01, c10, c11);
        }
        if (ks != 0) {
            u64* xc = sm->xch + (ks - 1) * 512 + r * 4;
            xc[0] = c00; xc[1] = c01; xc[2] = c10; xc[3] = c11;
        }
        __syncthreads();
        if (ks == 0) {
#pragma unroll
            for (int s = 0; s < 3; s++) {
                const u64* xc = sm->xch + s * 512 + r * 4;
                add2(c00, xc[0]); add2(c01, xc[1]);
                add2(c10, xc[2]); add2(c11, xc[3]);
            }
            float2 if0 = unpack2(c00), go0 = unpack2(c01);
            float2 if1 = unpack2(c10), go1 = unpack2(c11);
            float iv0 = if0.x + xwv[0], fv0 = if0.y + xwv[1];
            float gv0 = go0.x + xwv[2], ov0 = go0.y + xwv[3];
            float iv1 = if1.x + xwv[4], fv1 = if1.y + xwv[5];
            float gv1 = go1.x + xwv[6], ov1 = go1.y + xwv[7];
            float cA = sm->c1s[b0 * 4 + oo], cB = sm->c1s[(b0 + 1) * 4 + oo];
            float cn0 = sigm(fv0) * cA + sigm(iv0) * tanhf(gv0);
            float cn1 = sigm(fv1) * cB + sigm(iv1) * tanhf(gv1);
            sm->c1s[b0 * 4 + oo] = cn0;
            sm->c1s[(b0 + 1) * 4 + oo] = cn1;
            g_h1buf[wp * (BATCH * HID) + b0 * HID + col]       = sigm(ov0) * tanhf(cn0);
            g_h1buf[wp * (BATCH * HID) + (b0 + 1) * HID + col] = sigm(ov1) * tanhf(cn1);
        }

        grid_barrier(t);

        // ------- Phase B: layer2; ks0/1 -> wi2 halves, ks2/3 -> wh2 halves --
        c00 = 0; c01 = 0; c10 = 0; c11 = 0;
        {
            const int half = (ks & 1) * 256;
            const float* aB;
            const float* wB;
            if (ks < 2) {
                aB = g_h1buf + wp * (BATCH * HID) + b0 * HID + half;
                wB = sm->wi2 + half * 16 + oo * 4;
            } else {
                aB = g_h2buf + rp * (BATCH * HID) + b0 * HID + half;
                wB = sm->wh2 + half * 16 + oo * 4;
            }
            gemm_range(aB, aB + HID, wB, 256, c00, c01, c10, c11);
        }
        if (ks != 0) {
            u64* xc = sm->xch + (ks - 1) * 512 + r * 4;
            xc[0] = c00; xc[1] = c01; xc[2] = c10; xc[3] = c11;
        }
        __syncthreads();
        if (ks == 0) {
#pragma unroll
            for (int s = 0; s < 3; s++) {
                const u64* xc = sm->xch + s * 512 + r * 4;
                add2(c00, xc[0]); add2(c01, xc[1]);
                add2(c10, xc[2]); add2(c11, xc[3]);
            }
            float2 if0 = unpack2(c00), go0 = unpack2(c01);
            float2 if1 = unpack2(c10), go1 = unpack2(c11);
            float cA = sm->c2s[b0 * 4 + oo], cB = sm->c2s[(b0 + 1) * 4 + oo];
            float cn0 = sigm(if0.y) * cA + sigm(if0.x) * tanhf(go0.x);
            float cn1 = sigm(if1.y) * cB + sigm(if1.x) * tanhf(go1.x);
            sm->c2s[b0 * 4 + oo] = cn0;
            sm->c2s[(b0 + 1) * 4 + oo] = cn1;
            float hn0 = sigm(go0.y) * tanhf(cn0);
            float hn1 = sigm(go1.y) * tanhf(cn1);
            g_h2buf[wp * (BATCH * HID) + b0 * HID + col]       = hn0;
            g_h2buf[wp * (BATCH * HID) + (b0 + 1) * HID + col] = hn1;
            int m0 = t * BATCH + b0;
            g_AfragH2[afrag_idx(m0,     f_kc, f_ka, f_lk, f_khi)] = cvt_tf32(hn0);
            g_AfragH2[afrag_idx(m0 + 1, f_kc, f_ka, f_lk, f_khi)] = cvt_tf32(hn1);
        }
        __syncthreads();   // protect xch before next step's phase A store
    }

    // final c slices
    if (tid < 256) {
        int b = tid >> 2, oo2 = tid & 3;
        g_c1f[b * HID + o0 + oo2] = sm->c1s[tid];
        g_c2f[b * HID + o0 + oo2] = sm->c2s[tid];
    }
}

// ------------------------- decoder: tf32 mma, fragment-order + cp.async ------
#define DEC_SM_FLOATS (2 * 4096 + 2 * 8192)

__global__ __launch_bounds__(256, 1) void decoder_frag(
    const float* __restrict__ Afrag,
    const float* __restrict__ Bfrag,
    const float* __restrict__ bias,
    float* __restrict__ out)
{
    extern __shared__ float smf[];
    float* As = smf;            // [2][4096]
    float* Bs = smf + 8192;     // [2][8192]

    const int tid  = threadIdx.x;
    const int mb   = blockIdx.y;
    const int nb   = blockIdx.x;
    const int warp = tid >> 5, lane = tid & 31;
    const int wm = warp >> 2, wn = warp & 3;

    const float* Ag = Afrag + (size_t)mb * 16 * 4096;
    const float* Bg = Bfrag + (size_t)nb * 16 * 8192;

    float acc[4][8][4];
#pragma unroll
    for (int i = 0; i < 4; i++)
#pragma unroll
        for (int j = 0; j < 8; j++)
#pragma unroll
            for (int q = 0; q < 4; q++) acc[i][j][q] = 0.f;

#define DSTAGE(kc, buf)                                                        \
    {                                                                          \
        _Pragma("unroll")                                                      \
        for (int i = 0; i < 4; i++)                                            \
            cp_async16(As + (buf) * 4096 + (i * 256 + tid) * 4,                \
                       Ag + (kc) * 4096 + (i * 256 + tid) * 4);                \
        _Pragma("unroll")                                                      \
        for (int i = 0; i < 8; i++)                                            \
            cp_async16(Bs + (buf) * 8192 + (i * 256 + tid) * 4,                \
                       Bg + (kc) * 8192 + (i * 256 + tid) * 4);                \
    }

    DSTAGE(0, 0);
    cp_commit();

    for (int c = 0; c < 16; c++) {
        const int cur = c & 1, nxt = cur ^ 1;
        if (c < 15) { DSTAGE(c + 1, nxt); cp_commit(); cp_wait<1>(); }
        else        { cp_wait<0>(); }
        __syncthreads();
        const float* Ab = As + cur * 4096;
        const float* Bb = Bs + cur * 8192;
#pragma unroll
        for (int ka = 0; ka < 4; ka++) {
            uint4 af[4];
            uint2 bf[8];
#pragma unroll
            for (int i = 0; i < 4; i++)
                af[i] = *(const uint4*)(Ab + (((wm * 4 + i) * 4 + ka) * 32 + lane) * 4);
#pragma unroll
            for (int j = 0; j < 8; j++)
                bf[j] = *(const uint2*)(Bb + (((wn * 8 + j) * 4 + ka) * 32 + lane) * 2);
#pragma unroll
            for (int i = 0; i < 4; i++)
#pragma unroll
                for (int j = 0; j < 8; j++)
                    mma_tf32(acc[i][j], af[i], bf[j]);
        }
        __syncthreads();
    }
#undef DSTAGE

    const int g = lane >> 2, t4 = lane & 3;
#pragma unroll
    for (int i = 0; i < 4; i++) {
        int mrow = mb * 128 + wm * 64 + i * 16 + g;
#pragma unroll
        for (int j = 0; j < 8; j++) {
            int cb = nb * 256 + wn * 64 + j * 8 + t4 * 2;
            if (cb < VOCAB) {
                float bb0 = bias[cb], bb1 = bias[cb + 1];
                float2 v0 = make_float2(acc[i][j][0] + bb0, acc[i][j][1] + bb1);
                float2 v1 = make_float2(acc[i][j][2] + bb0, acc[i][j][3] + bb1);
                *(float2*)&out[(size_t)mrow * VOCAB + cb]       = v0;
                *(float2*)&out[(size_t)(mrow + 8) * VOCAB + cb] = v1;
            }
        }
    }
}

// ------------------------- finals -------------------------------------------
__global__ void write_finals(float* __restrict__ out) {
    int i = blockIdx.x * blockDim.x + threadIdx.x;
    if (i < BATCH * HID) {
        float* o = out + (size_t)T_STEPS * BATCH * VOCAB;
        o[i]                   = g_h1buf[i];    // T even -> parity 0 slot
        o[BATCH * HID + i]     = g_h2buf[i];
        o[2 * BATCH * HID + i] = g_c1f[i];
        o[3 * BATCH * HID + i] = g_c2f[i];
    }
}

// ------------------------- launch -------------------------------------------
extern "C" void kernel_launch(void* const* d_in, const int* in_sizes, int n_in,
                              void* d_out, int out_size) {
    const int*   raw   = (const int*)  d_in[0];
    const float* h1    = (const float*)d_in[1];
    const float* h2    = (const float*)d_in[2];
    const float* c1    = (const float*)d_in[3];
    const float* c2    = (const float*)d_in[4];
    const float* emb   = (const float*)d_in[5];
    const float* wi1   = (const float*)d_in[6];
    const float* wh1   = (const float*)d_in[7];
    const float* wi2   = (const float*)d_in[8];
    const float* wh2   = (const float*)d_in[9];
    const float* dec_w = (const float*)d_in[10];
    const float* dec_b = (const float*)d_in[11];
    float* out = (float*)d_out;

    float *p_afrag, *p_bfrag;
    cudaGetSymbolAddress((void**)&p_afrag, g_AfragH2);
    cudaGetSymbolAddress((void**)&p_bfrag, g_BfragDec);

    static int attr_set = 0;
    if (!attr_set) {
        cudaFuncSetAttribute(lstm_recur, cudaFuncAttributeMaxDynamicSharedMemorySize,
                             (int)sizeof(SmemT));
        cudaFuncSetAttribute(decoder_frag, cudaFuncAttributeMaxDynamicSharedMemorySize,
                             DEC_SM_FLOATS * 4);
        attr_set = 1;
    }

    init_state<<<128, 256>>>(h1, h2);
    conv_b_dec<<<dim3(40, 64), 256>>>(dec_w);
    precompute_xw1<<<dim3(16, 50), 256>>>(raw, emb, wi1);
    lstm_recur<<<NBLK, 512, sizeof(SmemT)>>>(wh1, wi2, wh2, c1, c2);
    decoder_frag<<<dim3(40, 50), 256, DEC_SM_FLOATS * 4>>>(p_afrag, p_bfrag, dec_b, out);
    write_finals<<<128, 256>>>(out);
}

// round 8
// speedup vs baseline: 2.6249x; 1.1905x over previous
#include <cuda_runtime.h>
#include <cuda_bf16.h>
#include <math.h>

#define T_STEPS 100
#define BATCH   64
#define HID     512
#define NGATE   2048   // 4*512
#define VOCAB   10000
#define NVPAD   10240  // vocab padded to 256
#define NBLK    128
#define BH      (BATCH * HID)

typedef unsigned long long u64;

// ------------------------- scratch (static device memory) -------------------
__device__ float g_XW1[T_STEPS * BATCH * NGATE];       // [t][b][g*512+o]
__device__ float g_AfragH2[T_STEPS * BATCH * HID];     // h2 in A-fragment order
__device__ float g_BfragDec[NVPAD * HID];              // dec_w in B-fragment order
__device__ float g_h1buf[2 * BH];                      // K-MAJOR: [k][64 b]
__device__ float g_h2buf[2 * BH];                      // K-MAJOR: [k][64 b]
__device__ float g_c1f[BH];
__device__ float g_c2f[BH];
__device__ unsigned g_bar_cnt;
__device__ volatile unsigned g_bar_flag;

// ------------------------- f32x2 helpers -------------------------------------
__device__ __forceinline__ u64 pack2(float x, float y) {
    u64 r;
    asm("mov.b64 %0, {%1, %2};" : "=l"(r)
        : "r"(__float_as_uint(x)), "r"(__float_as_uint(y)));
    return r;
}
__device__ __forceinline__ u64 dup2(float x) {
    u64 r;
    asm("mov.b64 %0, {%1, %1};" : "=l"(r) : "r"(__float_as_uint(x)));
    return r;
}
__device__ __forceinline__ void fma2(u64 &d, u64 a, u64 b) {
    asm("fma.rn.f32x2 %0, %1, %2, %0;" : "+l"(d) : "l"(a), "l"(b));
}
__device__ __forceinline__ void add2(u64 &d, u64 a) {
    asm("add.rn.f32x2 %0, %0, %1;" : "+l"(d) : "l"(a));
}
__device__ __forceinline__ float2 unpack2(u64 v) {
    float2 r;
    r.x = __uint_as_float((unsigned)(v & 0xFFFFFFFFu));
    r.y = __uint_as_float((unsigned)(v >> 32));
    return r;
}
__device__ __forceinline__ float sigm(float x) { return 1.f / (1.f + expf(-x)); }

// ------------------------- tf32 mma helpers ----------------------------------
__device__ __forceinline__ float cvt_tf32(float x) {
    unsigned r;
    asm("cvt.rn.tf32.f32 %0, %1;" : "=r"(r) : "f"(x));
    return __uint_as_float(r);
}
__device__ __forceinline__ void mma_tf32(float* d, const uint4& a, const uint2& b) {
    asm("mma.sync.aligned.m16n8k8.row.col.f32.tf32.tf32.f32 "
        "{%0,%1,%2,%3}, {%4,%5,%6,%7}, {%8,%9}, {%0,%1,%2,%3};"
        : "+f"(d[0]), "+f"(d[1]), "+f"(d[2]), "+f"(d[3])
        : "r"(a.x), "r"(a.y), "r"(a.z), "r"(a.w), "r"(b.x), "r"(b.y));
}

// ------------------------- cp.async helpers ----------------------------------
__device__ __forceinline__ void cp_async16(void* dst, const void* src) {
    unsigned d = (unsigned)__cvta_generic_to_shared(dst);
    asm volatile("cp.async.cg.shared.global [%0], [%1], 16;" :: "r"(d), "l"(src));
}
__device__ __forceinline__ void cp_commit() {
    asm volatile("cp.async.commit_group;");
}
template<int N> __device__ __forceinline__ void cp_wait() {
    asm volatile("cp.async.wait_group %0;" :: "n"(N));
}

// ------------------------- init (transpose states to k-major) ----------------
__global__ void init_state(const float* __restrict__ h1, const float* __restrict__ h2) {
    int i = blockIdx.x * blockDim.x + threadIdx.x;
    if (i < BH) {
        int k = i >> 6, b = i & 63;
        g_h1buf[i] = h1[b * HID + k];   // parity-0 slot, [k][b]
        g_h2buf[i] = h2[b * HID + k];
    }
    if (i == 0) { g_bar_cnt = 0; g_bar_flag = 0; }
}

// ------------------------- conv: dec_w -> B-fragment order -------------------
__global__ __launch_bounds__(256) void conv_b_dec(const float* __restrict__ Bw) {
    const int n  = blockIdx.x * 256 + threadIdx.x;   // 0..10239
    const int kg = blockIdx.y;                       // 0..63
    const int k0 = kg * 8;

    float v[8];
    if (n < VOCAB) {
        float4 a = *(const float4*)(Bw + (size_t)n * HID + k0);
        float4 b = *(const float4*)(Bw + (size_t)n * HID + k0 + 4);
        v[0]=a.x; v[1]=a.y; v[2]=a.z; v[3]=a.w;
        v[4]=b.x; v[5]=b.y; v[6]=b.z; v[7]=b.w;
    } else {
#pragma unroll
        for (int j = 0; j < 8; j++) v[j] = 0.f;
    }
    const int nb = n >> 8, nn = n & 255, natom = nn >> 3, g = nn & 7;
    const int kc = k0 >> 5, ka = (k0 & 31) >> 3;
    float* dst = g_BfragDec +
        ((((size_t)(nb * 16 + kc) * 32 + natom) * 4 + ka) * 32 + g * 4) * 2;
    float4 o0 = make_float4(cvt_tf32(v[0]), cvt_tf32(v[4]), cvt_tf32(v[1]), cvt_tf32(v[5]));
    float4 o1 = make_float4(cvt_tf32(v[2]), cvt_tf32(v[6]), cvt_tf32(v[3]), cvt_tf32(v[7]));
    *(float4*)dst       = o0;
    *(float4*)(dst + 4) = o1;
}

// ------------------------- precompute XW1 = emb[tok] @ wi1 -------------------
__global__ __launch_bounds__(256) void precompute_xw1(
    const int* __restrict__ tok, const float* __restrict__ emb,
    const float* __restrict__ wi1)
{
    __shared__ float As[8][128];
    __shared__ float Bs[8][128];
    __shared__ int   toks[128];

    const int tid = threadIdx.x;
    const int m0 = blockIdx.y * 128;
    const int n0 = blockIdx.x * 128;
    const int g  = n0 >> 9;
    const float* wbase = wi1 + (size_t)g * HID * HID + (n0 & 511);

    if (tid < 128) toks[tid] = tok[m0 + tid];
    __syncthreads();

    const int lr = tid >> 1;
    const int lk = (tid & 1) * 4;
    const int bk = tid >> 5;
    const int bn = (tid & 31) * 4;
    const int tx = tid & 15, ty = tid >> 4;

    u64 acc[8][4];
#pragma unroll
    for (int i = 0; i < 8; i++)
#pragma unroll
        for (int j = 0; j < 4; j++) acc[i][j] = 0ULL;

    for (int k0 = 0; k0 < HID; k0 += 8) {
        float4 av = *(const float4*)(emb + (size_t)toks[lr] * HID + k0 + lk);
        As[lk+0][lr] = av.x; As[lk+1][lr] = av.y; As[lk+2][lr] = av.z; As[lk+3][lr] = av.w;
        float4 bv = *(const float4*)(wbase + (size_t)(k0 + bk) * HID + bn);
        *(float4*)&Bs[bk][bn] = bv;
        __syncthreads();
#pragma unroll
        for (int k = 0; k < 8; k++) {
            float4 a0 = *(float4*)&As[k][ty * 4];
            float4 a1 = *(float4*)&As[k][64 + ty * 4];
            float4 b0 = *(float4*)&Bs[k][tx * 4];
            float4 b1 = *(float4*)&Bs[k][64 + tx * 4];
            u64 bp0 = pack2(b0.x, b0.y), bp1 = pack2(b0.z, b0.w);
            u64 bp2 = pack2(b1.x, b1.y), bp3 = pack2(b1.z, b1.w);
            float ar[8] = {a0.x, a0.y, a0.z, a0.w, a1.x, a1.y, a1.z, a1.w};
#pragma unroll
            for (int i = 0; i < 8; i++) {
                u64 ad = dup2(ar[i]);
                fma2(acc[i][0], ad, bp0);
                fma2(acc[i][1], ad, bp1);
                fma2(acc[i][2], ad, bp2);
                fma2(acc[i][3], ad, bp3);
            }
        }
        __syncthreads();
    }
#pragma unroll
    for (int i = 0; i < 8; i++) {
        int m = m0 + (i < 4 ? ty * 4 + i : 64 + ty * 4 + (i - 4));
        float* orow = g_XW1 + (size_t)m * NGATE + n0;
#pragma unroll
        for (int j = 0; j < 4; j++) {
            float2 v = unpack2(acc[i][j]);
            int cb = (j < 2) ? (tx * 4 + j * 2) : (64 + tx * 4 + (j - 2) * 2);
            orow[cb] = v.x; orow[cb + 1] = v.y;
        }
    }
}

// ------------------------- persistent recurrence kernel ----------------------
// 512 threads: 4-way K-split (ks = tid>>7), r = tid&127 owns (bp, oo).
// h buffers are K-MAJOR [k][64 b] -> per-k LDG.64 loads both batch rows,
// warp-coalesced (8 bp x 8B contiguous, oo broadcast).
struct SmemT {
    float w1 [HID * 16];    // [k][oo][g]
    float wi2[HID * 16];
    float wh2[HID * 16];
    u64   xch[3 * 512];     // [writer ks-1][r*4 + acc]
    float c1s[256];         // [b][oo]
    float c2s[256];
};

__device__ __forceinline__ void grid_barrier(int t) {
    __syncthreads();
    if (threadIdx.x == 0) {
        __threadfence();   // release (emits CCTL.IVALL too)
        unsigned prev = atomicAdd(&g_bar_cnt, 1u);
        if (prev == (unsigned)NBLK * (unsigned)(t + 1) - 1u) {
            g_bar_flag = (unsigned)(t + 1);
        } else {
            while (g_bar_flag < (unsigned)(t + 1)) { }
        }
        __threadfence();   // acquire + invalidate this SM's L1D
    }
    __syncthreads();
}

// hk: k-major h base already offset by b0 (stride 64 floats per k).
// Same FMA order as round 7 (k ascending, 4 fma2 per k).
__device__ __forceinline__ void gemm_range(
    const float* __restrict__ hk,
    const float* __restrict__ w, int klen,
    u64 &c00, u64 &c01, u64 &c10, u64 &c11)
{
#pragma unroll 2
    for (int kk = 0; kk < klen; kk += 8) {
        u64 hv[8];
#pragma unroll
        for (int j = 0; j < 8; j++)
            hv[j] = *(const u64*)(hk + (size_t)(kk + j) * BATCH);
#pragma unroll
        for (int j = 0; j < 8; j++) {
            float2 hf = unpack2(hv[j]);
            float4 wv = *(const float4*)(w + (kk + j) * 16);
            u64 w0 = pack2(wv.x, wv.y);
            u64 w1 = pack2(wv.z, wv.w);
            u64 d0 = dup2(hf.x), d1 = dup2(hf.y);
            fma2(c00, d0, w0); fma2(c01, d0, w1);
            fma2(c10, d1, w0); fma2(c11, d1, w1);
        }
    }
}

// h2 value (m = t*64+b, k = col) -> A-fragment global index
__device__ __forceinline__ size_t afrag_idx(int m, int kc, int ka, int lk, int khi) {
    int mb = m >> 7, mm = m & 127, matom = mm >> 4, r16 = mm & 15;
    int lane = (r16 & 7) * 4 + lk;
    int reg  = (r16 >> 3) + 2 * khi;
    return ((((size_t)(mb * 16 + kc) * 8 + matom) * 4 + ka) * 32 + lane) * 4 + reg;
}

__global__ __launch_bounds__(512, 1) void lstm_recur(
    const float* __restrict__ wh1, const float* __restrict__ wi2g,
    const float* __restrict__ wh2g,
    const float* __restrict__ c1in, const float* __restrict__ c2in)
{
    extern __shared__ char smraw[];
    SmemT* sm = (SmemT*)smraw;
    const int tid = threadIdx.x;
    const int bi  = blockIdx.x;
    const int o0  = bi * 4;

    // weights: [k][oo][g] <- W[g][k][o0+oo], once for all 100 steps
    for (int idx = tid; idx < HID * 16; idx += 512) {
        int k = idx >> 4, c = idx & 15;
        int oo = c >> 2, g = c & 3;
        size_t src = ((size_t)g * HID + k) * HID + o0 + oo;
        sm->w1 [idx] = wh1 [src];
        sm->wi2[idx] = wi2g[src];
        sm->wh2[idx] = wh2g[src];
    }
    if (tid < 256) {   // c state slice
        int b = tid >> 2, oo = tid & 3;
        sm->c1s[tid] = c1in[b * HID + o0 + oo];
        sm->c2s[tid] = c2in[b * HID + o0 + oo];
    }
    __syncthreads();

    const int ks = tid >> 7;        // k-split quarter: 0..3
    const int r  = tid & 127;
    const int oo = r & 3;
    const int bp = r >> 2;
    const int b0 = bp * 2;
    const int col = o0 + oo;

    // A-fragment constants for (k = col)
    const int f_kc = col >> 5, f_kk = col & 31;
    const int f_ka = f_kk >> 3, f_lk = f_kk & 3, f_khi = (f_kk >> 2) & 1;

    for (int t = 0; t < T_STEPS; t++) {
        const int rp = t & 1, wp = rp ^ 1;

        // ---------------- Phase A: layer1 (h1 @ wh1 + XW1), K split 4x128 --
        float xwv[8];
        if (ks == 0) {
            const float* xr = g_XW1 + ((size_t)t * BATCH + b0) * NGATE + col;
#pragma unroll
            for (int g = 0; g < 4; g++) {
                xwv[g]     = xr[g * HID];
                xwv[4 + g] = xr[NGATE + g * HID];
            }
        }
        u64 c00 = 0, c01 = 0, c10 = 0, c11 = 0;
        {
            const float* hk = g_h1buf + rp * BH + (ks * 128) * BATCH + b0;
            const float* w  = sm->w1 + (ks * 128) * 16 + oo * 4;
            gemm_range(hk, w, 128, c00, c01, c10, c11);
        }
        if (ks != 0) {
            u64* xc = sm->xch + (ks - 1) * 512 + r * 4;
            xc[0] = c00; xc[1] = c01; xc[2] = c10; xc[3] = c11;
        }
        __syncthreads();
        if (ks == 0) {
#pragma unroll
            for (int s = 0; s < 3; s++) {
                const u64* xc = sm->xch + s * 512 + r * 4;
                add2(c00, xc[0]); add2(c01, xc[1]);
                add2(c10, xc[2]); add2(c11, xc[3]);
            }
            float2 if0 = unpack2(c00), go0 = unpack2(c01);
            float2 if1 = unpack2(c10), go1 = unpack2(c11);
            float iv0 = if0.x + xwv[0], fv0 = if0.y + xwv[1];
            float gv0 = go0.x + xwv[2], ov0 = go0.y + xwv[3];
            float iv1 = if1.x + xwv[4], fv1 = if1.y + xwv[5];
            float gv1 = go1.x + xwv[6], ov1 = go1.y + xwv[7];
            float cA = sm->c1s[b0 * 4 + oo], cB = sm->c1s[(b0 + 1) * 4 + oo];
            float cn0 = sigm(fv0) * cA + sigm(iv0) * tanhf(gv0);
            float cn1 = sigm(fv1) * cB + sigm(iv1) * tanhf(gv1);
            sm->c1s[b0 * 4 + oo] = cn0;
            sm->c1s[(b0 + 1) * 4 + oo] = cn1;
            float2 hw = make_float2(sigm(ov0) * tanhf(cn0), sigm(ov1) * tanhf(cn1));
            *(float2*)(g_h1buf + wp * BH + col * BATCH + b0) = hw;
        }

        grid_barrier(t);

        // ------- Phase B: layer2; ks0/1 -> wi2 halves, ks2/3 -> wh2 halves --
        c00 = 0; c01 = 0; c10 = 0; c11 = 0;
        {
            const int half = (ks & 1) * 256;
            const float* hk;
            const float* wB;
            if (ks < 2) {
                hk = g_h1buf + wp * BH + half * BATCH + b0;
                wB = sm->wi2 + half * 16 + oo * 4;
            } else {
                hk = g_h2buf + rp * BH + half * BATCH + b0;
                wB = sm->wh2 + half * 16 + oo * 4;
            }
            gemm_range(hk, wB, 256, c00, c01, c10, c11);
        }
        if (ks != 0) {
            u64* xc = sm->xch + (ks - 1) * 512 + r * 4;
            xc[0] = c00; xc[1] = c01; xc[2] = c10; xc[3] = c11;
        }
        __syncthreads();
        if (ks == 0) {
#pragma unroll
            for (int s = 0; s < 3; s++) {
                const u64* xc = sm->xch + s * 512 + r * 4;
                add2(c00, xc[0]); add2(c01, xc[1]);
                add2(c10, xc[2]); add2(c11, xc[3]);
            }
            float2 if0 = unpack2(c00), go0 = unpack2(c01);
            float2 if1 = unpack2(c10), go1 = unpack2(c11);
            float cA = sm->c2s[b0 * 4 + oo], cB = sm->c2s[(b0 + 1) * 4 + oo];
            float cn0 = sigm(if0.y) * cA + sigm(if0.x) * tanhf(go0.x);
            float cn1 = sigm(if1.y) * cB + sigm(if1.x) * tanhf(go1.x);
            sm->c2s[b0 * 4 + oo] = cn0;
            sm->c2s[(b0 + 1) * 4 + oo] = cn1;
            float hn0 = sigm(go0.y) * tanhf(cn0);
            float hn1 = sigm(go1.y) * tanhf(cn1);
            *(float2*)(g_h2buf + wp * BH + col * BATCH + b0) = make_float2(hn0, hn1);
            int m0 = t * BATCH + b0;
            g_AfragH2[afrag_idx(m0,     f_kc, f_ka, f_lk, f_khi)] = cvt_tf32(hn0);
            g_AfragH2[afrag_idx(m0 + 1, f_kc, f_ka, f_lk, f_khi)] = cvt_tf32(hn1);
        }
        __syncthreads();   // protect xch before next step's phase A store
    }

    // final c slices (b-major, small)
    if (tid < 256) {
        int b = tid >> 2, oo2 = tid & 3;
        g_c1f[b * HID + o0 + oo2] = sm->c1s[tid];
        g_c2f[b * HID + o0 + oo2] = sm->c2s[tid];
    }
}

// ------------------------- decoder: tf32 mma, fragment-order + cp.async ------
#define DEC_SM_FLOATS (2 * 4096 + 2 * 8192)

__global__ __launch_bounds__(256, 1) void decoder_frag(
    const float* __restrict__ Afrag,
    const float* __restrict__ Bfrag,
    const float* __restrict__ bias,
    float* __restrict__ out)
{
    extern __shared__ float smf[];
    float* As = smf;            // [2][4096]
    float* Bs = smf + 8192;     // [2][8192]

    const int tid  = threadIdx.x;
    const int mb   = blockIdx.y;
    const int nb   = blockIdx.x;
    const int warp = tid >> 5, lane = tid & 31;
    const int wm = warp >> 2, wn = warp & 3;

    const float* Ag = Afrag + (size_t)mb * 16 * 4096;
    const float* Bg = Bfrag + (size_t)nb * 16 * 8192;

    float acc[4][8][4];
#pragma unroll
    for (int i = 0; i < 4; i++)
#pragma unroll
        for (int j = 0; j < 8; j++)
#pragma unroll
            for (int q = 0; q < 4; q++) acc[i][j][q] = 0.f;

#define DSTAGE(kc, buf)                                                        \
    {                                                                          \
        _Pragma("unroll")                                                      \
        for (int i = 0; i < 4; i++)                                            \
            cp_async16(As + (buf) * 4096 + (i * 256 + tid) * 4,                \
                       Ag + (kc) * 4096 + (i * 256 + tid) * 4);                \
        _Pragma("unroll")                                                      \
        for (int i = 0; i < 8; i++)                                            \
            cp_async16(Bs + (buf) * 8192 + (i * 256 + tid) * 4,                \
                       Bg + (kc) * 8192 + (i * 256 + tid) * 4);                \
    }

    DSTAGE(0, 0);
    cp_commit();

    for (int c = 0; c < 16; c++) {
        const int cur = c & 1, nxt = cur ^ 1;
        if (c < 15) { DSTAGE(c + 1, nxt); cp_commit(); cp_wait<1>(); }
        else        { cp_wait<0>(); }
        __syncthreads();
        const float* Ab = As + cur * 4096;
        const float* Bb = Bs + cur * 8192;
#pragma unroll
        for (int ka = 0; ka < 4; ka++) {
            uint4 af[4];
            uint2 bf[8];
#pragma unroll
            for (int i = 0; i < 4; i++)
                af[i] = *(const uint4*)(Ab + (((wm * 4 + i) * 4 + ka) * 32 + lane) * 4);
#pragma unroll
            for (int j = 0; j < 8; j++)
                bf[j] = *(const uint2*)(Bb + (((wn * 8 + j) * 4 + ka) * 32 + lane) * 2);
#pragma unroll
            for (int i = 0; i < 4; i++)
#pragma unroll
                for (int j = 0; j < 8; j++)
                    mma_tf32(acc[i][j], af[i], bf[j]);
        }
        __syncthreads();
    }
#undef DSTAGE

    const int g = lane >> 2, t4 = lane & 3;
#pragma unroll
    for (int i = 0; i < 4; i++) {
        int mrow = mb * 128 + wm * 64 + i * 16 + g;
#pragma unroll
        for (int j = 0; j < 8; j++) {
            int cb = nb * 256 + wn * 64 + j * 8 + t4 * 2;
            if (cb < VOCAB) {
                float bb0 = bias[cb], bb1 = bias[cb + 1];
                float2 v0 = make_float2(acc[i][j][0] + bb0, acc[i][j][1] + bb1);
                float2 v1 = make_float2(acc[i][j][2] + bb0, acc[i][j][3] + bb1);
                *(float2*)&out[(size_t)mrow * VOCAB + cb]       = v0;
                *(float2*)&out[(size_t)(mrow + 8) * VOCAB + cb] = v1;
            }
        }
    }
}

// ------------------------- finals (transpose back to b-major) ----------------
__global__ void write_finals(float* __restrict__ out) {
    int i = blockIdx.x * blockDim.x + threadIdx.x;
    if (i < BH) {
        int b = i / HID, k = i % HID;
        float* o = out + (size_t)T_STEPS * BATCH * VOCAB;
        o[i]          = g_h1buf[k * BATCH + b];    // T even -> parity 0 slot
        o[BH + i]     = g_h2buf[k * BATCH + b];
        o[2 * BH + i] = g_c1f[i];
        o[3 * BH + i] = g_c2f[i];
    }
}

// ------------------------- launch -------------------------------------------
extern "C" void kernel_launch(void* const* d_in, const int* in_sizes, int n_in,
                              void* d_out, int out_size) {
    const int*   raw   = (const int*)  d_in[0];
    const float* h1    = (const float*)d_in[1];
    const float* h2    = (const float*)d_in[2];
    const float* c1    = (const float*)d_in[3];
    const float* c2    = (const float*)d_in[4];
    const float* emb   = (const float*)d_in[5];
    const float* wi1   = (const float*)d_in[6];
    const float* wh1   = (const float*)d_in[7];
    const float* wi2   = (const float*)d_in[8];
    const float* wh2   = (const float*)d_in[9];
    const float* dec_w = (const float*)d_in[10];
    const float* dec_b = (const float*)d_in[11];
    float* out = (float*)d_out;

    float *p_afrag, *p_bfrag;
    cudaGetSymbolAddress((void**)&p_afrag, g_AfragH2);
    cudaGetSymbolAddress((void**)&p_bfrag, g_BfragDec);

    static int attr_set = 0;
    if (!attr_set) {
        cudaFuncSetAttribute(lstm_recur, cudaFuncAttributeMaxDynamicSharedMemorySize,
                             (int)sizeof(SmemT));
        cudaFuncSetAttribute(decoder_frag, cudaFuncAttributeMaxDynamicSharedMemorySize,
                             DEC_SM_FLOATS * 4);
        attr_set = 1;
    }

    init_state<<<128, 256>>>(h1, h2);
    conv_b_dec<<<dim3(40, 64), 256>>>(dec_w);
    precompute_xw1<<<dim3(16, 50), 256>>>(raw, emb, wi1);
    lstm_recur<<<NBLK, 512, sizeof(SmemT)>>>(wh1, wi2, wh2, c1, c2);
    decoder_frag<<<dim3(40, 50), 256, DEC_SM_FLOATS * 4>>>(p_afrag, p_bfrag, dec_b, out);
    write_finals<<<128, 256>>>(out);
}

// round 9
// speedup vs baseline: 3.0389x; 1.1577x over previous
#include <cuda_runtime.h>
#include <cuda_bf16.h>
#include <math.h>

#define T_STEPS 100
#define BATCH   64
#define HID     512
#define NGATE   2048   // 4*512
#define VOCAB   10000
#define NVPAD   10240  // vocab padded to 256
#define NBLK    128
#define BH      (BATCH * HID)

typedef unsigned long long u64;

// ------------------------- scratch (static device memory) -------------------
__device__ float g_XW1[T_STEPS * 4 * HID * BATCH];    // [t][g][o][b] k-major
__device__ float g_AfragH2[T_STEPS * BATCH * HID];    // h2 in A-fragment order
__device__ float g_BfragDec[NVPAD * HID];             // dec_w in B-fragment order
__device__ float g_h1buf[2 * BH];                     // K-MAJOR: [k][64 b]
__device__ float g_h2buf[2 * BH];                     // K-MAJOR: [k][64 b]
__device__ float g_c1f[BH];
__device__ float g_c2f[BH];
__device__ unsigned g_bar_cnt;
__device__ volatile unsigned g_bar_flag;

// ------------------------- f32x2 helpers -------------------------------------
__device__ __forceinline__ u64 pack2(float x, float y) {
    u64 r;
    asm("mov.b64 %0, {%1, %2};" : "=l"(r)
        : "r"(__float_as_uint(x)), "r"(__float_as_uint(y)));
    return r;
}
__device__ __forceinline__ u64 dup2(float x) {
    u64 r;
    asm("mov.b64 %0, {%1, %1};" : "=l"(r) : "r"(__float_as_uint(x)));
    return r;
}
__device__ __forceinline__ void fma2(u64 &d, u64 a, u64 b) {
    asm("fma.rn.f32x2 %0, %1, %2, %0;" : "+l"(d) : "l"(a), "l"(b));
}
__device__ __forceinline__ void add2(u64 &d, u64 a) {
    asm("add.rn.f32x2 %0, %0, %1;" : "+l"(d) : "l"(a));
}
__device__ __forceinline__ float2 unpack2(u64 v) {
    float2 r;
    r.x = __uint_as_float((unsigned)(v & 0xFFFFFFFFu));
    r.y = __uint_as_float((unsigned)(v >> 32));
    return r;
}
__device__ __forceinline__ float sigm(float x) { return 1.f / (1.f + expf(-x)); }

// ------------------------- tf32 mma helpers ----------------------------------
__device__ __forceinline__ float cvt_tf32(float x) {
    unsigned r;
    asm("cvt.rn.tf32.f32 %0, %1;" : "=r"(r) : "f"(x));
    return __uint_as_float(r);
}
__device__ __forceinline__ void mma_tf32(float* d, const uint4& a, const uint2& b) {
    asm("mma.sync.aligned.m16n8k8.row.col.f32.tf32.tf32.f32 "
        "{%0,%1,%2,%3}, {%4,%5,%6,%7}, {%8,%9}, {%0,%1,%2,%3};"
        : "+f"(d[0]), "+f"(d[1]), "+f"(d[2]), "+f"(d[3])
        : "r"(a.x), "r"(a.y), "r"(a.z), "r"(a.w), "r"(b.x), "r"(b.y));
}

// ------------------------- cp.async helpers ----------------------------------
__device__ __forceinline__ void cp_async16(void* dst, const void* src) {
    unsigned d = (unsigned)__cvta_generic_to_shared(dst);
    asm volatile("cp.async.cg.shared.global [%0], [%1], 16;" :: "r"(d), "l"(src));
}
__device__ __forceinline__ void cp_commit() {
    asm volatile("cp.async.commit_group;");
}
template<int N> __device__ __forceinline__ void cp_wait() {
    asm volatile("cp.async.wait_group %0;" :: "n"(N));
}

// ------------------------- init (transpose states to k-major) ----------------
__global__ void init_state(const float* __restrict__ h1, const float* __restrict__ h2) {
    int i = blockIdx.x * blockDim.x + threadIdx.x;
    if (i < BH) {
        int k = i >> 6, b = i & 63;
        g_h1buf[i] = h1[b * HID + k];   // parity-0 slot, [k][b]
        g_h2buf[i] = h2[b * HID + k];
    }
    if (i == 0) { g_bar_cnt = 0; g_bar_flag = 0; }
}

// ------------------------- conv: dec_w -> B-fragment order -------------------
__global__ __launch_bounds__(256) void conv_b_dec(const float* __restrict__ Bw) {
    const int n  = blockIdx.x * 256 + threadIdx.x;   // 0..10239
    const int kg = blockIdx.y;                       // 0..63
    const int k0 = kg * 8;

    float v[8];
    if (n < VOCAB) {
        float4 a = *(const float4*)(Bw + (size_t)n * HID + k0);
        float4 b = *(const float4*)(Bw + (size_t)n * HID + k0 + 4);
        v[0]=a.x; v[1]=a.y; v[2]=a.z; v[3]=a.w;
        v[4]=b.x; v[5]=b.y; v[6]=b.z; v[7]=b.w;
    } else {
#pragma unroll
        for (int j = 0; j < 8; j++) v[j] = 0.f;
    }
    const int nb = n >> 8, nn = n & 255, natom = nn >> 3, g = nn & 7;
    const int kc = k0 >> 5, ka = (k0 & 31) >> 3;
    float* dst = g_BfragDec +
        ((((size_t)(nb * 16 + kc) * 32 + natom) * 4 + ka) * 32 + g * 4) * 2;
    float4 o0 = make_float4(cvt_tf32(v[0]), cvt_tf32(v[4]), cvt_tf32(v[1]), cvt_tf32(v[5]));
    float4 o1 = make_float4(cvt_tf32(v[2]), cvt_tf32(v[6]), cvt_tf32(v[3]), cvt_tf32(v[7]));
    *(float4*)dst       = o0;
    *(float4*)(dst + 4) = o1;
}

// ------------------------- precompute XW1 = emb[tok] @ wi1 -------------------
// Output layout: g_XW1[t][g][o][b] (k-major for the recurrence gather).
__global__ __launch_bounds__(256) void precompute_xw1(
    const int* __restrict__ tok, const float* __restrict__ emb,
    const float* __restrict__ wi1)
{
    __shared__ float As[8][128];
    __shared__ float Bs[8][128];
    __shared__ int   toks[128];

    const int tid = threadIdx.x;
    const int m0 = blockIdx.y * 128;
    const int n0 = blockIdx.x * 128;
    const int g  = n0 >> 9;
    const int og0 = n0 & 511;
    const float* wbase = wi1 + (size_t)g * HID * HID + og0;

    if (tid < 128) toks[tid] = tok[m0 + tid];
    __syncthreads();

    const int lr = tid >> 1;
    const int lk = (tid & 1) * 4;
    const int bk = tid >> 5;
    const int bn = (tid & 31) * 4;
    const int tx = tid & 15, ty = tid >> 4;

    u64 acc[8][4];
#pragma unroll
    for (int i = 0; i < 8; i++)
#pragma unroll
        for (int j = 0; j < 4; j++) acc[i][j] = 0ULL;

    for (int k0 = 0; k0 < HID; k0 += 8) {
        float4 av = *(const float4*)(emb + (size_t)toks[lr] * HID + k0 + lk);
        As[lk+0][lr] = av.x; As[lk+1][lr] = av.y; As[lk+2][lr] = av.z; As[lk+3][lr] = av.w;
        float4 bv = *(const float4*)(wbase + (size_t)(k0 + bk) * HID + bn);
        *(float4*)&Bs[bk][bn] = bv;
        __syncthreads();
#pragma unroll
        for (int k = 0; k < 8; k++) {
            float4 a0 = *(float4*)&As[k][ty * 4];
            float4 a1 = *(float4*)&As[k][64 + ty * 4];
            float4 b0 = *(float4*)&Bs[k][tx * 4];
            float4 b1 = *(float4*)&Bs[k][64 + tx * 4];
            u64 bp0 = pack2(b0.x, b0.y), bp1 = pack2(b0.z, b0.w);
            u64 bp2 = pack2(b1.x, b1.y), bp3 = pack2(b1.z, b1.w);
            float ar[8] = {a0.x, a0.y, a0.z, a0.w, a1.x, a1.y, a1.z, a1.w};
#pragma unroll
            for (int i = 0; i < 8; i++) {
                u64 ad = dup2(ar[i]);
                fma2(acc[i][0], ad, bp0);
                fma2(acc[i][1], ad, bp1);
                fma2(acc[i][2], ad, bp2);
                fma2(acc[i][3], ad, bp3);
            }
        }
        __syncthreads();
    }
    // scatter epilogue: element (m, n=g*512+o) -> g_XW1[((t*4+g)*512+o)*64+b]
#pragma unroll
    for (int i = 0; i < 8; i++) {
        int m = m0 + (i < 4 ? ty * 4 + i : 64 + ty * 4 + (i - 4));
        int t = m >> 6, b = m & 63;
        float* tb = g_XW1 + (((size_t)t * 4 + g) * HID) * BATCH + b;
#pragma unroll
        for (int j = 0; j < 4; j++) {
            float2 v = unpack2(acc[i][j]);
            int cb = (j < 2) ? (tx * 4 + j * 2) : (64 + tx * 4 + (j - 2) * 2);
            int o = og0 + cb;
            tb[(size_t)o * BATCH]       = v.x;
            tb[(size_t)(o + 1) * BATCH] = v.y;
        }
    }
}

// ------------------------- persistent recurrence kernel ----------------------
// 512 threads: 8-way K-split (ks = tid>>6), r = tid&63 owns (bq: 4 batches, oo).
// Per k: 1 LDG.128 (h, 4 batches) + 1 LDS.128 (4 gate weights, reinterpreted
// as two u64) + 4 dups + 8 fma2.
struct SmemT {
    float w1 [HID * 16];    // [k][oo][g]
    float wi2[HID * 16];
    float wh2[HID * 16];
    u64   xch[7 * 64 * 8];  // [writer ks-1][r][8 accs]
    float c1s[256];         // [b][oo]
    float c2s[256];
};

__device__ __forceinline__ void grid_barrier(int t) {
    __syncthreads();
    if (threadIdx.x == 0) {
        __threadfence();   // release (emits CCTL.IVALL too)
        unsigned prev = atomicAdd(&g_bar_cnt, 1u);
        if (prev == (unsigned)NBLK * (unsigned)(t + 1) - 1u) {
            g_bar_flag = (unsigned)(t + 1);
        } else {
            while (g_bar_flag < (unsigned)(t + 1)) { }
        }
        __threadfence();   // acquire + invalidate this SM's L1D
    }
    __syncthreads();
}

// acc[b*2+0] = {i,f}, acc[b*2+1] = {g,o} for 4 batches b.
__device__ __forceinline__ void gemm_b4(
    const float* __restrict__ hk,     // k-major h + b0 offset
    const float* __restrict__ w,      // smem weights + oo*4
    int klen, u64 (&acc)[8])
{
#pragma unroll 2
    for (int kk = 0; kk < klen; kk += 4) {
        float4 hv[4];
#pragma unroll
        for (int j = 0; j < 4; j++)
            hv[j] = *(const float4*)(hk + (size_t)(kk + j) * BATCH);
#pragma unroll
        for (int j = 0; j < 4; j++) {
            float4 wv = *(const float4*)(w + (kk + j) * 16);
            u64 w0 = ((const u64*)&wv)[0];
            u64 w1 = ((const u64*)&wv)[1];
            u64 d0 = dup2(hv[j].x), d1 = dup2(hv[j].y);
            u64 d2 = dup2(hv[j].z), d3 = dup2(hv[j].w);
            fma2(acc[0], d0, w0); fma2(acc[1], d0, w1);
            fma2(acc[2], d1, w0); fma2(acc[3], d1, w1);
            fma2(acc[4], d2, w0); fma2(acc[5], d2, w1);
            fma2(acc[6], d3, w0); fma2(acc[7], d3, w1);
        }
    }
}

// h2 value (m = t*64+b, k = col) -> A-fragment global index
__device__ __forceinline__ size_t afrag_idx(int m, int kc, int ka, int lk, int khi) {
    int mb = m >> 7, mm = m & 127, matom = mm >> 4, r16 = mm & 15;
    int lane = (r16 & 7) * 4 + lk;
    int reg  = (r16 >> 3) + 2 * khi;
    return ((((size_t)(mb * 16 + kc) * 8 + matom) * 4 + ka) * 32 + lane) * 4 + reg;
}

__global__ __launch_bounds__(512, 1) void lstm_recur(
    const float* __restrict__ wh1, const float* __restrict__ wi2g,
    const float* __restrict__ wh2g,
    const float* __restrict__ c1in, const float* __restrict__ c2in)
{
    extern __shared__ char smraw[];
    SmemT* sm = (SmemT*)smraw;
    const int tid = threadIdx.x;
    const int bi  = blockIdx.x;
    const int o0  = bi * 4;

    // weights: [k][oo][g] <- W[g][k][o0+oo], once for all 100 steps
    for (int idx = tid; idx < HID * 16; idx += 512) {
        int k = idx >> 4, c = idx & 15;
        int oo = c >> 2, g = c & 3;
        size_t src = ((size_t)g * HID + k) * HID + o0 + oo;
        sm->w1 [idx] = wh1 [src];
        sm->wi2[idx] = wi2g[src];
        sm->wh2[idx] = wh2g[src];
    }
    if (tid < 256) {   // c state slice [b][oo]
        int b = tid >> 2, oo = tid & 3;
        sm->c1s[tid] = c1in[b * HID + o0 + oo];
        sm->c2s[tid] = c2in[b * HID + o0 + oo];
    }
    __syncthreads();

    const int ks = tid >> 6;        // k-split eighth: 0..7
    const int r  = tid & 63;
    const int oo = r & 3;
    const int bq = r >> 2;
    const int b0 = bq * 4;
    const int col = o0 + oo;

    // A-fragment constants for (k = col)
    const int f_kc = col >> 5, f_kk = col & 31;
    const int f_ka = f_kk >> 3, f_lk = f_kk & 3, f_khi = (f_kk >> 2) & 1;

    for (int t = 0; t < T_STEPS; t++) {
        const int rp = t & 1, wp = rp ^ 1;

        // ---------------- Phase A: layer1 (h1 @ wh1 + XW1), K split 8x64 ---
        float4 xwg[4];
        if (ks == 0) {
#pragma unroll
            for (int g = 0; g < 4; g++)
                xwg[g] = *(const float4*)(g_XW1 +
                    (((size_t)t * 4 + g) * HID + col) * BATCH + b0);
        }
        u64 acc[8];
#pragma unroll
        for (int i = 0; i < 8; i++) acc[i] = 0ULL;
        gemm_b4(g_h1buf + rp * BH + (ks * 64) * BATCH + b0,
                sm->w1 + (ks * 64) * 16 + oo * 4, 64, acc);
        if (ks != 0) {
            u64* xc = sm->xch + (ks - 1) * 512 + r * 8;
#pragma unroll
            for (int i = 0; i < 8; i++) xc[i] = acc[i];
        }
        __syncthreads();
        if (ks == 0) {
#pragma unroll
            for (int s = 0; s < 7; s++) {
                const u64* xc = sm->xch + s * 512 + r * 8;
#pragma unroll
                for (int i = 0; i < 8; i++) add2(acc[i], xc[i]);
            }
            float hw[4];
#pragma unroll
            for (int bb = 0; bb < 4; bb++) {
                float2 iff = unpack2(acc[bb * 2]);
                float2 go  = unpack2(acc[bb * 2 + 1]);
                float iv = iff.x + ((const float*)&xwg[0])[bb];
                float fv = iff.y + ((const float*)&xwg[1])[bb];
                float gv = go.x  + ((const float*)&xwg[2])[bb];
                float ov = go.y  + ((const float*)&xwg[3])[bb];
                float c = sm->c1s[(b0 + bb) * 4 + oo];
                float cn = sigm(fv) * c + sigm(iv) * tanhf(gv);
                sm->c1s[(b0 + bb) * 4 + oo] = cn;
                hw[bb] = sigm(ov) * tanhf(cn);
            }
            *(float4*)(g_h1buf + wp * BH + col * BATCH + b0) =
                make_float4(hw[0], hw[1], hw[2], hw[3]);
        }

        grid_barrier(t);

        // ------- Phase B: layer2; ks0-3 -> wi2 quarters, ks4-7 -> wh2 ------
#pragma unroll
        for (int i = 0; i < 8; i++) acc[i] = 0ULL;
        if (ks < 4) {
            gemm_b4(g_h1buf + wp * BH + (ks * 128) * BATCH + b0,
                    sm->wi2 + (ks * 128) * 16 + oo * 4, 128, acc);
        } else {
            gemm_b4(g_h2buf + rp * BH + ((ks - 4) * 128) * BATCH + b0,
                    sm->wh2 + ((ks - 4) * 128) * 16 + oo * 4, 128, acc);
        }
        if (ks != 0) {
            u64* xc = sm->xch + (ks - 1) * 512 + r * 8;
#pragma unroll
            for (int i = 0; i < 8; i++) xc[i] = acc[i];
        }
        __syncthreads();
        if (ks == 0) {
#pragma unroll
            for (int s = 0; s < 7; s++) {
                const u64* xc = sm->xch + s * 512 + r * 8;
#pragma unroll
                for (int i = 0; i < 8; i++) add2(acc[i], xc[i]);
            }
            float hw[4];
#pragma unroll
            for (int bb = 0; bb < 4; bb++) {
                float2 iff = unpack2(acc[bb * 2]);
                float2 go  = unpack2(acc[bb * 2 + 1]);
                float c = sm->c2s[(b0 + bb) * 4 + oo];
                float cn = sigm(iff.y) * c + sigm(iff.x) * tanhf(go.x);
                sm->c2s[(b0 + bb) * 4 + oo] = cn;
                hw[bb] = sigm(go.y) * tanhf(cn);
            }
            *(float4*)(g_h2buf + wp * BH + col * BATCH + b0) =
                make_float4(hw[0], hw[1], hw[2], hw[3]);
            int m0 = t * BATCH + b0;
#pragma unroll
            for (int bb = 0; bb < 4; bb++)
                g_AfragH2[afrag_idx(m0 + bb, f_kc, f_ka, f_lk, f_khi)] =
                    cvt_tf32(hw[bb]);
        }
        __syncthreads();   // protect xch before next step's phase A store
    }

    // final c slices (b-major, small)
    if (tid < 256) {
        int b = tid >> 2, oo2 = tid & 3;
        g_c1f[b * HID + o0 + oo2] = sm->c1s[tid];
        g_c2f[b * HID + o0 + oo2] = sm->c2s[tid];
    }
}

// ------------------------- decoder: tf32 mma, fragment-order + cp.async ------
#define DEC_SM_FLOATS (2 * 4096 + 2 * 8192)

__global__ __launch_bounds__(256, 1) void decoder_frag(
    const float* __restrict__ Afrag,
    const float* __restrict__ Bfrag,
    const float* __restrict__ bias,
    float* __restrict__ out)
{
    extern __shared__ float smf[];
    float* As = smf;            // [2][4096]
    float* Bs = smf + 8192;     // [2][8192]

    const int tid  = threadIdx.x;
    const int mb   = blockIdx.y;
    const int nb   = blockIdx.x;
    const int warp = tid >> 5, lane = tid & 31;
    const int wm = warp >> 2, wn = warp & 3;

    const float* Ag = Afrag + (size_t)mb * 16 * 4096;
    const float* Bg = Bfrag + (size_t)nb * 16 * 8192;

    float acc[4][8][4];
#pragma unroll
    for (int i = 0; i < 4; i++)
#pragma unroll
        for (int j = 0; j < 8; j++)
#pragma unroll
            for (int q = 0; q < 4; q++) acc[i][j][q] = 0.f;

#define DSTAGE(kc, buf)                                                        \
    {                                                                          \
        _Pragma("unroll")                                                      \
        for (int i = 0; i < 4; i++)                                            \
            cp_async16(As + (buf) * 4096 + (i * 256 + tid) * 4,                \
                       Ag + (kc) * 4096 + (i * 256 + tid) * 4);                \
        _Pragma("unroll")                                                      \
        for (int i = 0; i < 8; i++)                                            \
            cp_async16(Bs + (buf) * 8192 + (i * 256 + tid) * 4,                \
                       Bg + (kc) * 8192 + (i * 256 + tid) * 4);                \
    }

    DSTAGE(0, 0);
    cp_commit();

    for (int c = 0; c < 16; c++) {
        const int cur = c & 1, nxt = cur ^ 1;
        if (c < 15) { DSTAGE(c + 1, nxt); cp_commit(); cp_wait<1>(); }
        else        { cp_wait<0>(); }
        __syncthreads();
        const float* Ab = As + cur * 4096;
        const float* Bb = Bs + cur * 8192;
#pragma unroll
        for (int ka = 0; ka < 4; ka++) {
            uint4 af[4];
            uint2 bf[8];
#pragma unroll
            for (int i = 0; i < 4; i++)
                af[i] = *(const uint4*)(Ab + (((wm * 4 + i) * 4 + ka) * 32 + lane) * 4);
#pragma unroll
            for (int j = 0; j < 8; j++)
                bf[j] = *(const uint2*)(Bb + (((wn * 8 + j) * 4 + ka) * 32 + lane) * 2);
#pragma unroll
            for (int i = 0; i < 4; i++)
#pragma unroll
                for (int j = 0; j < 8; j++)
                    mma_tf32(acc[i][j], af[i], bf[j]);
        }
        __syncthreads();
    }
#undef DSTAGE

    const int g = lane >> 2, t4 = lane & 3;
#pragma unroll
    for (int i = 0; i < 4; i++) {
        int mrow = mb * 128 + wm * 64 + i * 16 + g;
#pragma unroll
        for (int j = 0; j < 8; j++) {
            int cb = nb * 256 + wn * 64 + j * 8 + t4 * 2;
            if (cb < VOCAB) {
                float bb0 = bias[cb], bb1 = bias[cb + 1];
                float2 v0 = make_float2(acc[i][j][0] + bb0, acc[i][j][1] + bb1);
                float2 v1 = make_float2(acc[i][j][2] + bb0, acc[i][j][3] + bb1);
                *(float2*)&out[(size_t)mrow * VOCAB + cb]       = v0;
                *(float2*)&out[(size_t)(mrow + 8) * VOCAB + cb] = v1;
            }
        }
    }
}

// ------------------------- finals (transpose back to b-major) ----------------
__global__ void write_finals(float* __restrict__ out) {
    int i = blockIdx.x * blockDim.x + threadIdx.x;
    if (i < BH) {
        int b = i / HID, k = i % HID;
        float* o = out + (size_t)T_STEPS * BATCH * VOCAB;
        o[i]          = g_h1buf[k * BATCH + b];    // T even -> parity 0 slot
        o[BH + i]     = g_h2buf[k * BATCH + b];
        o[2 * BH + i] = g_c1f[i];
        o[3 * BH + i] = g_c2f[i];
    }
}

// ------------------------- launch -------------------------------------------
extern "C" void kernel_launch(void* const* d_in, const int* in_sizes, int n_in,
                              void* d_out, int out_size) {
    const int*   raw   = (const int*)  d_in[0];
    const float* h1    = (const float*)d_in[1];
    const float* h2    = (const float*)d_in[2];
    const float* c1    = (const float*)d_in[3];
    const float* c2    = (const float*)d_in[4];
    const float* emb   = (const float*)d_in[5];
    const float* wi1   = (const float*)d_in[6];
    const float* wh1   = (const float*)d_in[7];
    const float* wi2   = (const float*)d_in[8];
    const float* wh2   = (const float*)d_in[9];
    const float* dec_w = (const float*)d_in[10];
    const float* dec_b = (const float*)d_in[11];
    float* out = (float*)d_out;

    float *p_afrag, *p_bfrag;
    cudaGetSymbolAddress((void**)&p_afrag, g_AfragH2);
    cudaGetSymbolAddress((void**)&p_bfrag, g_BfragDec);

    static int attr_set = 0;
    if (!attr_set) {
        cudaFuncSetAttribute(lstm_recur, cudaFuncAttributeMaxDynamicSharedMemorySize,
                             (int)sizeof(SmemT));
        cudaFuncSetAttribute(decoder_frag, cudaFuncAttributeMaxDynamicSharedMemorySize,
                             DEC_SM_FLOATS * 4);
        attr_set = 1;
    }

    init_state<<<128, 256>>>(h1, h2);
    conv_b_dec<<<dim3(40, 64), 256>>>(dec_w);
    precompute_xw1<<<dim3(16, 50), 256>>>(raw, emb, wi1);
    lstm_recur<<<NBLK, 512, sizeof(SmemT)>>>(wh1, wi2, wh2, c1, c2);
    decoder_frag<<<dim3(40, 50), 256, DEC_SM_FLOATS * 4>>>(p_afrag, p_bfrag, dec_b, out);
    write_finals<<<128, 256>>>(out);
}

// round 11
// speedup vs baseline: 3.1445x; 1.0348x over previous
#include <cuda_runtime.h>
#include <cuda_bf16.h>
#include <math.h>

#define T_STEPS 100
#define BATCH   64
#define HID     512
#define NGATE   2048   // 4*512
#define VOCAB   10000
#define NVPAD   10240  // vocab padded to 256
#define NBLK    128
#define BH      (BATCH * HID)

typedef unsigned long long u64;

// ------------------------- scratch (static device memory) -------------------
__device__ float g_XW1[T_STEPS * 4 * HID * BATCH];    // [t][g][o][b] k-major
__device__ float g_AfragH2[T_STEPS * BATCH * HID];    // h2 in A-fragment order
__device__ float g_BfragDec[NVPAD * HID];             // dec_w in B-fragment order
__device__ float g_h1buf[2 * BH];                     // K-MAJOR: [k][64 b]
__device__ float g_h2buf[2 * BH];                     // K-MAJOR: [k][64 b]
__device__ float g_c1f[BH];
__device__ float g_c2f[BH];
__device__ unsigned g_bar_cnt;
__device__ volatile unsigned g_bar_flag;

// ------------------------- f32x2 helpers -------------------------------------
__device__ __forceinline__ u64 pack2(float x, float y) {
    u64 r;
    asm("mov.b64 %0, {%1, %2};" : "=l"(r)
        : "r"(__float_as_uint(x)), "r"(__float_as_uint(y)));
    return r;
}
__device__ __forceinline__ u64 dup2(float x) {
    u64 r;
    asm("mov.b64 %0, {%1, %1};" : "=l"(r) : "r"(__float_as_uint(x)));
    return r;
}
__device__ __forceinline__ void fma2(u64 &d, u64 a, u64 b) {
    asm("fma.rn.f32x2 %0, %1, %2, %0;" : "+l"(d) : "l"(a), "l"(b));
}
__device__ __forceinline__ void add2(u64 &d, u64 a) {
    asm("add.rn.f32x2 %0, %0, %1;" : "+l"(d) : "l"(a));
}
__device__ __forceinline__ float2 unpack2(u64 v) {
    float2 r;
    r.x = __uint_as_float((unsigned)(v & 0xFFFFFFFFu));
    r.y = __uint_as_float((unsigned)(v >> 32));
    return r;
}
__device__ __forceinline__ float sigm(float x) { return 1.f / (1.f + expf(-x)); }

// ------------------------- tf32 mma helpers ----------------------------------
__device__ __forceinline__ float cvt_tf32(float x) {
    unsigned r;
    asm("cvt.rn.tf32.f32 %0, %1;" : "=r"(r) : "f"(x));
    return __uint_as_float(r);
}
__device__ __forceinline__ void mma_tf32(float* d, const uint4& a, const uint2& b) {
    asm("mma.sync.aligned.m16n8k8.row.col.f32.tf32.tf32.f32 "
        "{%0,%1,%2,%3}, {%4,%5,%6,%7}, {%8,%9}, {%0,%1,%2,%3};"
        : "+f"(d[0]), "+f"(d[1]), "+f"(d[2]), "+f"(d[3])
        : "r"(a.x), "r"(a.y), "r"(a.z), "r"(a.w), "r"(b.x), "r"(b.y));
}

// ------------------------- cp.async helpers ----------------------------------
__device__ __forceinline__ void cp_async16(void* dst, const void* src) {
    unsigned d = (unsigned)__cvta_generic_to_shared(dst);
    asm volatile("cp.async.cg.shared.global [%0], [%1], 16;" :: "r"(d), "l"(src));
}
__device__ __forceinline__ void cp_commit() {
    asm volatile("cp.async.commit_group;");
}
template<int N> __device__ __forceinline__ void cp_wait() {
    asm volatile("cp.async.wait_group %0;" :: "n"(N));
}

// ------------------------- init (transpose states to k-major) ----------------
__global__ void init_state(const float* __restrict__ h1, const float* __restrict__ h2) {
    int i = blockIdx.x * blockDim.x + threadIdx.x;
    if (i < BH) {
        int k = i >> 6, b = i & 63;
        g_h1buf[i] = h1[b * HID + k];   // parity-0 slot, [k][b]
        g_h2buf[i] = h2[b * HID + k];
    }
    if (i == 0) { g_bar_cnt = 0; g_bar_flag = 0; }
}

// ------------------------- conv: dec_w -> B-fragment order -------------------
__global__ __launch_bounds__(256) void conv_b_dec(const float* __restrict__ Bw) {
    const int n  = blockIdx.x * 256 + threadIdx.x;   // 0..10239
    const int kg = blockIdx.y;                       // 0..63
    const int k0 = kg * 8;

    float v[8];
    if (n < VOCAB) {
        float4 a = *(const float4*)(Bw + (size_t)n * HID + k0);
        float4 b = *(const float4*)(Bw + (size_t)n * HID + k0 + 4);
        v[0]=a.x; v[1]=a.y; v[2]=a.z; v[3]=a.w;
        v[4]=b.x; v[5]=b.y; v[6]=b.z; v[7]=b.w;
    } else {
#pragma unroll
        for (int j = 0; j < 8; j++) v[j] = 0.f;
    }
    const int nb = n >> 8, nn = n & 255, natom = nn >> 3, g = nn & 7;
    const int kc = k0 >> 5, ka = (k0 & 31) >> 3;
    float* dst = g_BfragDec +
        ((((size_t)(nb * 16 + kc) * 32 + natom) * 4 + ka) * 32 + g * 4) * 2;
    float4 o0 = make_float4(cvt_tf32(v[0]), cvt_tf32(v[4]), cvt_tf32(v[1]), cvt_tf32(v[5]));
    float4 o1 = make_float4(cvt_tf32(v[2]), cvt_tf32(v[6]), cvt_tf32(v[3]), cvt_tf32(v[7]));
    *(float4*)dst       = o0;
    *(float4*)(dst + 4) = o1;
}

// ------------------------- precompute XW1 = emb[tok] @ wi1 -------------------
// Output layout: g_XW1[t][g][o][b] (k-major for the recurrence gather).
__global__ __launch_bounds__(256) void precompute_xw1(
    const int* __restrict__ tok, const float* __restrict__ emb,
    const float* __restrict__ wi1)
{
    __shared__ float As[8][128];
    __shared__ float Bs[8][128];
    __shared__ int   toks[128];

    const int tid = threadIdx.x;
    const int m0 = blockIdx.y * 128;
    const int n0 = blockIdx.x * 128;
    const int g  = n0 >> 9;
    const int og0 = n0 & 511;
    const float* wbase = wi1 + (size_t)g * HID * HID + og0;

    if (tid < 128) toks[tid] = tok[m0 + tid];
    __syncthreads();

    const int lr = tid >> 1;
    const int lk = (tid & 1) * 4;
    const int bk = tid >> 5;
    const int bn = (tid & 31) * 4;
    const int tx = tid & 15, ty = tid >> 4;

    u64 acc[8][4];
#pragma unroll
    for (int i = 0; i < 8; i++)
#pragma unroll
        for (int j = 0; j < 4; j++) acc[i][j] = 0ULL;

    for (int k0 = 0; k0 < HID; k0 += 8) {
        float4 av = *(const float4*)(emb + (size_t)toks[lr] * HID + k0 + lk);
        As[lk+0][lr] = av.x; As[lk+1][lr] = av.y; As[lk+2][lr] = av.z; As[lk+3][lr] = av.w;
        float4 bv = *(const float4*)(wbase + (size_t)(k0 + bk) * HID + bn);
        *(float4*)&Bs[bk][bn] = bv;
        __syncthreads();
#pragma unroll
        for (int k = 0; k < 8; k++) {
            float4 a0 = *(float4*)&As[k][ty * 4];
            float4 a1 = *(float4*)&As[k][64 + ty * 4];
            float4 b0 = *(float4*)&Bs[k][tx * 4];
            float4 b1 = *(float4*)&Bs[k][64 + tx * 4];
            u64 bp0 = ((const u64*)&b0)[0], bp1 = ((const u64*)&b0)[1];
            u64 bp2 = ((const u64*)&b1)[0], bp3 = ((const u64*)&b1)[1];
            float ar[8] = {a0.x, a0.y, a0.z, a0.w, a1.x, a1.y, a1.z, a1.w};
#pragma unroll
            for (int i = 0; i < 8; i++) {
                u64 ad = dup2(ar[i]);
                fma2(acc[i][0], ad, bp0);
                fma2(acc[i][1], ad, bp1);
                fma2(acc[i][2], ad, bp2);
                fma2(acc[i][3], ad, bp3);
            }
        }
        __syncthreads();
    }
    // scatter epilogue: element (m, n=g*512+o) -> g_XW1[((t*4+g)*512+o)*64+b]
#pragma unroll
    for (int i = 0; i < 8; i++) {
        int m = m0 + (i < 4 ? ty * 4 + i : 64 + ty * 4 + (i - 4));
        int t = m >> 6, b = m & 63;
        float* tb = g_XW1 + (((size_t)t * 4 + g) * HID) * BATCH + b;
#pragma unroll
        for (int j = 0; j < 4; j++) {
            float2 v = unpack2(acc[i][j]);
            int cb = (j < 2) ? (tx * 4 + j * 2) : (64 + tx * 4 + (j - 2) * 2);
            int o = og0 + cb;
            tb[(size_t)o * BATCH]       = v.x;
            tb[(size_t)(o + 1) * BATCH] = v.y;
        }
    }
}

// ------------------------- persistent recurrence kernel ----------------------
// 512 threads: 8-way K-split (ks = tid>>6), r = tid&63 owns (bq: 4 batches, oo).
// R9 schedule (phase A: layer1 K 8x64; barrier; phase B: wi2/wh2 4x128 each)
// with: (1) xch double-buffered by step parity (no end-of-step sync),
//       (2) reduce+pointwise split across ks0 (bb 0-1) and ks1 (bb 2-3).
struct SmemT {
    float w1 [HID * 16];       // [k][oo][g]
    float wi2[HID * 16];
    float wh2[HID * 16];
    u64   xch[2][8 * 64 * 8];  // [parity][ks][r][8 accs]
    float c1s[256];            // [b][oo]
    float c2s[256];
};

__device__ __forceinline__ void grid_barrier(int t) {
    __syncthreads();
    if (threadIdx.x == 0) {
        __threadfence();   // release (emits CCTL.IVALL too)
        unsigned prev = atomicAdd(&g_bar_cnt, 1u);
        if (prev == (unsigned)NBLK * (unsigned)(t + 1) - 1u) {
            g_bar_flag = (unsigned)(t + 1);
        } else {
            while (g_bar_flag < (unsigned)(t + 1)) { }
        }
        __threadfence();   // acquire + invalidate this SM's L1D
    }
    __syncthreads();
}

// acc[b*2+0] = {i,f}, acc[b*2+1] = {g,o} for 4 batches b.
__device__ __forceinline__ void gemm_b4(
    const float* __restrict__ hk,     // k-major h + b0 offset
    const float* __restrict__ w,      // smem weights + oo*4
    int klen, u64 (&acc)[8])
{
#pragma unroll 2
    for (int kk = 0; kk < klen; kk += 4) {
        float4 hv[4];
#pragma unroll
        for (int j = 0; j < 4; j++)
            hv[j] = *(const float4*)(hk + (size_t)(kk + j) * BATCH);
#pragma unroll
        for (int j = 0; j < 4; j++) {
            float4 wv = *(const float4*)(w + (kk + j) * 16);
            u64 w0 = ((const u64*)&wv)[0];
            u64 w1 = ((const u64*)&wv)[1];
            u64 d0 = dup2(hv[j].x), d1 = dup2(hv[j].y);
            u64 d2 = dup2(hv[j].z), d3 = dup2(hv[j].w);
            fma2(acc[0], d0, w0); fma2(acc[1], d0, w1);
            fma2(acc[2], d1, w0); fma2(acc[3], d1, w1);
            fma2(acc[4], d2, w0); fma2(acc[5], d2, w1);
            fma2(acc[6], d3, w0); fma2(acc[7], d3, w1);
        }
    }
}

// h2 value (m = t*64+b, k = col) -> A-fragment global index
__device__ __forceinline__ size_t afrag_idx(int m, int kc, int ka, int lk, int khi) {
    int mb = m >> 7, mm = m & 127, matom = mm >> 4, r16 = mm & 15;
    int lane = (r16 & 7) * 4 + lk;
    int reg  = (r16 >> 3) + 2 * khi;
    return ((((size_t)(mb * 16 + kc) * 8 + matom) * 4 + ka) * 32 + lane) * 4 + reg;
}

__global__ __launch_bounds__(512, 1) void lstm_recur(
    const float* __restrict__ wh1, const float* __restrict__ wi2g,
    const float* __restrict__ wh2g,
    const float* __restrict__ c1in, const float* __restrict__ c2in)
{
    extern __shared__ char smraw[];
    SmemT* sm = (SmemT*)smraw;
    const int tid = threadIdx.x;
    const int bi  = blockIdx.x;
    const int o0  = bi * 4;

    // weights: [k][oo][g] <- W[g][k][o0+oo], once for all 100 steps
    for (int idx = tid; idx < HID * 16; idx += 512) {
        int k = idx >> 4, c = idx & 15;
        int oo = c >> 2, g = c & 3;
        size_t src = ((size_t)g * HID + k) * HID + o0 + oo;
        sm->w1 [idx] = wh1 [src];
        sm->wi2[idx] = wi2g[src];
        sm->wh2[idx] = wh2g[src];
    }
    if (tid < 256) {   // c state slice [b][oo]
        int b = tid >> 2, oo = tid & 3;
        sm->c1s[tid] = c1in[b * HID + o0 + oo];
        sm->c2s[tid] = c2in[b * HID + o0 + oo];
    }
    __syncthreads();

    const int ks = tid >> 6;        // k-split eighth: 0..7
    const int r  = tid & 63;
    const int oo = r & 3;
    const int bq = r >> 2;
    const int b0 = bq * 4;
    const int col = o0 + oo;

    // A-fragment constants for (k = col)
    const int f_kc = col >> 5, f_kk = col & 31;
    const int f_ka = f_kk >> 3, f_lk = f_kk & 3, f_khi = (f_kk >> 2) & 1;

    for (int t = 0; t < T_STEPS; t++) {
        const int rp = t & 1, wp = rp ^ 1;

        // ---------------- Phase A: layer1 (h1 @ wh1 + XW1), K split 8x64 ---
        float2 xwg[4];
        if (ks < 2) {
#pragma unroll
            for (int g = 0; g < 4; g++)
                xwg[g] = *(const float2*)(g_XW1 +
                    (((size_t)t * 4 + g) * HID + col) * BATCH + b0 + ks * 2);
        }
        u64 acc[8];
#pragma unroll
        for (int i = 0; i < 8; i++) acc[i] = 0ULL;
        gemm_b4(g_h1buf + rp * BH + (ks * 64) * BATCH + b0,
                sm->w1 + (ks * 64) * 16 + oo * 4, 64, acc);
        {
            u64* xc = sm->xch[rp] + ks * 512 + r * 8;
#pragma unroll
            for (int i = 0; i < 8; i++) xc[i] = acc[i];
        }
        __syncthreads();
        if (ks < 2) {
            const int ibase = ks * 4;    // acc indices for bb = ks*2, ks*2+1
            u64 a4[4] = {0ULL, 0ULL, 0ULL, 0ULL};
#pragma unroll
            for (int s = 0; s < 8; s++) {
                const u64* xc = sm->xch[rp] + s * 512 + r * 8 + ibase;
#pragma unroll
                for (int j = 0; j < 4; j++) add2(a4[j], xc[j]);
            }
            float hw[2];
#pragma unroll
            for (int jbb = 0; jbb < 2; jbb++) {
                int gbb = ks * 2 + jbb;
                float2 iff = unpack2(a4[jbb * 2]);
                float2 go  = unpack2(a4[jbb * 2 + 1]);
                float iv = iff.x + ((const float*)&xwg[0])[jbb];
                float fv = iff.y + ((const float*)&xwg[1])[jbb];
                float gv = go.x  + ((const float*)&xwg[2])[jbb];
                float ov = go.y  + ((const float*)&xwg[3])[jbb];
                float c = sm->c1s[(b0 + gbb) * 4 + oo];
                float cn = sigm(fv) * c + sigm(iv) * tanhf(gv);
                sm->c1s[(b0 + gbb) * 4 + oo] = cn;
                hw[jbb] = sigm(ov) * tanhf(cn);
            }
            *(float2*)(g_h1buf + wp * BH + col * BATCH + b0 + ks * 2) =
                make_float2(hw[0], hw[1]);
        }

        grid_barrier(t);

        // ------- Phase B: layer2; ks0-3 -> wi2 quarters, ks4-7 -> wh2 ------
#pragma unroll
        for (int i = 0; i < 8; i++) acc[i] = 0ULL;
        if (ks < 4) {
            gemm_b4(g_h1buf + wp * BH + (ks * 128) * BATCH + b0,
                    sm->wi2 + (ks * 128) * 16 + oo * 4, 128, acc);
        } else {
            gemm_b4(g_h2buf + rp * BH + ((ks - 4) * 128) * BATCH + b0,
                    sm->wh2 + ((ks - 4) * 128) * 16 + oo * 4, 128, acc);
        }
        {
            u64* xc = sm->xch[rp] + ks * 512 + r * 8;
#pragma unroll
            for (int i = 0; i < 8; i++) xc[i] = acc[i];
        }
        __syncthreads();
        if (ks < 2) {
            const int ibase = ks * 4;
            u64 a4[4] = {0ULL, 0ULL, 0ULL, 0ULL};
#pragma unroll
            for (int s = 0; s < 8; s++) {
                const u64* xc = sm->xch[rp] + s * 512 + r * 8 + ibase;
#pragma unroll
                for (int j = 0; j < 4; j++) add2(a4[j], xc[j]);
            }
            float hw[2];
#pragma unroll
            for (int jbb = 0; jbb < 2; jbb++) {
                int gbb = ks * 2 + jbb;
                float2 iff = unpack2(a4[jbb * 2]);
                float2 go  = unpack2(a4[jbb * 2 + 1]);
                float c = sm->c2s[(b0 + gbb) * 4 + oo];
                float cn = sigm(iff.y) * c + sigm(iff.x) * tanhf(go.x);
                sm->c2s[(b0 + gbb) * 4 + oo] = cn;
                hw[jbb] = sigm(go.y) * tanhf(cn);
            }
            *(float2*)(g_h2buf + wp * BH + col * BATCH + b0 + ks * 2) =
                make_float2(hw[0], hw[1]);
            int m0 = t * BATCH + b0 + ks * 2;
#pragma unroll
            for (int jbb = 0; jbb < 2; jbb++)
                g_AfragH2[afrag_idx(m0 + jbb, f_kc, f_ka, f_lk, f_khi)] =
                    cvt_tf32(hw[jbb]);
        }
        // no end-of-step sync: xch is parity double-buffered; next step's
        // phase A writes xch[wp], and the next __syncthreads/barrier order
        // everything else.
    }

    __syncthreads();
    // final c slices (b-major, small)
    if (tid < 256) {
        int b = tid >> 2, oo2 = tid & 3;
        g_c1f[b * HID + o0 + oo2] = sm->c1s[tid];
        g_c2f[b * HID + o0 + oo2] = sm->c2s[tid];
    }
}

// ------------------------- decoder: tf32 mma, fragment-order + cp.async ------
#define DEC_SM_FLOATS (2 * 4096 + 2 * 8192)

__global__ __launch_bounds__(256, 1) void decoder_frag(
    const float* __restrict__ Afrag,
    const float* __restrict__ Bfrag,
    const float* __restrict__ bias,
    float* __restrict__ out)
{
    extern __shared__ float smf[];
    float* As = smf;            // [2][4096]
    float* Bs = smf + 8192;     // [2][8192]

    const int tid  = threadIdx.x;
    const int mb   = blockIdx.y;
    const int nb   = blockIdx.x;
    const int warp = tid >> 5, lane = tid & 31;
    const int wm = warp >> 2, wn = warp & 3;

    const float* Ag = Afrag + (size_t)mb * 16 * 4096;
    const float* Bg = Bfrag + (size_t)nb * 16 * 8192;

    float acc[4][8][4];
#pragma unroll
    for (int i = 0; i < 4; i++)
#pragma unroll
        for (int j = 0; j < 8; j++)
#pragma unroll
            for (int q = 0; q < 4; q++) acc[i][j][q] = 0.f;

#define DSTAGE(kc, buf)                                                        \
    {                                                                          \
        _Pragma("unroll")                                                      \
        for (int i = 0; i < 4; i++)                                            \
            cp_async16(As + (buf) * 4096 + (i * 256 + tid) * 4,                \
                       Ag + (kc) * 4096 + (i * 256 + tid) * 4);                \
        _Pragma("unroll")                                                      \
        for (int i = 0; i < 8; i++)                                            \
            cp_async16(Bs + (buf) * 8192 + (i * 256 + tid) * 4,                \
                       Bg + (kc) * 8192 + (i * 256 + tid) * 4);                \
    }

    DSTAGE(0, 0);
    cp_commit();

    for (int c = 0; c < 16; c++) {
        const int cur = c & 1, nxt = cur ^ 1;
        if (c < 15) { DSTAGE(c + 1, nxt); cp_commit(); cp_wait<1>(); }
        else        { cp_wait<0>(); }
        __syncthreads();
        const float* Ab = As + cur * 4096;
        const float* Bb = Bs + cur * 8192;
#pragma unroll
        for (int ka = 0; ka < 4; ka++) {
            uint4 af[4];
            uint2 bf[8];
#pragma unroll
            for (int i = 0; i < 4; i++)
                af[i] = *(const uint4*)(Ab + (((wm * 4 + i) * 4 + ka) * 32 + lane) * 4);
#pragma unroll
            for (int j = 0; j < 8; j++)
                bf[j] = *(const uint2*)(Bb + (((wn * 8 + j) * 4 + ka) * 32 + lane) * 2);
#pragma unroll
            for (int i = 0; i < 4; i++)
#pragma unroll
                for (int j = 0; j < 8; j++)
                    mma_tf32(acc[i][j], af[i], bf[j]);
        }
        __syncthreads();
    }
#undef DSTAGE

    const int g = lane >> 2, t4 = lane & 3;
#pragma unroll
    for (int i = 0; i < 4; i++) {
        int mrow = mb * 128 + wm * 64 + i * 16 + g;
#pragma unroll
        for (int j = 0; j < 8; j++) {
            int cb = nb * 256 + wn * 64 + j * 8 + t4 * 2;
            if (cb < VOCAB) {
                float bb0 = bias[cb], bb1 = bias[cb + 1];
                float2 v0 = make_float2(acc[i][j][0] + bb0, acc[i][j][1] + bb1);
                float2 v1 = make_float2(acc[i][j][2] + bb0, acc[i][j][3] + bb1);
                *(float2*)&out[(size_t)mrow * VOCAB + cb]       = v0;
                *(float2*)&out[(size_t)(mrow + 8) * VOCAB + cb] = v1;
            }
        }
    }
}

// ------------------------- finals (transpose back to b-major) ----------------
__global__ void write_finals(float* __restrict__ out) {
    int i = blockIdx.x * blockDim.x + threadIdx.x;
    if (i < BH) {
        int b = i / HID, k = i % HID;
        float* o = out + (size_t)T_STEPS * BATCH * VOCAB;
        o[i]          = g_h1buf[k * BATCH + b];    // T even -> parity 0 slot
        o[BH + i]     = g_h2buf[k * BATCH + b];
        o[2 * BH + i] = g_c1f[i];
        o[3 * BH + i] = g_c2f[i];
    }
}

// ------------------------- launch -------------------------------------------
extern "C" void kernel_launch(void* const* d_in, const int* in_sizes, int n_in,
                              void* d_out, int out_size) {
    const int*   raw   = (const int*)  d_in[0];
    const float* h1    = (const float*)d_in[1];
    const float* h2    = (const float*)d_in[2];
    const float* c1    = (const float*)d_in[3];
    const float* c2    = (const float*)d_in[4];
    const float* emb   = (const float*)d_in[5];
    const float* wi1   = (const float*)d_in[6];
    const float* wh1   = (const float*)d_in[7];
    const float* wi2   = (const float*)d_in[8];
    const float* wh2   = (const float*)d_in[9];
    const float* dec_w = (const float*)d_in[10];
    const float* dec_b = (const float*)d_in[11];
    float* out = (float*)d_out;

    float *p_afrag, *p_bfrag;
    cudaGetSymbolAddress((void**)&p_afrag, g_AfragH2);
    cudaGetSymbolAddress((void**)&p_bfrag, g_BfragDec);

    static int attr_set = 0;
    if (!attr_set) {
        cudaFuncSetAttribute(lstm_recur, cudaFuncAttributeMaxDynamicSharedMemorySize,
                             (int)sizeof(SmemT));
        cudaFuncSetAttribute(decoder_frag, cudaFuncAttributeMaxDynamicSharedMemorySize,
                             DEC_SM_FLOATS * 4);
        attr_set = 1;
    }

    init_state<<<128, 256>>>(h1, h2);
    conv_b_dec<<<dim3(40, 64), 256>>>(dec_w);
    precompute_xw1<<<dim3(16, 50), 256>>>(raw, emb, wi1);
    lstm_recur<<<NBLK, 512, sizeof(SmemT)>>>(wh1, wi2, wh2, c1, c2);
    decoder_frag<<<dim3(40, 50), 256, DEC_SM_FLOATS * 4>>>(p_afrag, p_bfrag, dec_b, out);
    write_finals<<<128, 256>>>(out);
}

// round 12
// speedup vs baseline: 3.1836x; 1.0124x over previous
#include <cuda_runtime.h>
#include <cuda_bf16.h>
#include <math.h>

#define T_STEPS 100
#define BATCH   64
#define HID     512
#define NGATE   2048   // 4*512
#define VOCAB   10000
#define NVPAD   10240  // vocab padded to 256
#define NBLK    128
#define BH      (BATCH * HID)

typedef unsigned long long u64;

// ------------------------- scratch (static device memory) -------------------
__device__ float g_XW1[T_STEPS * 4 * HID * BATCH];    // [t][g][o][b] k-major
__device__ float g_AfragH2[T_STEPS * BATCH * HID];    // h2 in A-fragment order
__device__ float g_BfragDec[NVPAD * HID];             // dec_w in B-fragment order
__device__ float g_h1buf[2 * BH];                     // K-MAJOR: [k][64 b]
__device__ float g_h2buf[2 * BH];                     // K-MAJOR: [k][64 b]
__device__ float g_c1f[BH];
__device__ float g_c2f[BH];
__device__ unsigned g_bar_cnt;
__device__ volatile unsigned g_bar_flag;

// ------------------------- f32x2 helpers -------------------------------------
__device__ __forceinline__ u64 pack2(float x, float y) {
    u64 r;
    asm("mov.b64 %0, {%1, %2};" : "=l"(r)
        : "r"(__float_as_uint(x)), "r"(__float_as_uint(y)));
    return r;
}
__device__ __forceinline__ u64 dup2(float x) {
    u64 r;
    asm("mov.b64 %0, {%1, %1};" : "=l"(r) : "r"(__float_as_uint(x)));
    return r;
}
__device__ __forceinline__ void fma2(u64 &d, u64 a, u64 b) {
    asm("fma.rn.f32x2 %0, %1, %2, %0;" : "+l"(d) : "l"(a), "l"(b));
}
__device__ __forceinline__ void add2(u64 &d, u64 a) {
    asm("add.rn.f32x2 %0, %0, %1;" : "+l"(d) : "l"(a));
}
__device__ __forceinline__ float2 unpack2(u64 v) {
    float2 r;
    r.x = __uint_as_float((unsigned)(v & 0xFFFFFFFFu));
    r.y = __uint_as_float((unsigned)(v >> 32));
    return r;
}
__device__ __forceinline__ float sigm(float x) { return 1.f / (1.f + expf(-x)); }

// ------------------------- tf32 mma helpers ----------------------------------
__device__ __forceinline__ float cvt_tf32(float x) {
    unsigned r;
    asm("cvt.rn.tf32.f32 %0, %1;" : "=r"(r) : "f"(x));
    return __uint_as_float(r);
}
__device__ __forceinline__ void mma_tf32(float* d, const uint4& a, const uint2& b) {
    asm("mma.sync.aligned.m16n8k8.row.col.f32.tf32.tf32.f32 "
        "{%0,%1,%2,%3}, {%4,%5,%6,%7}, {%8,%9}, {%0,%1,%2,%3};"
        : "+f"(d[0]), "+f"(d[1]), "+f"(d[2]), "+f"(d[3])
        : "r"(a.x), "r"(a.y), "r"(a.z), "r"(a.w), "r"(b.x), "r"(b.y));
}

// ------------------------- cp.async helpers ----------------------------------
__device__ __forceinline__ void cp_async16(void* dst, const void* src) {
    unsigned d = (unsigned)__cvta_generic_to_shared(dst);
    asm volatile("cp.async.cg.shared.global [%0], [%1], 16;" :: "r"(d), "l"(src));
}
__device__ __forceinline__ void cp_commit() {
    asm volatile("cp.async.commit_group;");
}
template<int N> __device__ __forceinline__ void cp_wait() {
    asm volatile("cp.async.wait_group %0;" :: "n"(N));
}

// ------------------------- init (transpose states to k-major) ----------------
__global__ void init_state(const float* __restrict__ h1, const float* __restrict__ h2) {
    int i = blockIdx.x * blockDim.x + threadIdx.x;
    if (i < BH) {
        int k = i >> 6, b = i & 63;
        g_h1buf[i] = h1[b * HID + k];   // slot 0 = h1(-1): phase 0 reads slot 0
        g_h2buf[BH + i] = h2[b * HID + k];  // slot 1 = h2(-1): phase 1 reads slot (1&1)^1=0? see below
        // NOTE: phase p reads h2 from slot (p&1)^1. Phase 1 (first layer2, t2=0)
        // reads slot 0... so h2(-1) must be in slot 0? Let's check: layer2(0)
        // needs h2(-1); phase 1 reads slot (1&1)^1 = 0. So initial h2 -> slot 0.
        g_h2buf[i] = h2[b * HID + k];
    }
    if (i == 0) { g_bar_cnt = 0; g_bar_flag = 0; }
}

// ------------------------- conv: dec_w -> B-fragment order -------------------
__global__ __launch_bounds__(256) void conv_b_dec(const float* __restrict__ Bw) {
    const int n  = blockIdx.x * 256 + threadIdx.x;   // 0..10239
    const int kg = blockIdx.y;                       // 0..63
    const int k0 = kg * 8;

    float v[8];
    if (n < VOCAB) {
        float4 a = *(const float4*)(Bw + (size_t)n * HID + k0);
        float4 b = *(const float4*)(Bw + (size_t)n * HID + k0 + 4);
        v[0]=a.x; v[1]=a.y; v[2]=a.z; v[3]=a.w;
        v[4]=b.x; v[5]=b.y; v[6]=b.z; v[7]=b.w;
    } else {
#pragma unroll
        for (int j = 0; j < 8; j++) v[j] = 0.f;
    }
    const int nb = n >> 8, nn = n & 255, natom = nn >> 3, g = nn & 7;
    const int kc = k0 >> 5, ka = (k0 & 31) >> 3;
    float* dst = g_BfragDec +
        ((((size_t)(nb * 16 + kc) * 32 + natom) * 4 + ka) * 32 + g * 4) * 2;
    float4 o0 = make_float4(cvt_tf32(v[0]), cvt_tf32(v[4]), cvt_tf32(v[1]), cvt_tf32(v[5]));
    float4 o1 = make_float4(cvt_tf32(v[2]), cvt_tf32(v[6]), cvt_tf32(v[3]), cvt_tf32(v[7]));
    *(float4*)dst       = o0;
    *(float4*)(dst + 4) = o1;
}

// ------------------------- precompute XW1 = emb[tok] @ wi1 -------------------
// Output layout: g_XW1[t][g][o][b] (k-major for the recurrence gather).
__global__ __launch_bounds__(256) void precompute_xw1(
    const int* __restrict__ tok, const float* __restrict__ emb,
    const float* __restrict__ wi1)
{
    __shared__ float As[8][128];
    __shared__ float Bs[8][128];
    __shared__ int   toks[128];

    const int tid = threadIdx.x;
    const int m0 = blockIdx.y * 128;
    const int n0 = blockIdx.x * 128;
    const int g  = n0 >> 9;
    const int og0 = n0 & 511;
    const float* wbase = wi1 + (size_t)g * HID * HID + og0;

    if (tid < 128) toks[tid] = tok[m0 + tid];
    __syncthreads();

    const int lr = tid >> 1;
    const int lk = (tid & 1) * 4;
    const int bk = tid >> 5;
    const int bn = (tid & 31) * 4;
    const int tx = tid & 15, ty = tid >> 4;

    u64 acc[8][4];
#pragma unroll
    for (int i = 0; i < 8; i++)
#pragma unroll
        for (int j = 0; j < 4; j++) acc[i][j] = 0ULL;

    for (int k0 = 0; k0 < HID; k0 += 8) {
        float4 av = *(const float4*)(emb + (size_t)toks[lr] * HID + k0 + lk);
        As[lk+0][lr] = av.x; As[lk+1][lr] = av.y; As[lk+2][lr] = av.z; As[lk+3][lr] = av.w;
        float4 bv = *(const float4*)(wbase + (size_t)(k0 + bk) * HID + bn);
        *(float4*)&Bs[bk][bn] = bv;
        __syncthreads();
#pragma unroll
        for (int k = 0; k < 8; k++) {
            float4 a0 = *(float4*)&As[k][ty * 4];
            float4 a1 = *(float4*)&As[k][64 + ty * 4];
            float4 b0 = *(float4*)&Bs[k][tx * 4];
            float4 b1 = *(float4*)&Bs[k][64 + tx * 4];
            u64 bp0 = ((const u64*)&b0)[0], bp1 = ((const u64*)&b0)[1];
            u64 bp2 = ((const u64*)&b1)[0], bp3 = ((const u64*)&b1)[1];
            float ar[8] = {a0.x, a0.y, a0.z, a0.w, a1.x, a1.y, a1.z, a1.w};
#pragma unroll
            for (int i = 0; i < 8; i++) {
                u64 ad = dup2(ar[i]);
                fma2(acc[i][0], ad, bp0);
                fma2(acc[i][1], ad, bp1);
                fma2(acc[i][2], ad, bp2);
                fma2(acc[i][3], ad, bp3);
            }
        }
        __syncthreads();
    }
    // scatter epilogue: element (m, n=g*512+o) -> g_XW1[((t*4+g)*512+o)*64+b]
#pragma unroll
    for (int i = 0; i < 8; i++) {
        int m = m0 + (i < 4 ? ty * 4 + i : 64 + ty * 4 + (i - 4));
        int t = m >> 6, b = m & 63;
        float* tb = g_XW1 + (((size_t)t * 4 + g) * HID) * BATCH + b;
#pragma unroll
        for (int j = 0; j < 4; j++) {
            float2 v = unpack2(acc[i][j]);
            int cb = (j < 2) ? (tx * 4 + j * 2) : (64 + tx * 4 + (j - 2) * 2);
            int o = og0 + cb;
            tb[(size_t)o * BATCH]       = v.x;
            tb[(size_t)(o + 1) * BATCH] = v.y;
        }
    }
}

// ------------------------- persistent recurrence kernel ----------------------
// WAVEFRONT: phase p (0..100) computes layer1(t=p) AND layer2(t=p-1) with ONE
// grid barrier per phase.  512 threads, ks = tid>>6 (0..7), r = tid&63.
// Per phase: all ks run layer1 (64k -> xchA) and layer2 (128k: ks0-3 wi2 with
// h1(p-1), ks4-7 wh2 with h2(p-2) -> xchB); __syncthreads; ks0/1 reduce L1,
// ks2/3 reduce L2 (slot order identical to R11 -> identical arithmetic);
// grid barrier.  All producer->consumer edges cross >=1 barrier:
//   h1(p-1): written phase p-1 slot p&1, read phase p slot p&1       (1 bar)
//   h2(p-2): written phase p-1 slot (p&1)^1, read phase p slot (p&1)^1 (1 bar)
//   xch: written pre-sync, read post-sync, rewritten after barrier   (safe)
struct SmemT {
    float w1 [HID * 16];    // [k][oo][g]
    float wi2[HID * 16];
    float wh2[HID * 16];
    u64   xchA[8 * 64 * 8]; // layer1 partials [ks][r][8]
    u64   xchB[8 * 64 * 8]; // layer2 partials [ks][r][8]
    float c1s[256];         // [b][oo]
    float c2s[256];
};

__device__ __forceinline__ void grid_barrier(int p) {
    __syncthreads();
    if (threadIdx.x == 0) {
        __threadfence();   // release (emits CCTL.IVALL too)
        unsigned prev = atomicAdd(&g_bar_cnt, 1u);
        if (prev == (unsigned)NBLK * (unsigned)(p + 1) - 1u) {
            g_bar_flag = (unsigned)(p + 1);
        } else {
            while (g_bar_flag < (unsigned)(p + 1)) { }
        }
        __threadfence();   // acquire + invalidate this SM's L1D
    }
    __syncthreads();
}

// acc[b*2+0] = {i,f}, acc[b*2+1] = {g,o} for 4 batches b.
__device__ __forceinline__ void gemm_b4(
    const float* __restrict__ hk,     // k-major h + b0 offset
    const float* __restrict__ w,      // smem weights + oo*4
    int klen, u64 (&acc)[8])
{
#pragma unroll 2
    for (int kk = 0; kk < klen; kk += 4) {
        float4 hv[4];
#pragma unroll
        for (int j = 0; j < 4; j++)
            hv[j] = *(const float4*)(hk + (size_t)(kk + j) * BATCH);
#pragma unroll
        for (int j = 0; j < 4; j++) {
            float4 wv = *(const float4*)(w + (kk + j) * 16);
            u64 w0 = ((const u64*)&wv)[0];
            u64 w1 = ((const u64*)&wv)[1];
            u64 d0 = dup2(hv[j].x), d1 = dup2(hv[j].y);
            u64 d2 = dup2(hv[j].z), d3 = dup2(hv[j].w);
            fma2(acc[0], d0, w0); fma2(acc[1], d0, w1);
            fma2(acc[2], d1, w0); fma2(acc[3], d1, w1);
            fma2(acc[4], d2, w0); fma2(acc[5], d2, w1);
            fma2(acc[6], d3, w0); fma2(acc[7], d3, w1);
        }
    }
}

// h2 value (m = t*64+b, k = col) -> A-fragment global index
__device__ __forceinline__ size_t afrag_idx(int m, int kc, int ka, int lk, int khi) {
    int mb = m >> 7, mm = m & 127, matom = mm >> 4, r16 = mm & 15;
    int lane = (r16 & 7) * 4 + lk;
    int reg  = (r16 >> 3) + 2 * khi;
    return ((((size_t)(mb * 16 + kc) * 8 + matom) * 4 + ka) * 32 + lane) * 4 + reg;
}

__global__ __launch_bounds__(512, 1) void lstm_recur(
    const float* __restrict__ wh1, const float* __restrict__ wi2g,
    const float* __restrict__ wh2g,
    const float* __restrict__ c1in, const float* __restrict__ c2in)
{
    extern __shared__ char smraw[];
    SmemT* sm = (SmemT*)smraw;
    const int tid = threadIdx.x;
    const int bi  = blockIdx.x;
    const int o0  = bi * 4;

    // weights: [k][oo][g] <- W[g][k][o0+oo], once for all phases
    for (int idx = tid; idx < HID * 16; idx += 512) {
        int k = idx >> 4, c = idx & 15;
        int oo = c >> 2, g = c & 3;
        size_t src = ((size_t)g * HID + k) * HID + o0 + oo;
        sm->w1 [idx] = wh1 [src];
        sm->wi2[idx] = wi2g[src];
        sm->wh2[idx] = wh2g[src];
    }
    if (tid < 256) {   // c state slice [b][oo]
        int b = tid >> 2, oo = tid & 3;
        sm->c1s[tid] = c1in[b * HID + o0 + oo];
        sm->c2s[tid] = c2in[b * HID + o0 + oo];
    }
    __syncthreads();

    const int ks = tid >> 6;        // 0..7
    const int r  = tid & 63;
    const int oo = r & 3;
    const int bq = r >> 2;
    const int b0 = bq * 4;
    const int col = o0 + oo;

    // A-fragment constants for (k = col)
    const int f_kc = col >> 5, f_kk = col & 31;
    const int f_ka = f_kk >> 3, f_lk = f_kk & 3, f_khi = (f_kk >> 2) & 1;

    for (int p = 0; p <= T_STEPS; p++) {
        const int s1r = p & 1;          // h1(p-1) slot
        const int s1w = s1r ^ 1;        // h1(p) slot
        const int s2r = s1w;            // h2(p-2) slot
        const int s2w = s1r;            // h2(p-1) slot
        const bool doL1 = (p < T_STEPS);
        const bool doL2 = (p > 0);

        // ---- layer1(t=p): K split 8x64, accumulate to xchA ----
        float2 xwg[4];
        if (doL1 && ks < 2) {
#pragma unroll
            for (int g = 0; g < 4; g++)
                xwg[g] = *(const float2*)(g_XW1 +
                    (((size_t)p * 4 + g) * HID + col) * BATCH + b0 + ks * 2);
        }
        if (doL1) {
            u64 acc[8];
#pragma unroll
            for (int i = 0; i < 8; i++) acc[i] = 0ULL;
            gemm_b4(g_h1buf + s1r * BH + (ks * 64) * BATCH + b0,
                    sm->w1 + (ks * 64) * 16 + oo * 4, 64, acc);
            u64* xc = sm->xchA + ks * 512 + r * 8;
#pragma unroll
            for (int i = 0; i < 8; i++) xc[i] = acc[i];
        }

        // ---- layer2(t=p-1): ks0-3 wi2 quarters (h1(p-1)), ks4-7 wh2 -------
        if (doL2) {
            u64 acc[8];
#pragma unroll
            for (int i = 0; i < 8; i++) acc[i] = 0ULL;
            if (ks < 4) {
                gemm_b4(g_h1buf + s1r * BH + (ks * 128) * BATCH + b0,
                        sm->wi2 + (ks * 128) * 16 + oo * 4, 128, acc);
            } else {
                gemm_b4(g_h2buf + s2r * BH + ((ks - 4) * 128) * BATCH + b0,
                        sm->wh2 + ((ks - 4) * 128) * 16 + oo * 4, 128, acc);
            }
            u64* xc = sm->xchB + ks * 512 + r * 8;
#pragma unroll
            for (int i = 0; i < 8; i++) xc[i] = acc[i];
        }

        __syncthreads();

        // ---- reduce + pointwise: ks0/1 -> layer1, ks2/3 -> layer2 ---------
        if (doL1 && ks < 2) {
            const int ibase = ks * 4;    // bb = ks*2, ks*2+1
            u64 a4[4] = {0ULL, 0ULL, 0ULL, 0ULL};
#pragma unroll
            for (int s = 0; s < 8; s++) {
                const u64* xc = sm->xchA + s * 512 + r * 8 + ibase;
#pragma unroll
                for (int j = 0; j < 4; j++) add2(a4[j], xc[j]);
            }
            float hw[2];
#pragma unroll
            for (int jbb = 0; jbb < 2; jbb++) {
                int gbb = ks * 2 + jbb;
                float2 iff = unpack2(a4[jbb * 2]);
                float2 go  = unpack2(a4[jbb * 2 + 1]);
                float iv = iff.x + ((const float*)&xwg[0])[jbb];
                float fv = iff.y + ((const float*)&xwg[1])[jbb];
                float gv = go.x  + ((const float*)&xwg[2])[jbb];
                float ov = go.y  + ((const float*)&xwg[3])[jbb];
                float c = sm->c1s[(b0 + gbb) * 4 + oo];
                float cn = sigm(fv) * c + sigm(iv) * tanhf(gv);
                sm->c1s[(b0 + gbb) * 4 + oo] = cn;
                hw[jbb] = sigm(ov) * tanhf(cn);
            }
            *(float2*)(g_h1buf + s1w * BH + col * BATCH + b0 + ks * 2) =
                make_float2(hw[0], hw[1]);
        }
        if (doL2 && ks >= 2 && ks < 4) {
            const int kr = ks - 2;       // 0/1
            const int ibase = kr * 4;
            u64 a4[4] = {0ULL, 0ULL, 0ULL, 0ULL};
#pragma unroll
            for (int s = 0; s < 8; s++) {
                const u64* xc = sm->xchB + s * 512 + r * 8 + ibase;
#pragma unroll
                for (int j = 0; j < 4; j++) add2(a4[j], xc[j]);
            }
            float hw[2];
#pragma unroll
            for (int jbb = 0; jbb < 2; jbb++) {
                int gbb = kr * 2 + jbb;
                float2 iff = unpack2(a4[jbb * 2]);
                float2 go  = unpack2(a4[jbb * 2 + 1]);
                float c = sm->c2s[(b0 + gbb) * 4 + oo];
                float cn = sigm(iff.y) * c + sigm(iff.x) * tanhf(go.x);
                sm->c2s[(b0 + gbb) * 4 + oo] = cn;
                hw[jbb] = sigm(go.y) * tanhf(cn);
            }
            *(float2*)(g_h2buf + s2w * BH + col * BATCH + b0 + kr * 2) =
                make_float2(hw[0], hw[1]);
            int m0 = (p - 1) * BATCH + b0 + kr * 2;
#pragma unroll
            for (int jbb = 0; jbb < 2; jbb++)
                g_AfragH2[afrag_idx(m0 + jbb, f_kc, f_ka, f_lk, f_khi)] =
                    cvt_tf32(hw[jbb]);
        }

        grid_barrier(p);
    }

    // final c slices (b-major, small)
    if (tid < 256) {
        int b = tid >> 2, oo2 = tid & 3;
        g_c1f[b * HID + o0 + oo2] = sm->c1s[tid];
        g_c2f[b * HID + o0 + oo2] = sm->c2s[tid];
    }
}

// ------------------------- decoder: tf32 mma, fragment-order + cp.async ------
#define DEC_SM_FLOATS (2 * 4096 + 2 * 8192)

__global__ __launch_bounds__(256, 1) void decoder_frag(
    const float* __restrict__ Afrag,
    const float* __restrict__ Bfrag,
    const float* __restrict__ bias,
    float* __restrict__ out)
{
    extern __shared__ float smf[];
    float* As = smf;            // [2][4096]
    float* Bs = smf + 8192;     // [2][8192]

    const int tid  = threadIdx.x;
    const int mb   = blockIdx.y;
    const int nb   = blockIdx.x;
    const int warp = tid >> 5, lane = tid & 31;
    const int wm = warp >> 2, wn = warp & 3;

    const float* Ag = Afrag + (size_t)mb * 16 * 4096;
    const float* Bg = Bfrag + (size_t)nb * 16 * 8192;

    float acc[4][8][4];
#pragma unroll
    for (int i = 0; i < 4; i++)
#pragma unroll
        for (int j = 0; j < 8; j++)
#pragma unroll
            for (int q = 0; q < 4; q++) acc[i][j][q] = 0.f;

#define DSTAGE(kc, buf)                                                        \
    {                                                                          \
        _Pragma("unroll")                                                      \
        for (int i = 0; i < 4; i++)                                            \
            cp_async16(As + (buf) * 4096 + (i * 256 + tid) * 4,                \
                       Ag + (kc) * 4096 + (i * 256 + tid) * 4);                \
        _Pragma("unroll")                                                      \
        for (int i = 0; i < 8; i++)                                            \
            cp_async16(Bs + (buf) * 8192 + (i * 256 + tid) * 4,                \
                       Bg + (kc) * 8192 + (i * 256 + tid) * 4);                \
    }

    DSTAGE(0, 0);
    cp_commit();

    for (int c = 0; c < 16; c++) {
        const int cur = c & 1, nxt = cur ^ 1;
        if (c < 15) { DSTAGE(c + 1, nxt); cp_commit(); cp_wait<1>(); }
        else        { cp_wait<0>(); }
        __syncthreads();
        const float* Ab = As + cur * 4096;
        const float* Bb = Bs + cur * 8192;
#pragma unroll
        for (int ka = 0; ka < 4; ka++) {
            uint4 af[4];
            uint2 bf[8];
#pragma unroll
            for (int i = 0; i < 4; i++)
                af[i] = *(const uint4*)(Ab + (((wm * 4 + i) * 4 + ka) * 32 + lane) * 4);
#pragma unroll
            for (int j = 0; j < 8; j++)
                bf[j] = *(const uint2*)(Bb + (((wn * 8 + j) * 4 + ka) * 32 + lane) * 2);
#pragma unroll
            for (int i = 0; i < 4; i++)
#pragma unroll
                for (int j = 0; j < 8; j++)
                    mma_tf32(acc[i][j], af[i], bf[j]);
        }
        __syncthreads();
    }
#undef DSTAGE

    const int g = lane >> 2, t4 = lane & 3;
#pragma unroll
    for (int i = 0; i < 4; i++) {
        int mrow = mb * 128 + wm * 64 + i * 16 + g;
#pragma unroll
        for (int j = 0; j < 8; j++) {
            int cb = nb * 256 + wn * 64 + j * 8 + t4 * 2;
            if (cb < VOCAB) {
                float bb0 = bias[cb], bb1 = bias[cb + 1];
                float2 v0 = make_float2(acc[i][j][0] + bb0, acc[i][j][1] + bb1);
                float2 v1 = make_float2(acc[i][j][2] + bb0, acc[i][j][3] + bb1);
                *(float2*)&out[(size_t)mrow * VOCAB + cb]       = v0;
                *(float2*)&out[(size_t)(mrow + 8) * VOCAB + cb] = v1;
            }
        }
    }
}

// ------------------------- finals (transpose back to b-major) ----------------
__global__ void write_finals(float* __restrict__ out) {
    int i = blockIdx.x * blockDim.x + threadIdx.x;
    if (i < BH) {
        int b = i / HID, k = i % HID;
        float* o = out + (size_t)T_STEPS * BATCH * VOCAB;
        // h1(99): written phase 99 -> slot (99&1)^1 = 0
        // h2(99): written phase 100 -> slot 100&1 = 0
        o[i]          = g_h1buf[k * BATCH + b];
        o[BH + i]     = g_h2buf[k * BATCH + b];
        o[2 * BH + i] = g_c1f[i];
        o[3 * BH + i] = g_c2f[i];
    }
}

// ------------------------- launch -------------------------------------------
extern "C" void kernel_launch(void* const* d_in, const int* in_sizes, int n_in,
                              void* d_out, int out_size) {
    const int*   raw   = (const int*)  d_in[0];
    const float* h1    = (const float*)d_in[1];
    const float* h2    = (const float*)d_in[2];
    const float* c1    = (const float*)d_in[3];
    const float* c2    = (const float*)d_in[4];
    const float* emb   = (const float*)d_in[5];
    const float* wi1   = (const float*)d_in[6];
    const float* wh1   = (const float*)d_in[7];
    const float* wi2   = (const float*)d_in[8];
    const float* wh2   = (const float*)d_in[9];
    const float* dec_w = (const float*)d_in[10];
    const float* dec_b = (const float*)d_in[11];
    float* out = (float*)d_out;

    float *p_afrag, *p_bfrag;
    cudaGetSymbolAddress((void**)&p_afrag, g_AfragH2);
    cudaGetSymbolAddress((void**)&p_bfrag, g_BfragDec);

    static int attr_set = 0;
    if (!attr_set) {
        cudaFuncSetAttribute(lstm_recur, cudaFuncAttributeMaxDynamicSharedMemorySize,
                             (int)sizeof(SmemT));
        cudaFuncSetAttribute(decoder_frag, cudaFuncAttributeMaxDynamicSharedMemorySize,
                             DEC_SM_FLOATS * 4);
        attr_set = 1;
    }

    init_state<<<128, 256>>>(h1, h2);
    conv_b_dec<<<dim3(40, 64), 256>>>(dec_w);
    precompute_xw1<<<dim3(16, 50), 256>>>(raw, emb, wi1);
    lstm_recur<<<NBLK, 512, sizeof(SmemT)>>>(wh1, wi2, wh2, c1, c2);
    decoder_frag<<<dim3(40, 50), 256, DEC_SM_FLOATS * 4>>>(p_afrag, p_bfrag, dec_b, out);
    write_finals<<<128, 256>>>(out);
}

// round 13
// speedup vs baseline: 3.2477x; 1.0201x over previous
#include <cuda_runtime.h>
#include <cuda_bf16.h>
#include <math.h>

#define T_STEPS 100
#define BATCH   64
#define HID     512
#define NGATE   2048   // 4*512
#define VOCAB   10000
#define NVPAD   10240  // vocab padded to 256
#define NBLK    128
#define BH      (BATCH * HID)

typedef unsigned long long u64;

// ------------------------- scratch (static device memory) -------------------
__device__ float g_XW1[T_STEPS * 4 * HID * BATCH];    // [t][g][o][b] k-major
__device__ float g_AfragH2[T_STEPS * BATCH * HID];    // h2 in A-fragment order
__device__ float g_BfragDec[NVPAD * HID];             // dec_w in B-fragment order
__device__ float g_h1buf[2 * BH];                     // K-MAJOR: [k][64 b]
__device__ float g_h2buf[2 * BH];                     // K-MAJOR: [k][64 b]
__device__ float g_c1f[BH];
__device__ float g_c2f[BH];
__device__ unsigned g_bar_cnt;
__device__ volatile unsigned g_bar_flag;

// ------------------------- f32x2 helpers -------------------------------------
__device__ __forceinline__ u64 pack2(float x, float y) {
    u64 r;
    asm("mov.b64 %0, {%1, %2};" : "=l"(r)
        : "r"(__float_as_uint(x)), "r"(__float_as_uint(y)));
    return r;
}
__device__ __forceinline__ u64 dup2(float x) {
    u64 r;
    asm("mov.b64 %0, {%1, %1};" : "=l"(r) : "r"(__float_as_uint(x)));
    return r;
}
__device__ __forceinline__ void fma2(u64 &d, u64 a, u64 b) {
    asm("fma.rn.f32x2 %0, %1, %2, %0;" : "+l"(d) : "l"(a), "l"(b));
}
__device__ __forceinline__ void add2(u64 &d, u64 a) {
    asm("add.rn.f32x2 %0, %0, %1;" : "+l"(d) : "l"(a));
}
__device__ __forceinline__ float2 unpack2(u64 v) {
    float2 r;
    r.x = __uint_as_float((unsigned)(v & 0xFFFFFFFFu));
    r.y = __uint_as_float((unsigned)(v >> 32));
    return r;
}
__device__ __forceinline__ float sigm(float x) { return 1.f / (1.f + expf(-x)); }

// ------------------------- tf32 mma helpers ----------------------------------
__device__ __forceinline__ float cvt_tf32(float x) {
    unsigned r;
    asm("cvt.rn.tf32.f32 %0, %1;" : "=r"(r) : "f"(x));
    return __uint_as_float(r);
}
__device__ __forceinline__ void mma_tf32(float* d, const uint4& a, const uint2& b) {
    asm("mma.sync.aligned.m16n8k8.row.col.f32.tf32.tf32.f32 "
        "{%0,%1,%2,%3}, {%4,%5,%6,%7}, {%8,%9}, {%0,%1,%2,%3};"
        : "+f"(d[0]), "+f"(d[1]), "+f"(d[2]), "+f"(d[3])
        : "r"(a.x), "r"(a.y), "r"(a.z), "r"(a.w), "r"(b.x), "r"(b.y));
}

// ------------------------- cp.async helpers ----------------------------------
__device__ __forceinline__ void cp_async16(void* dst, const void* src) {
    unsigned d = (unsigned)__cvta_generic_to_shared(dst);
    asm volatile("cp.async.cg.shared.global [%0], [%1], 16;" :: "r"(d), "l"(src));
}
__device__ __forceinline__ void cp_commit() {
    asm volatile("cp.async.commit_group;");
}
template<int N> __device__ __forceinline__ void cp_wait() {
    asm volatile("cp.async.wait_group %0;" :: "n"(N));
}

// ------------------------- init (transpose states to k-major) ----------------
__global__ void init_state(const float* __restrict__ h1, const float* __restrict__ h2) {
    int i = blockIdx.x * blockDim.x + threadIdx.x;
    if (i < BH) {
        int k = i >> 6, b = i & 63;
        g_h1buf[i] = h1[b * HID + k];       // slot 0 = h1(-1)
        g_h2buf[BH + i] = h2[b * HID + k];
        g_h2buf[i] = h2[b * HID + k];       // slot 0 = h2(-1) (phase 1 reads slot 0)
    }
    if (i == 0) { g_bar_cnt = 0; g_bar_flag = 0; }
}

// ------------------------- conv: dec_w -> B-fragment order -------------------
__global__ __launch_bounds__(256) void conv_b_dec(const float* __restrict__ Bw) {
    const int n  = blockIdx.x * 256 + threadIdx.x;   // 0..10239
    const int kg = blockIdx.y;                       // 0..63
    const int k0 = kg * 8;

    float v[8];
    if (n < VOCAB) {
        float4 a = *(const float4*)(Bw + (size_t)n * HID + k0);
        float4 b = *(const float4*)(Bw + (size_t)n * HID + k0 + 4);
        v[0]=a.x; v[1]=a.y; v[2]=a.z; v[3]=a.w;
        v[4]=b.x; v[5]=b.y; v[6]=b.z; v[7]=b.w;
    } else {
#pragma unroll
        for (int j = 0; j < 8; j++) v[j] = 0.f;
    }
    const int nb = n >> 8, nn = n & 255, natom = nn >> 3, g = nn & 7;
    const int kc = k0 >> 5, ka = (k0 & 31) >> 3;
    float* dst = g_BfragDec +
        ((((size_t)(nb * 16 + kc) * 32 + natom) * 4 + ka) * 32 + g * 4) * 2;
    float4 o0 = make_float4(cvt_tf32(v[0]), cvt_tf32(v[4]), cvt_tf32(v[1]), cvt_tf32(v[5]));
    float4 o1 = make_float4(cvt_tf32(v[2]), cvt_tf32(v[6]), cvt_tf32(v[3]), cvt_tf32(v[7]));
    *(float4*)dst       = o0;
    *(float4*)(dst + 4) = o1;
}

// ------------------------- precompute XW1 = emb[tok] @ wi1 -------------------
// Output layout: g_XW1[t][g][o][b].  Double-buffered: A prefetched to regs,
// B staged via cp.async; ONE __syncthreads per 8-k chunk.
__global__ __launch_bounds__(256) void precompute_xw1(
    const int* __restrict__ tok, const float* __restrict__ emb,
    const float* __restrict__ wi1)
{
    __shared__ float As[2][8][128];
    __shared__ float Bs[2][8][128];
    __shared__ int   toks[128];

    const int tid = threadIdx.x;
    const int m0 = blockIdx.y * 128;
    const int n0 = blockIdx.x * 128;
    const int g  = n0 >> 9;
    const int og0 = n0 & 511;
    const float* wbase = wi1 + (size_t)g * HID * HID + og0;

    if (tid < 128) toks[tid] = tok[m0 + tid];
    __syncthreads();

    const int lr = tid >> 1;
    const int lk = (tid & 1) * 4;
    const int bk = tid >> 5;
    const int bn = (tid & 31) * 4;
    const int tx = tid & 15, ty = tid >> 4;

    const float* a_src = emb + (size_t)toks[lr] * HID + lk;
    const float* b_src = wbase + (size_t)bk * HID + bn;

    u64 acc[8][4];
#pragma unroll
    for (int i = 0; i < 8; i++)
#pragma unroll
        for (int j = 0; j < 4; j++) acc[i][j] = 0ULL;

    // prologue: stage chunk 0
    {
        float4 av = *(const float4*)(a_src);
        cp_async16(&Bs[0][bk][bn], b_src);
        cp_commit();
        As[0][lk+0][lr] = av.x; As[0][lk+1][lr] = av.y;
        As[0][lk+2][lr] = av.z; As[0][lk+3][lr] = av.w;
        cp_wait<0>();
        __syncthreads();
    }

    for (int c = 0; c < 64; c++) {
        const int cur = c & 1, nxt = cur ^ 1;
        float4 avn;
        if (c < 63) {
            avn = *(const float4*)(a_src + (size_t)(c + 1) * 8);
            cp_async16(&Bs[nxt][bk][bn], b_src + (size_t)(c + 1) * 8 * HID);
            cp_commit();
        }
#pragma unroll
        for (int k = 0; k < 8; k++) {
            float4 a0 = *(float4*)&As[cur][k][ty * 4];
            float4 a1 = *(float4*)&As[cur][k][64 + ty * 4];
            float4 b0 = *(float4*)&Bs[cur][k][tx * 4];
            float4 b1 = *(float4*)&Bs[cur][k][64 + tx * 4];
            u64 bp0 = ((const u64*)&b0)[0], bp1 = ((const u64*)&b0)[1];
            u64 bp2 = ((const u64*)&b1)[0], bp3 = ((const u64*)&b1)[1];
            float ar[8] = {a0.x, a0.y, a0.z, a0.w, a1.x, a1.y, a1.z, a1.w};
#pragma unroll
            for (int i = 0; i < 8; i++) {
                u64 ad = dup2(ar[i]);
                fma2(acc[i][0], ad, bp0);
                fma2(acc[i][1], ad, bp1);
                fma2(acc[i][2], ad, bp2);
                fma2(acc[i][3], ad, bp3);
            }
        }
        if (c < 63) {
            As[nxt][lk+0][lr] = avn.x; As[nxt][lk+1][lr] = avn.y;
            As[nxt][lk+2][lr] = avn.z; As[nxt][lk+3][lr] = avn.w;
            cp_wait<0>();
        }
        __syncthreads();
    }

    // scatter epilogue: element (m, n=g*512+o) -> g_XW1[((t*4+g)*512+o)*64+b]
#pragma unroll
    for (int i = 0; i < 8; i++) {
        int m = m0 + (i < 4 ? ty * 4 + i : 64 + ty * 4 + (i - 4));
        int t = m >> 6, b = m & 63;
        float* tb = g_XW1 + (((size_t)t * 4 + g) * HID) * BATCH + b;
#pragma unroll
        for (int j = 0; j < 4; j++) {
            float2 v = unpack2(acc[i][j]);
            int cb = (j < 2) ? (tx * 4 + j * 2) : (64 + tx * 4 + (j - 2) * 2);
            int o = og0 + cb;
            tb[(size_t)o * BATCH]       = v.x;
            tb[(size_t)(o + 1) * BATCH] = v.y;
        }
    }
}

// ------------------------- persistent recurrence kernel ----------------------
// WAVEFRONT (R12) + 8-way reduce split: phase p computes layer1(t=p) and
// layer2(t=p-1); one grid barrier per phase.  After the block sync, reducers:
//   ks0-3: layer1, batch element bb=ks     (accs bb*2, bb*2+1, slots s=0..7)
//   ks4-7: layer2, batch element bb=ks-4
// Slot sum order identical to R12 -> bit-identical arithmetic.
struct SmemT {
    float w1 [HID * 16];    // [k][oo][g]
    float wi2[HID * 16];
    float wh2[HID * 16];
    u64   xchA[8 * 64 * 8]; // layer1 partials [ks][r][8]
    u64   xchB[8 * 64 * 8]; // layer2 partials [ks][r][8]
    float c1s[256];         // [b][oo]
    float c2s[256];
};

__device__ __forceinline__ void grid_barrier(int p) {
    __syncthreads();
    if (threadIdx.x == 0) {
        __threadfence();   // release (emits CCTL.IVALL too)
        unsigned prev = atomicAdd(&g_bar_cnt, 1u);
        if (prev == (unsigned)NBLK * (unsigned)(p + 1) - 1u) {
            g_bar_flag = (unsigned)(p + 1);
        } else {
            while (g_bar_flag < (unsigned)(p + 1)) { }
        }
        __threadfence();   // acquire + invalidate this SM's L1D
    }
    __syncthreads();
}

// acc[b*2+0] = {i,f}, acc[b*2+1] = {g,o} for 4 batches b.
__device__ __forceinline__ void gemm_b4(
    const float* __restrict__ hk,     // k-major h + b0 offset
    const float* __restrict__ w,      // smem weights + oo*4
    int klen, u64 (&acc)[8])
{
#pragma unroll 2
    for (int kk = 0; kk < klen; kk += 4) {
        float4 hv[4];
#pragma unroll
        for (int j = 0; j < 4; j++)
            hv[j] = *(const float4*)(hk + (size_t)(kk + j) * BATCH);
#pragma unroll
        for (int j = 0; j < 4; j++) {
            float4 wv = *(const float4*)(w + (kk + j) * 16);
            u64 w0 = ((const u64*)&wv)[0];
            u64 w1 = ((const u64*)&wv)[1];
            u64 d0 = dup2(hv[j].x), d1 = dup2(hv[j].y);
            u64 d2 = dup2(hv[j].z), d3 = dup2(hv[j].w);
            fma2(acc[0], d0, w0); fma2(acc[1], d0, w1);
            fma2(acc[2], d1, w0); fma2(acc[3], d1, w1);
            fma2(acc[4], d2, w0); fma2(acc[5], d2, w1);
            fma2(acc[6], d3, w0); fma2(acc[7], d3, w1);
        }
    }
}

// h2 value (m = t*64+b, k = col) -> A-fragment global index
__device__ __forceinline__ size_t afrag_idx(int m, int kc, int ka, int lk, int khi) {
    int mb = m >> 7, mm = m & 127, matom = mm >> 4, r16 = mm & 15;
    int lane = (r16 & 7) * 4 + lk;
    int reg  = (r16 >> 3) + 2 * khi;
    return ((((size_t)(mb * 16 + kc) * 8 + matom) * 4 + ka) * 32 + lane) * 4 + reg;
}

__global__ __launch_bounds__(512, 1) void lstm_recur(
    const float* __restrict__ wh1, const float* __restrict__ wi2g,
    const float* __restrict__ wh2g,
    const float* __restrict__ c1in, const float* __restrict__ c2in)
{
    extern __shared__ char smraw[];
    SmemT* sm = (SmemT*)smraw;
    const int tid = threadIdx.x;
    const int bi  = blockIdx.x;
    const int o0  = bi * 4;

    // weights: [k][oo][g] <- W[g][k][o0+oo], once for all phases
    for (int idx = tid; idx < HID * 16; idx += 512) {
        int k = idx >> 4, c = idx & 15;
        int oo = c >> 2, g = c & 3;
        size_t src = ((size_t)g * HID + k) * HID + o0 + oo;
        sm->w1 [idx] = wh1 [src];
        sm->wi2[idx] = wi2g[src];
        sm->wh2[idx] = wh2g[src];
    }
    if (tid < 256) {   // c state slice [b][oo]
        int b = tid >> 2, oo = tid & 3;
        sm->c1s[tid] = c1in[b * HID + o0 + oo];
        sm->c2s[tid] = c2in[b * HID + o0 + oo];
    }
    __syncthreads();

    const int ks = tid >> 6;        // 0..7
    const int r  = tid & 63;
    const int oo = r & 3;
    const int bq = r >> 2;
    const int b0 = bq * 4;
    const int col = o0 + oo;

    // A-fragment constants for (k = col)
    const int f_kc = col >> 5, f_kk = col & 31;
    const int f_ka = f_kk >> 3, f_lk = f_kk & 3, f_khi = (f_kk >> 2) & 1;

    for (int p = 0; p <= T_STEPS; p++) {
        const int s1r = p & 1;          // h1(p-1) slot
        const int s1w = s1r ^ 1;        // h1(p) slot
        const int s2r = s1w;            // h2(p-2) slot
        const int s2w = s1r;            // h2(p-1) slot
        const bool doL1 = (p < T_STEPS);
        const bool doL2 = (p > 0);

        // ---- layer1(t=p): K split 8x64, partials to xchA ----
        float xw[4];
        if (doL1 && ks < 4) {
#pragma unroll
            for (int g = 0; g < 4; g++)
                xw[g] = g_XW1[(((size_t)p * 4 + g) * HID + col) * BATCH + b0 + ks];
        }
        if (doL1) {
            u64 acc[8];
#pragma unroll
            for (int i = 0; i < 8; i++) acc[i] = 0ULL;
            gemm_b4(g_h1buf + s1r * BH + (ks * 64) * BATCH + b0,
                    sm->w1 + (ks * 64) * 16 + oo * 4, 64, acc);
            u64* xc = sm->xchA + ks * 512 + r * 8;
#pragma unroll
            for (int i = 0; i < 8; i++) xc[i] = acc[i];
        }

        // ---- layer2(t=p-1): ks0-3 wi2 quarters (h1(p-1)), ks4-7 wh2 -------
        if (doL2) {
            u64 acc[8];
#pragma unroll
            for (int i = 0; i < 8; i++) acc[i] = 0ULL;
            if (ks < 4) {
                gemm_b4(g_h1buf + s1r * BH + (ks * 128) * BATCH + b0,
                        sm->wi2 + (ks * 128) * 16 + oo * 4, 128, acc);
            } else {
                gemm_b4(g_h2buf + s2r * BH + ((ks - 4) * 128) * BATCH + b0,
                        sm->wh2 + ((ks - 4) * 128) * 16 + oo * 4, 128, acc);
            }
            u64* xc = sm->xchB + ks * 512 + r * 8;
#pragma unroll
            for (int i = 0; i < 8; i++) xc[i] = acc[i];
        }

        __syncthreads();

        // ---- reduce + pointwise: ks0-3 -> layer1 (bb=ks), ks4-7 -> layer2 --
        if (doL1 && ks < 4) {
            const int bb = ks;
            const int ibase = bb * 2;
            u64 a0 = 0ULL, a1 = 0ULL;
#pragma unroll
            for (int s = 0; s < 8; s++) {
                const u64* xc = sm->xchA + s * 512 + r * 8 + ibase;
                add2(a0, xc[0]); add2(a1, xc[1]);
            }
            float2 iff = unpack2(a0);
            float2 go  = unpack2(a1);
            float iv = iff.x + xw[0];
            float fv = iff.y + xw[1];
            float gv = go.x  + xw[2];
            float ov = go.y  + xw[3];
            float c = sm->c1s[(b0 + bb) * 4 + oo];
            float cn = sigm(fv) * c + sigm(iv) * tanhf(gv);
            sm->c1s[(b0 + bb) * 4 + oo] = cn;
            g_h1buf[s1w * BH + col * BATCH + b0 + bb] = sigm(ov) * tanhf(cn);
        }
        if (doL2 && ks >= 4) {
            const int bb = ks - 4;
            const int ibase = bb * 2;
            u64 a0 = 0ULL, a1 = 0ULL;
#pragma unroll
            for (int s = 0; s < 8; s++) {
                const u64* xc = sm->xchB + s * 512 + r * 8 + ibase;
                add2(a0, xc[0]); add2(a1, xc[1]);
            }
            float2 iff = unpack2(a0);
            float2 go  = unpack2(a1);
            float c = sm->c2s[(b0 + bb) * 4 + oo];
            float cn = sigm(iff.y) * c + sigm(iff.x) * tanhf(go.x);
            sm->c2s[(b0 + bb) * 4 + oo] = cn;
            float hn = sigm(go.y) * tanhf(cn);
            g_h2buf[s2w * BH + col * BATCH + b0 + bb] = hn;
            int m = (p - 1) * BATCH + b0 + bb;
            g_AfragH2[afrag_idx(m, f_kc, f_ka, f_lk, f_khi)] = cvt_tf32(hn);
        }

        grid_barrier(p);
    }

    // final c slices (b-major, small)
    if (tid < 256) {
        int b = tid >> 2, oo2 = tid & 3;
        g_c1f[b * HID + o0 + oo2] = sm->c1s[tid];
        g_c2f[b * HID + o0 + oo2] = sm->c2s[tid];
    }
}

// ------------------------- decoder: tf32 mma, fragment-order + cp.async ------
#define DEC_SM_FLOATS (2 * 4096 + 2 * 8192)

__global__ __launch_bounds__(256, 1) void decoder_frag(
    const float* __restrict__ Afrag,
    const float* __restrict__ Bfrag,
    const float* __restrict__ bias,
    float* __restrict__ out)
{
    extern __shared__ float smf[];
    float* As = smf;            // [2][4096]
    float* Bs = smf + 8192;     // [2][8192]

    const int tid  = threadIdx.x;
    const int mb   = blockIdx.y;
    const int nb   = blockIdx.x;
    const int warp = tid >> 5, lane = tid & 31;
    const int wm = warp >> 2, wn = warp & 3;

    const float* Ag = Afrag + (size_t)mb * 16 * 4096;
    const float* Bg = Bfrag + (size_t)nb * 16 * 8192;

    float acc[4][8][4];
#pragma unroll
    for (int i = 0; i < 4; i++)
#pragma unroll
        for (int j = 0; j < 8; j++)
#pragma unroll
            for (int q = 0; q < 4; q++) acc[i][j][q] = 0.f;

#define DSTAGE(kc, buf)                                                        \
    {                                                                          \
        _Pragma("unroll")                                                      \
        for (int i = 0; i < 4; i++)                                            \
            cp_async16(As + (buf) * 4096 + (i * 256 + tid) * 4,                \
                       Ag + (kc) * 4096 + (i * 256 + tid) * 4);                \
        _Pragma("unroll")                                                      \
        for (int i = 0; i < 8; i++)                                            \
            cp_async16(Bs + (buf) * 8192 + (i * 256 + tid) * 4,                \
                       Bg + (kc) * 8192 + (i * 256 + tid) * 4);                \
    }

    DSTAGE(0, 0);
    cp_commit();

    for (int c = 0; c < 16; c++) {
        const int cur = c & 1, nxt = cur ^ 1;
        if (c < 15) { DSTAGE(c + 1, nxt); cp_commit(); cp_wait<1>(); }
        else        { cp_wait<0>(); }
        __syncthreads();
        const float* Ab = As + cur * 4096;
        const float* Bb = Bs + cur * 8192;
#pragma unroll
        for (int ka = 0; ka < 4; ka++) {
            uint4 af[4];
            uint2 bf[8];
#pragma unroll
            for (int i = 0; i < 4; i++)
                af[i] = *(const uint4*)(Ab + (((wm * 4 + i) * 4 + ka) * 32 + lane) * 4);
#pragma unroll
            for (int j = 0; j < 8; j++)
                bf[j] = *(const uint2*)(Bb + (((wn * 8 + j) * 4 + ka) * 32 + lane) * 2);
#pragma unroll
            for (int i = 0; i < 4; i++)
#pragma unroll
                for (int j = 0; j < 8; j++)
                    mma_tf32(acc[i][j], af[i], bf[j]);
        }
        __syncthreads();
    }
#undef DSTAGE

    const int g = lane >> 2, t4 = lane & 3;
#pragma unroll
    for (int i = 0; i < 4; i++) {
        int mrow = mb * 128 + wm * 64 + i * 16 + g;
#pragma unroll
        for (int j = 0; j < 8; j++) {
            int cb = nb * 256 + wn * 64 + j * 8 + t4 * 2;
            if (cb < VOCAB) {
                float bb0 = bias[cb], bb1 = bias[cb + 1];
                float2 v0 = make_float2(acc[i][j][0] + bb0, acc[i][j][1] + bb1);
                float2 v1 = make_float2(acc[i][j][2] + bb0, acc[i][j][3] + bb1);
                *(float2*)&out[(size_t)mrow * VOCAB + cb]       = v0;
                *(float2*)&out[(size_t)(mrow + 8) * VOCAB + cb] = v1;
            }
        }
    }
}

// ------------------------- finals (transpose back to b-major) ----------------
__global__ void write_finals(float* __restrict__ out) {
    int i = blockIdx.x * blockDim.x + threadIdx.x;
    if (i < BH) {
        int b = i / HID, k = i % HID;
        float* o = out + (size_t)T_STEPS * BATCH * VOCAB;
        // h1(99): written phase 99 -> slot 0; h2(99): written phase 100 -> slot 0
        o[i]          = g_h1buf[k * BATCH + b];
        o[BH + i]     = g_h2buf[k * BATCH + b];
        o[2 * BH + i] = g_c1f[i];
        o[3 * BH + i] = g_c2f[i];
    }
}

// ------------------------- launch -------------------------------------------
extern "C" void kernel_launch(void* const* d_in, const int* in_sizes, int n_in,
                              void* d_out, int out_size) {
    const int*   raw   = (const int*)  d_in[0];
    const float* h1    = (const float*)d_in[1];
    const float* h2    = (const float*)d_in[2];
    const float* c1    = (const float*)d_in[3];
    const float* c2    = (const float*)d_in[4];
    const float* emb   = (const float*)d_in[5];
    const float* wi1   = (const float*)d_in[6];
    const float* wh1   = (const float*)d_in[7];
    const float* wi2   = (const float*)d_in[8];
    const float* wh2   = (const float*)d_in[9];
    const float* dec_w = (const float*)d_in[10];
    const float* dec_b = (const float*)d_in[11];
    float* out = (float*)d_out;

    float *p_afrag, *p_bfrag;
    cudaGetSymbolAddress((void**)&p_afrag, g_AfragH2);
    cudaGetSymbolAddress((void**)&p_bfrag, g_BfragDec);

    static int attr_set = 0;
    if (!attr_set) {
        cudaFuncSetAttribute(lstm_recur, cudaFuncAttributeMaxDynamicSharedMemorySize,
                             (int)sizeof(SmemT));
        cudaFuncSetAttribute(decoder_frag, cudaFuncAttributeMaxDynamicSharedMemorySize,
                             DEC_SM_FLOATS * 4);
        attr_set = 1;
    }

    init_state<<<128, 256>>>(h1, h2);
    conv_b_dec<<<dim3(40, 64), 256>>>(dec_w);
    precompute_xw1<<<dim3(16, 50), 256>>>(raw, emb, wi1);
    lstm_recur<<<NBLK, 512, sizeof(SmemT)>>>(wh1, wi2, wh2, c1, c2);
    decoder_frag<<<dim3(40, 50), 256, DEC_SM_FLOATS * 4>>>(p_afrag, p_bfrag, dec_b, out);
    write_finals<<<128, 256>>>(out);
}